// round 2
// baseline (speedup 1.0000x reference)
#include <cuda_runtime.h>
#include <cuda_bf16.h>
#include <math.h>

#define B_   16
#define NQ   64
#define NKV  4096
#define CQ   768
#define CKV  1024
#define H_   12
#define D_   64

// Scratch (device globals: allocation-free per harness rules)
__device__ float g_q[(size_t)B_ * NQ * CQ];                 // 3 MB
__device__ float g_k[(size_t)B_ * NKV * CQ];                // 201 MB
__device__ float g_v[(size_t)B_ * NKV * CQ];                // 201 MB
__device__ float g_x[(size_t)B_ * NQ * CQ];                 // 3 MB

// ---------------------------------------------------------------------------
// C[M,N] = A[M,K] @ B[K,N] + bias[N]
// 128x128 block tile, 8 K-slice, 256 threads, 8x8 per-thread micro-tile.
// Requires: M%128==0, N%128==0, K%8==0 (all shapes here satisfy this).
// ---------------------------------------------------------------------------
__global__ __launch_bounds__(256) void sgemm_bias(
    const float* __restrict__ A, const float* __restrict__ Bm,
    const float* __restrict__ bias, float* __restrict__ C,
    int M, int N, int K)
{
    __shared__ float As[8][128];
    __shared__ float Bs[8][128];

    const int brow = blockIdx.y * 128;
    const int bcol = blockIdx.x * 128;
    const int tid  = threadIdx.x;

    const int a_row = tid >> 1;            // 0..127
    const int a_col = (tid & 1) << 2;      // 0 or 4
    const int b_row = tid >> 5;            // 0..7
    const int b_col = (tid & 31) << 2;     // 0..124

    const int tx = tid & 15;
    const int ty = tid >> 4;

    const float* Ap = A + (size_t)(brow + a_row) * K + a_col;
    const float* Bp = Bm + (size_t)b_row * N + bcol + b_col;

    float acc[8][8];
    #pragma unroll
    for (int i = 0; i < 8; i++)
        #pragma unroll
        for (int j = 0; j < 8; j++)
            acc[i][j] = 0.f;

    for (int k0 = 0; k0 < K; k0 += 8) {
        float4 av = *(const float4*)(Ap + k0);
        float4 bv = *(const float4*)(Bp + (size_t)k0 * N);

        As[a_col + 0][a_row] = av.x;
        As[a_col + 1][a_row] = av.y;
        As[a_col + 2][a_row] = av.z;
        As[a_col + 3][a_row] = av.w;
        *(float4*)&Bs[b_row][b_col] = bv;
        __syncthreads();

        #pragma unroll
        for (int k = 0; k < 8; k++) {
            float a[8], b[8];
            *(float4*)&a[0] = *(const float4*)&As[k][ty * 8];
            *(float4*)&a[4] = *(const float4*)&As[k][ty * 8 + 4];
            *(float4*)&b[0] = *(const float4*)&Bs[k][tx * 8];
            *(float4*)&b[4] = *(const float4*)&Bs[k][tx * 8 + 4];
            #pragma unroll
            for (int i = 0; i < 8; i++)
                #pragma unroll
                for (int j = 0; j < 8; j++)
                    acc[i][j] = fmaf(a[i], b[j], acc[i][j]);
        }
        __syncthreads();
    }

    float bb[8];
    #pragma unroll
    for (int j = 0; j < 8; j++)
        bb[j] = bias[bcol + tx * 8 + j];

    #pragma unroll
    for (int i = 0; i < 8; i++) {
        float* Cp = C + (size_t)(brow + ty * 8 + i) * N + bcol + tx * 8;
        float4 o0, o1;
        o0.x = acc[i][0] + bb[0]; o0.y = acc[i][1] + bb[1];
        o0.z = acc[i][2] + bb[2]; o0.w = acc[i][3] + bb[3];
        o1.x = acc[i][4] + bb[4]; o1.y = acc[i][5] + bb[5];
        o1.z = acc[i][6] + bb[6]; o1.w = acc[i][7] + bb[7];
        *(float4*)(Cp)     = o0;
        *(float4*)(Cp + 4) = o1;
    }
}

// ---------------------------------------------------------------------------
// Fused attention: one CTA per (b, h). Q tile 64x64 resident, stream KV in
// 64-row chunks, online softmax, accumulate O in registers.
// 256 threads = 16x16 grid; each thread owns a 4x4 tile of S and of O.
// ---------------------------------------------------------------------------
#define ATT_SMEM (4 * 64 * 65 * 4)

__global__ __launch_bounds__(256) void attention_kernel(
    const float* __restrict__ Qg, const float* __restrict__ Kg,
    const float* __restrict__ Vg, float* __restrict__ Xg)
{
    extern __shared__ float sm[];
    float (*Qt)[65] = (float(*)[65])(sm);                 // Q transposed [d][r]
    float (*Kt)[65] = (float(*)[65])(sm + 64 * 65);       // K transposed [d][j]
    float (*Vs)[65] = (float(*)[65])(sm + 2 * 64 * 65);   // V natural    [j][d]
    float (*Pt)[65] = (float(*)[65])(sm + 3 * 64 * 65);   // P transposed [j][r]

    const int b = blockIdx.x / H_;
    const int h = blockIdx.x % H_;
    const int tid = threadIdx.x;
    const int tx = tid & 15;   // S-col / O-col group
    const int ty = tid >> 4;   // S-row / O-row group

    // Load Q (scaled by D^-0.5 = 1/8), transposed.
    for (int idx = tid; idx < 64 * 64; idx += 256) {
        int rr = idx >> 6, dd = idx & 63;
        Qt[dd][rr] = Qg[(size_t)(b * NQ + rr) * CQ + h * D_ + dd] * 0.125f;
    }

    float acc[4][4];
    float m[4], l[4];
    #pragma unroll
    for (int i = 0; i < 4; i++) {
        m[i] = -1e30f; l[i] = 0.f;
        #pragma unroll
        for (int j = 0; j < 4; j++) acc[i][j] = 0.f;
    }

    for (int kv0 = 0; kv0 < NKV; kv0 += 64) {
        __syncthreads();   // protect Kt/Vs (and first-iter Q load)
        for (int idx = tid; idx < 64 * 64; idx += 256) {
            int rr = idx >> 6, dd = idx & 63;
            size_t g = (size_t)(b * NKV + kv0 + rr) * CQ + h * D_ + dd;
            Kt[dd][rr] = Kg[g];
            Vs[rr][dd] = Vg[g];
        }
        __syncthreads();

        // S = Q K^T tile (rows ty*4.., cols tx*4..)
        float s[4][4];
        #pragma unroll
        for (int i = 0; i < 4; i++)
            #pragma unroll
            for (int j = 0; j < 4; j++) s[i][j] = 0.f;

        #pragma unroll 4
        for (int d = 0; d < 64; d++) {
            float a[4], bb[4];
            #pragma unroll
            for (int i = 0; i < 4; i++) a[i]  = Qt[d][ty * 4 + i];
            #pragma unroll
            for (int j = 0; j < 4; j++) bb[j] = Kt[d][tx * 4 + j];
            #pragma unroll
            for (int i = 0; i < 4; i++)
                #pragma unroll
                for (int j = 0; j < 4; j++)
                    s[i][j] = fmaf(a[i], bb[j], s[i][j]);
        }

        // Online softmax per row; 16 threads (same ty) share a row group.
        #pragma unroll
        for (int ii = 0; ii < 4; ii++) {
            float mx = fmaxf(fmaxf(s[ii][0], s[ii][1]), fmaxf(s[ii][2], s[ii][3]));
            #pragma unroll
            for (int o = 1; o < 16; o <<= 1)
                mx = fmaxf(mx, __shfl_xor_sync(0xffffffffu, mx, o));
            float mnew = fmaxf(m[ii], mx);
            float corr = __expf(m[ii] - mnew);
            float ls = 0.f;
            #pragma unroll
            for (int jj = 0; jj < 4; jj++) {
                float p = __expf(s[ii][jj] - mnew);
                s[ii][jj] = p;
                ls += p;
            }
            #pragma unroll
            for (int o = 1; o < 16; o <<= 1)
                ls += __shfl_xor_sync(0xffffffffu, ls, o);
            l[ii] = l[ii] * corr + ls;
            m[ii] = mnew;
            #pragma unroll
            for (int jj = 0; jj < 4; jj++) {
                acc[ii][jj] *= corr;
                Pt[tx * 4 + jj][ty * 4 + ii] = s[ii][jj];
            }
        }
        __syncwarp();   // Pt producer/consumer are within the same warp (same ty)

        // O += P @ V
        #pragma unroll 4
        for (int j = 0; j < 64; j++) {
            float p[4], v[4];
            #pragma unroll
            for (int i = 0; i < 4; i++) p[i] = Pt[j][ty * 4 + i];
            #pragma unroll
            for (int c = 0; c < 4; c++) v[c] = Vs[j][tx * 4 + c];
            #pragma unroll
            for (int i = 0; i < 4; i++)
                #pragma unroll
                for (int c = 0; c < 4; c++)
                    acc[i][c] = fmaf(p[i], v[c], acc[i][c]);
        }
    }

    // Normalize and write x in (B, Nq, H*D) layout.
    #pragma unroll
    for (int ii = 0; ii < 4; ii++) {
        float inv = 1.f / l[ii];
        int r = ty * 4 + ii;
        #pragma unroll
        for (int jj = 0; jj < 4; jj++)
            Xg[(size_t)(b * NQ + r) * CQ + h * D_ + tx * 4 + jj] = acc[ii][jj] * inv;
    }
}

// ---------------------------------------------------------------------------
extern "C" void kernel_launch(void* const* d_in, const int* in_sizes, int n_in,
                              void* d_out, int out_size)
{
    const float* query = (const float*)d_in[0];
    const float* kv    = (const float*)d_in[1];
    const float* Wq    = (const float*)d_in[2];
    const float* bq    = (const float*)d_in[3];
    const float* Wk    = (const float*)d_in[4];
    const float* bk    = (const float*)d_in[5];
    const float* Wv    = (const float*)d_in[6];
    const float* bv    = (const float*)d_in[7];
    const float* Wo    = (const float*)d_in[8];
    const float* bo    = (const float*)d_in[9];
    float* out = (float*)d_out;

    float *qp, *kp, *vp, *xp;
    cudaGetSymbolAddress((void**)&qp, g_q);
    cudaGetSymbolAddress((void**)&kp, g_k);
    cudaGetSymbolAddress((void**)&vp, g_v);
    cudaGetSymbolAddress((void**)&xp, g_x);

    cudaFuncSetAttribute(attention_kernel,
                         cudaFuncAttributeMaxDynamicSharedMemorySize, ATT_SMEM);

    dim3 blk(256);

    // q = query @ Wq + bq        (1024 x 768 x 768)
    sgemm_bias<<<dim3(CQ / 128, (B_ * NQ) / 128), blk>>>(
        query, Wq, bq, qp, B_ * NQ, CQ, CQ);
    // k = kv @ Wk + bk           (65536 x 768 x 1024)
    sgemm_bias<<<dim3(CQ / 128, (B_ * NKV) / 128), blk>>>(
        kv, Wk, bk, kp, B_ * NKV, CQ, CKV);
    // v = kv @ Wv + bv
    sgemm_bias<<<dim3(CQ / 128, (B_ * NKV) / 128), blk>>>(
        kv, Wv, bv, vp, B_ * NKV, CQ, CKV);
    // fused attention
    attention_kernel<<<B_ * H_, 256, ATT_SMEM>>>(qp, kp, vp, xp);
    // out = x @ Wo + bo
    sgemm_bias<<<dim3(CQ / 128, (B_ * NQ) / 128), blk>>>(
        xp, Wo, bo, out, B_ * NQ, CQ, CQ);
}

// round 4
// speedup vs baseline: 1.8325x; 1.8325x over previous
#include <cuda_runtime.h>
#include <cuda_bf16.h>
#include <math.h>
#include <stdint.h>

#define B_   16
#define NQ   64
#define NKV  4096
#define CQ   768
#define CKV  1024
#define H_   12
#define D_   64
#define SPLIT 8

// ---------------- scratch (device globals; allocation-free) ----------------
__device__ float g_q[(size_t)B_ * NQ * CQ];
__device__ float g_k[(size_t)B_ * NKV * CQ];
__device__ float g_v[(size_t)B_ * NKV * CQ];
__device__ float g_x[(size_t)B_ * NQ * CQ];
__device__ __nv_bfloat16 g_kvh[(size_t)B_ * NKV * CKV];
__device__ __nv_bfloat16 g_kvl[(size_t)B_ * NKV * CKV];
__device__ __nv_bfloat16 g_wkth[(size_t)CQ * CKV];
__device__ __nv_bfloat16 g_wktl[(size_t)CQ * CKV];
__device__ __nv_bfloat16 g_wvth[(size_t)CQ * CKV];
__device__ __nv_bfloat16 g_wvtl[(size_t)CQ * CKV];
__device__ float g_accP[(size_t)B_ * H_ * SPLIT * NQ * D_];
__device__ float g_mP[(size_t)B_ * H_ * SPLIT * NQ];
__device__ float g_lP[(size_t)B_ * H_ * SPLIT * NQ];

// ---------------- helpers ----------------
__device__ __forceinline__ uint32_t smem_u32(const void* p) {
    uint32_t a;
    asm("{ .reg .u64 t; cvta.to.shared.u64 t, %1; cvt.u32.u64 %0, t; }"
        : "=r"(a) : "l"(p));
    return a;
}
__device__ __forceinline__ void cp16(uint32_t s, const void* g) {
    asm volatile("cp.async.cg.shared.global [%0], [%1], 16;\n"
                 :: "r"(s), "l"(__cvta_generic_to_global(g)) : "memory");
}
#define CP_COMMIT() asm volatile("cp.async.commit_group;\n" ::: "memory")
#define CP_WAIT(n)  asm volatile("cp.async.wait_group %0;\n" :: "n"(n) : "memory")

__device__ __forceinline__ void ldsm_x4(uint32_t addr, uint32_t& r0, uint32_t& r1,
                                        uint32_t& r2, uint32_t& r3) {
    asm volatile("ldmatrix.sync.aligned.m8n8.x4.shared.b16 {%0,%1,%2,%3}, [%4];"
                 : "=r"(r0), "=r"(r1), "=r"(r2), "=r"(r3) : "r"(addr));
}
__device__ __forceinline__ void mma_bf16(float* d, uint32_t a0, uint32_t a1,
                                         uint32_t a2, uint32_t a3,
                                         uint32_t b0, uint32_t b1) {
    asm volatile(
        "mma.sync.aligned.m16n8k16.row.col.f32.bf16.bf16.f32 "
        "{%0,%1,%2,%3}, {%4,%5,%6,%7}, {%8,%9}, {%0,%1,%2,%3};"
        : "+f"(d[0]), "+f"(d[1]), "+f"(d[2]), "+f"(d[3])
        : "r"(a0), "r"(a1), "r"(a2), "r"(a3), "r"(b0), "r"(b1));
}

// ---------------------------------------------------------------------------
// fp32 -> (bf16 hi, bf16 lo) elementwise split
// ---------------------------------------------------------------------------
__global__ __launch_bounds__(256) void split_kernel(
    const float* __restrict__ src, __nv_bfloat16* __restrict__ hi,
    __nv_bfloat16* __restrict__ lo, size_t n)
{
    size_t i = (size_t)blockIdx.x * blockDim.x + threadIdx.x;
    size_t stride = (size_t)gridDim.x * blockDim.x;
    for (; i < n; i += stride) {
        float x = src[i];
        __nv_bfloat16 h = __float2bfloat16(x);
        hi[i] = h;
        lo[i] = __float2bfloat16(x - __bfloat162float(h));
    }
}

// W [K=1024][N=768] -> Wt hi/lo [N=768][K=1024] bf16
__global__ __launch_bounds__(256) void transpose_split_kernel(
    const float* __restrict__ W, __nv_bfloat16* __restrict__ th,
    __nv_bfloat16* __restrict__ tl)
{
    int n = blockIdx.y;
    int k = blockIdx.x * 256 + threadIdx.x;
    float x = W[(size_t)k * CQ + n];
    __nv_bfloat16 h = __float2bfloat16(x);
    th[(size_t)n * CKV + k] = h;
    tl[(size_t)n * CKV + k] = __float2bfloat16(x - __bfloat162float(h));
}

// ---------------------------------------------------------------------------
// HMMA bf16x3 GEMM: C[M=65536, N=768] = Ah Bh^T + Ah Bl^T + Al Bh^T + bias
// A row-major [M,1024] bf16 (hi,lo); B row-major [768,1024] bf16 (hi,lo).
// CTA 128x128x32, 8 warps (warp tile 64x32), 3-stage cp.async pipeline.
// ---------------------------------------------------------------------------
#define LDS_E 40                      // padded bf16 row stride (80 bytes)
#define TILE_B (128 * LDS_E * 2)      // 10240 bytes per (128x32) tile
#define STAGE_B (4 * TILE_B)          // Ah, Al, Bh, Bl
#define STAGES 3
#define HGEMM_SMEM (STAGES * STAGE_B) // 122880
#define KT_N (CKV / 32)               // 32 k-tiles

__global__ __launch_bounds__(256, 1) void hgemm_bf16x3(
    const __nv_bfloat16* __restrict__ Ah_g, const __nv_bfloat16* __restrict__ Al_g,
    const __nv_bfloat16* __restrict__ Bh_g, const __nv_bfloat16* __restrict__ Bl_g,
    const float* __restrict__ bias, float* __restrict__ C)
{
    extern __shared__ char smem[];
    const uint32_t sbase = smem_u32(smem);
    const int tid = threadIdx.x;
    const int wid = tid >> 5, lane = tid & 31;
    const int wm = (wid & 1) * 64;         // warp m offset in CTA tile
    const int wn = (wid >> 1) * 32;        // warp n offset
    const int m0 = blockIdx.y * 128, n0 = blockIdx.x * 128;

    // global load mapping: thread -> (row, 32-byte half of a 64B row)
    const int lr = tid >> 1;
    const int lc = (tid & 1) * 16;         // bf16 element offset (0 or 16)
    const uint32_t s_off = (uint32_t)(lr * 80 + (tid & 1) * 32);

    const __nv_bfloat16* gAh = Ah_g + (size_t)(m0 + lr) * CKV + lc;
    const __nv_bfloat16* gAl = Al_g + (size_t)(m0 + lr) * CKV + lc;
    const __nv_bfloat16* gBh = Bh_g + (size_t)(n0 + lr) * CKV + lc;
    const __nv_bfloat16* gBl = Bl_g + (size_t)(n0 + lr) * CKV + lc;

    // ldmatrix lane addressing
    const int a_row = lane & 15;
    const int a_ko  = ((lane >> 4) & 1) * 8;
    const int b_row = (lane & 7) + ((lane >> 4) & 1) * 8;
    const int b_ko  = ((lane >> 3) & 1) * 8;

    float acc[4][4][4];
    #pragma unroll
    for (int i = 0; i < 4; i++)
        #pragma unroll
        for (int j = 0; j < 4; j++)
            #pragma unroll
            for (int c = 0; c < 4; c++) acc[i][j][c] = 0.f;

    auto load_stage = [&](int kt, int s) {
        const uint32_t sb = sbase + s * STAGE_B;
        const int ke = kt * 32;
        cp16(sb + s_off,                     gAh + ke);
        cp16(sb + s_off + 16,                gAh + ke + 8);
        cp16(sb + TILE_B + s_off,            gAl + ke);
        cp16(sb + TILE_B + s_off + 16,       gAl + ke + 8);
        cp16(sb + 2 * TILE_B + s_off,        gBh + ke);
        cp16(sb + 2 * TILE_B + s_off + 16,   gBh + ke + 8);
        cp16(sb + 3 * TILE_B + s_off,        gBl + ke);
        cp16(sb + 3 * TILE_B + s_off + 16,   gBl + ke + 8);
    };

    load_stage(0, 0); CP_COMMIT();
    load_stage(1, 1); CP_COMMIT();

    for (int kt = 0; kt < KT_N; kt++) {
        CP_WAIT(1);
        __syncthreads();

        const int nkt = kt + STAGES - 1;
        if (nkt < KT_N) load_stage(nkt, nkt % STAGES);
        CP_COMMIT();

        const uint32_t sb = sbase + (kt % STAGES) * STAGE_B;
        #pragma unroll
        for (int kb = 0; kb < 32; kb += 16) {
            uint32_t ah[4][4], al[4][4];
            #pragma unroll
            for (int mt = 0; mt < 4; mt++) {
                uint32_t ra = sb + (uint32_t)((wm + mt * 16 + a_row) * 80 + (a_ko + kb) * 2);
                ldsm_x4(ra, ah[mt][0], ah[mt][1], ah[mt][2], ah[mt][3]);
                ldsm_x4(ra + TILE_B, al[mt][0], al[mt][1], al[mt][2], al[mt][3]);
            }
            uint32_t bh[4][2], bl[4][2];
            #pragma unroll
            for (int np = 0; np < 2; np++) {  // each ldsm.x4 covers 2 n-tiles (n16)
                uint32_t rb = sb + 2 * TILE_B +
                              (uint32_t)((wn + np * 16 + b_row) * 80 + (b_ko + kb) * 2);
                ldsm_x4(rb, bh[np * 2][0], bh[np * 2][1], bh[np * 2 + 1][0], bh[np * 2 + 1][1]);
                ldsm_x4(rb + TILE_B, bl[np * 2][0], bl[np * 2][1],
                        bl[np * 2 + 1][0], bl[np * 2 + 1][1]);
            }
            #pragma unroll
            for (int mt = 0; mt < 4; mt++)
                #pragma unroll
                for (int nt = 0; nt < 4; nt++) {
                    mma_bf16(acc[mt][nt], ah[mt][0], ah[mt][1], ah[mt][2], ah[mt][3],
                             bh[nt][0], bh[nt][1]);
                    mma_bf16(acc[mt][nt], ah[mt][0], ah[mt][1], ah[mt][2], ah[mt][3],
                             bl[nt][0], bl[nt][1]);
                    mma_bf16(acc[mt][nt], al[mt][0], al[mt][1], al[mt][2], al[mt][3],
                             bh[nt][0], bh[nt][1]);
                }
        }
    }

    // epilogue: direct global stores + bias
    const int er = lane >> 2, ec = (lane & 3) * 2;
    #pragma unroll
    for (int mt = 0; mt < 4; mt++) {
        #pragma unroll
        for (int nt = 0; nt < 4; nt++) {
            const int col = n0 + wn + nt * 8 + ec;
            const float b0 = bias[col], b1 = bias[col + 1];
            float* p0 = C + (size_t)(m0 + wm + mt * 16 + er) * CQ + col;
            float* p1 = p0 + 8 * CQ;
            float2 v0 = { acc[mt][nt][0] + b0, acc[mt][nt][1] + b1 };
            float2 v1 = { acc[mt][nt][2] + b0, acc[mt][nt][3] + b1 };
            *(float2*)p0 = v0;
            *(float2*)p1 = v1;
        }
    }
}

// ---------------------------------------------------------------------------
// fp32 SGEMM (small Q / O projections)
// ---------------------------------------------------------------------------
__global__ __launch_bounds__(256) void sgemm_bias(
    const float* __restrict__ A, const float* __restrict__ Bm,
    const float* __restrict__ bias, float* __restrict__ C,
    int M, int N, int K)
{
    __shared__ float As[8][128];
    __shared__ float Bs[8][128];
    const int brow = blockIdx.y * 128;
    const int bcol = blockIdx.x * 128;
    const int tid  = threadIdx.x;
    const int a_row = tid >> 1, a_col = (tid & 1) << 2;
    const int b_row = tid >> 5, b_col = (tid & 31) << 2;
    const int tx = tid & 15, ty = tid >> 4;
    const float* Ap = A + (size_t)(brow + a_row) * K + a_col;
    const float* Bp = Bm + (size_t)b_row * N + bcol + b_col;

    float acc[8][8];
    #pragma unroll
    for (int i = 0; i < 8; i++)
        #pragma unroll
        for (int j = 0; j < 8; j++) acc[i][j] = 0.f;

    for (int k0 = 0; k0 < K; k0 += 8) {
        float4 av = *(const float4*)(Ap + k0);
        float4 bv = *(const float4*)(Bp + (size_t)k0 * N);
        As[a_col + 0][a_row] = av.x; As[a_col + 1][a_row] = av.y;
        As[a_col + 2][a_row] = av.z; As[a_col + 3][a_row] = av.w;
        *(float4*)&Bs[b_row][b_col] = bv;
        __syncthreads();
        #pragma unroll
        for (int k = 0; k < 8; k++) {
            float a[8], b[8];
            *(float4*)&a[0] = *(const float4*)&As[k][ty * 8];
            *(float4*)&a[4] = *(const float4*)&As[k][ty * 8 + 4];
            *(float4*)&b[0] = *(const float4*)&Bs[k][tx * 8];
            *(float4*)&b[4] = *(const float4*)&Bs[k][tx * 8 + 4];
            #pragma unroll
            for (int i = 0; i < 8; i++)
                #pragma unroll
                for (int j = 0; j < 8; j++)
                    acc[i][j] = fmaf(a[i], b[j], acc[i][j]);
        }
        __syncthreads();
    }
    float bb[8];
    #pragma unroll
    for (int j = 0; j < 8; j++) bb[j] = bias[bcol + tx * 8 + j];
    #pragma unroll
    for (int i = 0; i < 8; i++) {
        float* Cp = C + (size_t)(brow + ty * 8 + i) * N + bcol + tx * 8;
        float4 o0, o1;
        o0.x = acc[i][0] + bb[0]; o0.y = acc[i][1] + bb[1];
        o0.z = acc[i][2] + bb[2]; o0.w = acc[i][3] + bb[3];
        o1.x = acc[i][4] + bb[4]; o1.y = acc[i][5] + bb[5];
        o1.z = acc[i][6] + bb[6]; o1.w = acc[i][7] + bb[7];
        *(float4*)(Cp) = o0; *(float4*)(Cp + 4) = o1;
    }
}

// ---------------------------------------------------------------------------
// split-KV flash attention partial: one CTA per (b, h, split)
// ---------------------------------------------------------------------------
#define ATT_SMEM (4 * 64 * 65 * 4)
#define KV_PER_SPLIT (NKV / SPLIT)

__global__ __launch_bounds__(256) void attention_partial(
    const float* __restrict__ Qg, const float* __restrict__ Kg,
    const float* __restrict__ Vg,
    float* __restrict__ accP, float* __restrict__ mP, float* __restrict__ lP)
{
    extern __shared__ float sm[];
    float (*Qt)[65] = (float(*)[65])(sm);
    float (*Kt)[65] = (float(*)[65])(sm + 64 * 65);
    float (*Vs)[65] = (float(*)[65])(sm + 2 * 64 * 65);
    float (*Pt)[65] = (float(*)[65])(sm + 3 * 64 * 65);

    const int bh = blockIdx.x / SPLIT;
    const int sp = blockIdx.x % SPLIT;
    const int b = bh / H_, h = bh % H_;
    const int tid = threadIdx.x;
    const int tx = tid & 15, ty = tid >> 4;

    for (int idx = tid; idx < 64 * 64; idx += 256) {
        int rr = idx >> 6, dd = idx & 63;
        Qt[dd][rr] = Qg[(size_t)(b * NQ + rr) * CQ + h * D_ + dd] * 0.125f;
    }

    float acc[4][4], m[4], l[4];
    #pragma unroll
    for (int i = 0; i < 4; i++) {
        m[i] = -1e30f; l[i] = 0.f;
        #pragma unroll
        for (int j = 0; j < 4; j++) acc[i][j] = 0.f;
    }

    const int kv_base = sp * KV_PER_SPLIT;
    for (int kv0 = kv_base; kv0 < kv_base + KV_PER_SPLIT; kv0 += 64) {
        __syncthreads();
        for (int idx = tid; idx < 64 * 64; idx += 256) {
            int rr = idx >> 6, dd = idx & 63;
            size_t g = (size_t)(b * NKV + kv0 + rr) * CQ + h * D_ + dd;
            Kt[dd][rr] = Kg[g];
            Vs[rr][dd] = Vg[g];
        }
        __syncthreads();

        float s[4][4];
        #pragma unroll
        for (int i = 0; i < 4; i++)
            #pragma unroll
            for (int j = 0; j < 4; j++) s[i][j] = 0.f;
        #pragma unroll 4
        for (int d = 0; d < 64; d++) {
            float a[4], bb[4];
            #pragma unroll
            for (int i = 0; i < 4; i++) a[i]  = Qt[d][ty * 4 + i];
            #pragma unroll
            for (int j = 0; j < 4; j++) bb[j] = Kt[d][tx * 4 + j];
            #pragma unroll
            for (int i = 0; i < 4; i++)
                #pragma unroll
                for (int j = 0; j < 4; j++)
                    s[i][j] = fmaf(a[i], bb[j], s[i][j]);
        }

        #pragma unroll
        for (int ii = 0; ii < 4; ii++) {
            float mx = fmaxf(fmaxf(s[ii][0], s[ii][1]), fmaxf(s[ii][2], s[ii][3]));
            #pragma unroll
            for (int o = 1; o < 16; o <<= 1)
                mx = fmaxf(mx, __shfl_xor_sync(0xffffffffu, mx, o));
            float mnew = fmaxf(m[ii], mx);
            float corr = __expf(m[ii] - mnew);
            float ls = 0.f;
            #pragma unroll
            for (int jj = 0; jj < 4; jj++) {
                float p = __expf(s[ii][jj] - mnew);
                s[ii][jj] = p; ls += p;
            }
            #pragma unroll
            for (int o = 1; o < 16; o <<= 1)
                ls += __shfl_xor_sync(0xffffffffu, ls, o);
            l[ii] = l[ii] * corr + ls;
            m[ii] = mnew;
            #pragma unroll
            for (int jj = 0; jj < 4; jj++) {
                acc[ii][jj] *= corr;
                Pt[tx * 4 + jj][ty * 4 + ii] = s[ii][jj];
            }
        }
        __syncwarp();

        #pragma unroll 4
        for (int j = 0; j < 64; j++) {
            float p[4], v[4];
            #pragma unroll
            for (int i = 0; i < 4; i++) p[i] = Pt[j][ty * 4 + i];
            #pragma unroll
            for (int c = 0; c < 4; c++) v[c] = Vs[j][tx * 4 + c];
            #pragma unroll
            for (int i = 0; i < 4; i++)
                #pragma unroll
                for (int c = 0; c < 4; c++)
                    acc[i][c] = fmaf(p[i], v[c], acc[i][c]);
        }
    }

    float* accp = accP + (size_t)blockIdx.x * 64 * 64;
    #pragma unroll
    for (int ii = 0; ii < 4; ii++) {
        int r = ty * 4 + ii;
        #pragma unroll
        for (int jj = 0; jj < 4; jj++)
            accp[r * 64 + tx * 4 + jj] = acc[ii][jj];
        if (tx == 0) {
            mP[(size_t)blockIdx.x * 64 + r] = m[ii];
            lP[(size_t)blockIdx.x * 64 + r] = l[ii];
        }
    }
}

__global__ __launch_bounds__(256) void attention_combine(
    const float* __restrict__ accP, const float* __restrict__ mP,
    const float* __restrict__ lP, float* __restrict__ Xg)
{
    __shared__ float sw[SPLIT][64];
    __shared__ float sden[64];
    const int bh = blockIdx.x;
    const int b = bh / H_, h = bh % H_;
    const int tid = threadIdx.x;

    if (tid < 64) {
        int r = tid;
        float M = -1e30f;
        #pragma unroll
        for (int s = 0; s < SPLIT; s++)
            M = fmaxf(M, mP[(size_t)(bh * SPLIT + s) * 64 + r]);
        float den = 0.f;
        #pragma unroll
        for (int s = 0; s < SPLIT; s++) {
            float w = __expf(mP[(size_t)(bh * SPLIT + s) * 64 + r] - M);
            sw[s][r] = w;
            den += w * lP[(size_t)(bh * SPLIT + s) * 64 + r];
        }
        sden[r] = den;
    }
    __syncthreads();

    for (int idx = tid; idx < 64 * 64; idx += 256) {
        int r = idx >> 6, d = idx & 63;
        float num = 0.f;
        #pragma unroll
        for (int s = 0; s < SPLIT; s++)
            num += sw[s][r] * accP[(size_t)(bh * SPLIT + s) * 4096 + idx];
        Xg[(size_t)(b * NQ + r) * CQ + h * D_ + d] = num / sden[r];
    }
}

// ---------------------------------------------------------------------------
extern "C" void kernel_launch(void* const* d_in, const int* in_sizes, int n_in,
                              void* d_out, int out_size)
{
    const float* query = (const float*)d_in[0];
    const float* kv    = (const float*)d_in[1];
    const float* Wq    = (const float*)d_in[2];
    const float* bq    = (const float*)d_in[3];
    const float* Wk    = (const float*)d_in[4];
    const float* bk    = (const float*)d_in[5];
    const float* Wv    = (const float*)d_in[6];
    const float* bv    = (const float*)d_in[7];
    const float* Wo    = (const float*)d_in[8];
    const float* bo    = (const float*)d_in[9];
    float* out = (float*)d_out;

    float *qp, *kp, *vp, *xp, *accp, *mp, *lp;
    __nv_bfloat16 *kvh, *kvl, *wkth, *wktl, *wvth, *wvtl;
    cudaGetSymbolAddress((void**)&qp, g_q);
    cudaGetSymbolAddress((void**)&kp, g_k);
    cudaGetSymbolAddress((void**)&vp, g_v);
    cudaGetSymbolAddress((void**)&xp, g_x);
    cudaGetSymbolAddress((void**)&kvh, g_kvh);
    cudaGetSymbolAddress((void**)&kvl, g_kvl);
    cudaGetSymbolAddress((void**)&wkth, g_wkth);
    cudaGetSymbolAddress((void**)&wktl, g_wktl);
    cudaGetSymbolAddress((void**)&wvth, g_wvth);
    cudaGetSymbolAddress((void**)&wvtl, g_wvtl);
    cudaGetSymbolAddress((void**)&accp, g_accP);
    cudaGetSymbolAddress((void**)&mp, g_mP);
    cudaGetSymbolAddress((void**)&lp, g_lP);

    cudaFuncSetAttribute(attention_partial,
                         cudaFuncAttributeMaxDynamicSharedMemorySize, ATT_SMEM);
    cudaFuncSetAttribute(hgemm_bf16x3,
                         cudaFuncAttributeMaxDynamicSharedMemorySize, HGEMM_SMEM);

    // 1. prep: split kv; transpose+split weights
    split_kernel<<<2048, 256>>>(kv, kvh, kvl, (size_t)B_ * NKV * CKV);
    transpose_split_kernel<<<dim3(CKV / 256, CQ), 256>>>(Wk, wkth, wktl);
    transpose_split_kernel<<<dim3(CKV / 256, CQ), 256>>>(Wv, wvth, wvtl);

    // 2. q projection (small, fp32)
    sgemm_bias<<<dim3(CQ / 128, (B_ * NQ) / 128), 256>>>(
        query, Wq, bq, qp, B_ * NQ, CQ, CQ);

    // 3. K / V projections on HMMA tensor cores (bf16x3)
    dim3 ggrid(CQ / 128, (B_ * NKV) / 128);   // (6, 512)
    hgemm_bf16x3<<<ggrid, 256, HGEMM_SMEM>>>(kvh, kvl, wkth, wktl, bk, kp);
    hgemm_bf16x3<<<ggrid, 256, HGEMM_SMEM>>>(kvh, kvl, wvth, wvtl, bv, vp);

    // 4. split-KV attention + combine
    attention_partial<<<B_ * H_ * SPLIT, 256, ATT_SMEM>>>(qp, kp, vp, accp, mp, lp);
    attention_combine<<<B_ * H_, 256>>>(accp, mp, lp, xp);

    // 5. output projection
    sgemm_bias<<<dim3(CQ / 128, (B_ * NQ) / 128), 256>>>(
        xp, Wo, bo, out, B_ * NQ, CQ, CQ);
}

// round 5
// speedup vs baseline: 2.4990x; 1.3637x over previous
#include <cuda_runtime.h>
#include <cuda_bf16.h>
#include <cuda_fp16.h>
#include <math.h>
#include <stdint.h>

#define B_   16
#define NQ   64
#define NKV  4096
#define CQ   768
#define CKV  1024
#define H_   12
#define D_   64
#define SPLIT 8

// ---------------- scratch (device globals; allocation-free) ----------------
__device__ float g_q[(size_t)B_ * NQ * CQ];
__device__ float g_k[(size_t)B_ * NKV * CQ];
__device__ float g_v[(size_t)B_ * NKV * CQ];
__device__ float g_x[(size_t)B_ * NQ * CQ];
__device__ __half g_kva[(size_t)B_ * NKV * CKV];      // kv rounded to fp16
__device__ __half g_wkth[(size_t)CQ * CKV];
__device__ __half g_wktl[(size_t)CQ * CKV];
__device__ __half g_wvth[(size_t)CQ * CKV];
__device__ __half g_wvtl[(size_t)CQ * CKV];
__device__ float g_accP[(size_t)B_ * H_ * SPLIT * NQ * D_];
__device__ float g_mP[(size_t)B_ * H_ * SPLIT * NQ];
__device__ float g_lP[(size_t)B_ * H_ * SPLIT * NQ];

// ---------------- helpers ----------------
__device__ __forceinline__ uint32_t smem_u32(const void* p) {
    uint32_t a;
    asm("{ .reg .u64 t; cvta.to.shared.u64 t, %1; cvt.u32.u64 %0, t; }"
        : "=r"(a) : "l"(p));
    return a;
}
__device__ __forceinline__ void cp16(uint32_t s, const void* g) {
    asm volatile("cp.async.cg.shared.global [%0], [%1], 16;\n"
                 :: "r"(s), "l"(__cvta_generic_to_global(g)) : "memory");
}
#define CP_COMMIT() asm volatile("cp.async.commit_group;\n" ::: "memory")
#define CP_WAIT(n)  asm volatile("cp.async.wait_group %0;\n" :: "n"(n) : "memory")

__device__ __forceinline__ void ldsm_x4(uint32_t addr, uint32_t& r0, uint32_t& r1,
                                        uint32_t& r2, uint32_t& r3) {
    asm volatile("ldmatrix.sync.aligned.m8n8.x4.shared.b16 {%0,%1,%2,%3}, [%4];"
                 : "=r"(r0), "=r"(r1), "=r"(r2), "=r"(r3) : "r"(addr));
}
__device__ __forceinline__ void mma_f16(float* d, uint32_t a0, uint32_t a1,
                                        uint32_t a2, uint32_t a3,
                                        uint32_t b0, uint32_t b1) {
    asm volatile(
        "mma.sync.aligned.m16n8k16.row.col.f32.f16.f16.f32 "
        "{%0,%1,%2,%3}, {%4,%5,%6,%7}, {%8,%9}, {%0,%1,%2,%3};"
        : "+f"(d[0]), "+f"(d[1]), "+f"(d[2]), "+f"(d[3])
        : "r"(a0), "r"(a1), "r"(a2), "r"(a3), "r"(b0), "r"(b1));
}

// ---------------------------------------------------------------------------
// fp32 -> fp16 round (for kv)
// ---------------------------------------------------------------------------
__global__ __launch_bounds__(256) void round_kernel(
    const float* __restrict__ src, __half* __restrict__ dst, size_t n4)
{
    size_t i = (size_t)blockIdx.x * blockDim.x + threadIdx.x;
    size_t stride = (size_t)gridDim.x * blockDim.x;
    for (; i < n4; i += stride) {
        float4 x = ((const float4*)src)[i];
        __half2 lo = __floats2half2_rn(x.x, x.y);
        __half2 hi = __floats2half2_rn(x.z, x.w);
        ((__half2*)dst)[i * 2]     = lo;
        ((__half2*)dst)[i * 2 + 1] = hi;
    }
}

// W [K=1024][N=768] -> Wt hi/lo [N=768][K=1024] fp16
__global__ __launch_bounds__(256) void transpose_split_kernel(
    const float* __restrict__ W, __half* __restrict__ th,
    __half* __restrict__ tl)
{
    int n = blockIdx.y;
    int k = blockIdx.x * 256 + threadIdx.x;
    float x = W[(size_t)k * CQ + n];
    __half h = __float2half_rn(x);
    th[(size_t)n * CKV + k] = h;
    tl[(size_t)n * CKV + k] = __float2half_rn(x - __half2float(h));
}

// ---------------------------------------------------------------------------
// HMMA fp16x2 GEMM: C[M=65536, N=768] = A16 Bh^T + A16 Bl^T + bias
// A fp16 row-major [M,1024]; B hi/lo fp16 row-major [768,1024].
// CTA 128x128x32, 8 warps (warp tile 64x32), 3-stage cp.async pipeline.
// ---------------------------------------------------------------------------
#define LDS_E 40                      // padded fp16 row stride (80 bytes)
#define TILE_B (128 * LDS_E * 2)      // 10240 bytes per (128x32) tile
#define STAGE_B (3 * TILE_B)          // A, Bh, Bl
#define STAGES 3
#define HGEMM_SMEM (STAGES * STAGE_B) // 92160
#define KT_N (CKV / 32)               // 32 k-tiles

__global__ __launch_bounds__(256, 1) void hgemm_f16x2(
    const __half* __restrict__ A_g,
    const __half* __restrict__ Bh_g, const __half* __restrict__ Bl_g,
    const float* __restrict__ bias, float* __restrict__ C)
{
    extern __shared__ char smem[];
    const uint32_t sbase = smem_u32(smem);
    const int tid = threadIdx.x;
    const int wid = tid >> 5, lane = tid & 31;
    const int wm = (wid & 1) * 64;
    const int wn = (wid >> 1) * 32;
    const int m0 = blockIdx.y * 128, n0 = blockIdx.x * 128;

    const int lr = tid >> 1;
    const int lc = (tid & 1) * 16;
    const uint32_t s_off = (uint32_t)(lr * 80 + (tid & 1) * 32);

    const __half* gA  = A_g  + (size_t)(m0 + lr) * CKV + lc;
    const __half* gBh = Bh_g + (size_t)(n0 + lr) * CKV + lc;
    const __half* gBl = Bl_g + (size_t)(n0 + lr) * CKV + lc;

    const int a_row = lane & 15;
    const int a_ko  = ((lane >> 4) & 1) * 8;
    const int b_row = (lane & 7) + ((lane >> 4) & 1) * 8;
    const int b_ko  = ((lane >> 3) & 1) * 8;

    float acc[4][4][4];
    #pragma unroll
    for (int i = 0; i < 4; i++)
        #pragma unroll
        for (int j = 0; j < 4; j++)
            #pragma unroll
            for (int c = 0; c < 4; c++) acc[i][j][c] = 0.f;

    auto load_stage = [&](int kt, int s) {
        const uint32_t sb = sbase + s * STAGE_B;
        const int ke = kt * 32;
        cp16(sb + s_off,                   gA  + ke);
        cp16(sb + s_off + 16,              gA  + ke + 8);
        cp16(sb + TILE_B + s_off,          gBh + ke);
        cp16(sb + TILE_B + s_off + 16,     gBh + ke + 8);
        cp16(sb + 2 * TILE_B + s_off,      gBl + ke);
        cp16(sb + 2 * TILE_B + s_off + 16, gBl + ke + 8);
    };

    load_stage(0, 0); CP_COMMIT();
    load_stage(1, 1); CP_COMMIT();

    for (int kt = 0; kt < KT_N; kt++) {
        CP_WAIT(1);
        __syncthreads();

        const int nkt = kt + STAGES - 1;
        if (nkt < KT_N) load_stage(nkt, nkt % STAGES);
        CP_COMMIT();

        const uint32_t sb = sbase + (kt % STAGES) * STAGE_B;
        #pragma unroll
        for (int kb = 0; kb < 32; kb += 16) {
            uint32_t ah[4][4];
            #pragma unroll
            for (int mt = 0; mt < 4; mt++) {
                uint32_t ra = sb + (uint32_t)((wm + mt * 16 + a_row) * 80 + (a_ko + kb) * 2);
                ldsm_x4(ra, ah[mt][0], ah[mt][1], ah[mt][2], ah[mt][3]);
            }
            uint32_t bh[4][2], bl[4][2];
            #pragma unroll
            for (int np = 0; np < 2; np++) {
                uint32_t rb = sb + TILE_B +
                              (uint32_t)((wn + np * 16 + b_row) * 80 + (b_ko + kb) * 2);
                ldsm_x4(rb, bh[np * 2][0], bh[np * 2][1], bh[np * 2 + 1][0], bh[np * 2 + 1][1]);
                ldsm_x4(rb + TILE_B, bl[np * 2][0], bl[np * 2][1],
                        bl[np * 2 + 1][0], bl[np * 2 + 1][1]);
            }
            #pragma unroll
            for (int mt = 0; mt < 4; mt++)
                #pragma unroll
                for (int nt = 0; nt < 4; nt++) {
                    mma_f16(acc[mt][nt], ah[mt][0], ah[mt][1], ah[mt][2], ah[mt][3],
                            bh[nt][0], bh[nt][1]);
                    mma_f16(acc[mt][nt], ah[mt][0], ah[mt][1], ah[mt][2], ah[mt][3],
                            bl[nt][0], bl[nt][1]);
                }
        }
    }

    const int er = lane >> 2, ec = (lane & 3) * 2;
    #pragma unroll
    for (int mt = 0; mt < 4; mt++) {
        #pragma unroll
        for (int nt = 0; nt < 4; nt++) {
            const int col = n0 + wn + nt * 8 + ec;
            const float b0 = bias[col], b1 = bias[col + 1];
            float* p0 = C + (size_t)(m0 + wm + mt * 16 + er) * CQ + col;
            float* p1 = p0 + 8 * CQ;
            float2 v0 = { acc[mt][nt][0] + b0, acc[mt][nt][1] + b1 };
            float2 v1 = { acc[mt][nt][2] + b0, acc[mt][nt][3] + b1 };
            *(float2*)p0 = v0;
            *(float2*)p1 = v1;
        }
    }
}

// ---------------------------------------------------------------------------
// fp32 SGEMM, 64x64 tile (small Q / O projections; better SM coverage)
// ---------------------------------------------------------------------------
__global__ __launch_bounds__(256) void sgemm_bias64(
    const float* __restrict__ A, const float* __restrict__ Bm,
    const float* __restrict__ bias, float* __restrict__ C,
    int M, int N, int K)
{
    __shared__ float As[16][68];
    __shared__ float Bs[16][64];
    const int brow = blockIdx.y * 64;
    const int bcol = blockIdx.x * 64;
    const int tid  = threadIdx.x;
    const int a_row = tid >> 2, a_col = (tid & 3) << 2;   // 64 rows x 16 k
    const int b_row = tid >> 4, b_col = (tid & 15) << 2;  // 16 k x 64 cols
    const int tx = tid & 15, ty = tid >> 4;

    float acc[4][4];
    #pragma unroll
    for (int i = 0; i < 4; i++)
        #pragma unroll
        for (int j = 0; j < 4; j++) acc[i][j] = 0.f;

    for (int k0 = 0; k0 < K; k0 += 16) {
        float4 av = *(const float4*)(A + (size_t)(brow + a_row) * K + k0 + a_col);
        float4 bv = *(const float4*)(Bm + (size_t)(k0 + b_row) * N + bcol + b_col);
        As[a_col + 0][a_row] = av.x; As[a_col + 1][a_row] = av.y;
        As[a_col + 2][a_row] = av.z; As[a_col + 3][a_row] = av.w;
        *(float4*)&Bs[b_row][b_col] = bv;
        __syncthreads();
        #pragma unroll
        for (int k = 0; k < 16; k++) {
            float a[4], b[4];
            *(float4*)&a[0] = *(const float4*)&As[k][ty * 4];
            *(float4*)&b[0] = *(const float4*)&Bs[k][tx * 4];
            #pragma unroll
            for (int i = 0; i < 4; i++)
                #pragma unroll
                for (int j = 0; j < 4; j++)
                    acc[i][j] = fmaf(a[i], b[j], acc[i][j]);
        }
        __syncthreads();
    }
    float bb[4];
    #pragma unroll
    for (int j = 0; j < 4; j++) bb[j] = bias[bcol + tx * 4 + j];
    #pragma unroll
    for (int i = 0; i < 4; i++) {
        float* Cp = C + (size_t)(brow + ty * 4 + i) * N + bcol + tx * 4;
        float4 o;
        o.x = acc[i][0] + bb[0]; o.y = acc[i][1] + bb[1];
        o.z = acc[i][2] + bb[2]; o.w = acc[i][3] + bb[3];
        *(float4*)Cp = o;
    }
}

// ---------------------------------------------------------------------------
// split-KV flash attention partial: one CTA per (b, h, split)
// ---------------------------------------------------------------------------
#define ATT_SMEM (4 * 64 * 65 * 4)
#define KV_PER_SPLIT (NKV / SPLIT)

__global__ __launch_bounds__(256) void attention_partial(
    const float* __restrict__ Qg, const float* __restrict__ Kg,
    const float* __restrict__ Vg,
    float* __restrict__ accP, float* __restrict__ mP, float* __restrict__ lP)
{
    extern __shared__ float sm[];
    float (*Qt)[65] = (float(*)[65])(sm);
    float (*Kt)[65] = (float(*)[65])(sm + 64 * 65);
    float (*Vs)[65] = (float(*)[65])(sm + 2 * 64 * 65);
    float (*Pt)[65] = (float(*)[65])(sm + 3 * 64 * 65);

    const int bh = blockIdx.x / SPLIT;
    const int sp = blockIdx.x % SPLIT;
    const int b = bh / H_, h = bh % H_;
    const int tid = threadIdx.x;
    const int tx = tid & 15, ty = tid >> 4;

    for (int idx = tid; idx < 64 * 64; idx += 256) {
        int rr = idx >> 6, dd = idx & 63;
        Qt[dd][rr] = Qg[(size_t)(b * NQ + rr) * CQ + h * D_ + dd] * 0.125f;
    }

    float acc[4][4], m[4], l[4];
    #pragma unroll
    for (int i = 0; i < 4; i++) {
        m[i] = -1e30f; l[i] = 0.f;
        #pragma unroll
        for (int j = 0; j < 4; j++) acc[i][j] = 0.f;
    }

    const int kv_base = sp * KV_PER_SPLIT;
    for (int kv0 = kv_base; kv0 < kv_base + KV_PER_SPLIT; kv0 += 64) {
        __syncthreads();
        for (int idx = tid; idx < 64 * 64; idx += 256) {
            int rr = idx >> 6, dd = idx & 63;
            size_t g = (size_t)(b * NKV + kv0 + rr) * CQ + h * D_ + dd;
            Kt[dd][rr] = Kg[g];
            Vs[rr][dd] = Vg[g];
        }
        __syncthreads();

        float s[4][4];
        #pragma unroll
        for (int i = 0; i < 4; i++)
            #pragma unroll
            for (int j = 0; j < 4; j++) s[i][j] = 0.f;
        #pragma unroll 4
        for (int d = 0; d < 64; d++) {
            float a[4], bb[4];
            #pragma unroll
            for (int i = 0; i < 4; i++) a[i]  = Qt[d][ty * 4 + i];
            #pragma unroll
            for (int j = 0; j < 4; j++) bb[j] = Kt[d][tx * 4 + j];
            #pragma unroll
            for (int i = 0; i < 4; i++)
                #pragma unroll
                for (int j = 0; j < 4; j++)
                    s[i][j] = fmaf(a[i], bb[j], s[i][j]);
        }

        #pragma unroll
        for (int ii = 0; ii < 4; ii++) {
            float mx = fmaxf(fmaxf(s[ii][0], s[ii][1]), fmaxf(s[ii][2], s[ii][3]));
            #pragma unroll
            for (int o = 1; o < 16; o <<= 1)
                mx = fmaxf(mx, __shfl_xor_sync(0xffffffffu, mx, o));
            float mnew = fmaxf(m[ii], mx);
            float corr = __expf(m[ii] - mnew);
            float ls = 0.f;
            #pragma unroll
            for (int jj = 0; jj < 4; jj++) {
                float p = __expf(s[ii][jj] - mnew);
                s[ii][jj] = p; ls += p;
            }
            #pragma unroll
            for (int o = 1; o < 16; o <<= 1)
                ls += __shfl_xor_sync(0xffffffffu, ls, o);
            l[ii] = l[ii] * corr + ls;
            m[ii] = mnew;
            #pragma unroll
            for (int jj = 0; jj < 4; jj++) {
                acc[ii][jj] *= corr;
                Pt[tx * 4 + jj][ty * 4 + ii] = s[ii][jj];
            }
        }
        __syncwarp();

        #pragma unroll 4
        for (int j = 0; j < 64; j++) {
            float p[4], v[4];
            #pragma unroll
            for (int i = 0; i < 4; i++) p[i] = Pt[j][ty * 4 + i];
            #pragma unroll
            for (int c = 0; c < 4; c++) v[c] = Vs[j][tx * 4 + c];
            #pragma unroll
            for (int i = 0; i < 4; i++)
                #pragma unroll
                for (int c = 0; c < 4; c++)
                    acc[i][c] = fmaf(p[i], v[c], acc[i][c]);
        }
    }

    float* accp = accP + (size_t)blockIdx.x * 64 * 64;
    #pragma unroll
    for (int ii = 0; ii < 4; ii++) {
        int r = ty * 4 + ii;
        #pragma unroll
        for (int jj = 0; jj < 4; jj++)
            accp[r * 64 + tx * 4 + jj] = acc[ii][jj];
        if (tx == 0) {
            mP[(size_t)blockIdx.x * 64 + r] = m[ii];
            lP[(size_t)blockIdx.x * 64 + r] = l[ii];
        }
    }
}

__global__ __launch_bounds__(256) void attention_combine(
    const float* __restrict__ accP, const float* __restrict__ mP,
    const float* __restrict__ lP, float* __restrict__ Xg)
{
    __shared__ float sw[SPLIT][64];
    __shared__ float sden[64];
    const int bh = blockIdx.x;
    const int b = bh / H_, h = bh % H_;
    const int tid = threadIdx.x;

    if (tid < 64) {
        int r = tid;
        float M = -1e30f;
        #pragma unroll
        for (int s = 0; s < SPLIT; s++)
            M = fmaxf(M, mP[(size_t)(bh * SPLIT + s) * 64 + r]);
        float den = 0.f;
        #pragma unroll
        for (int s = 0; s < SPLIT; s++) {
            float w = __expf(mP[(size_t)(bh * SPLIT + s) * 64 + r] - M);
            sw[s][r] = w;
            den += w * lP[(size_t)(bh * SPLIT + s) * 64 + r];
        }
        sden[r] = den;
    }
    __syncthreads();

    for (int idx = tid; idx < 64 * 64; idx += 256) {
        int r = idx >> 6, d = idx & 63;
        float num = 0.f;
        #pragma unroll
        for (int s = 0; s < SPLIT; s++)
            num += sw[s][r] * accP[(size_t)(bh * SPLIT + s) * 4096 + idx];
        Xg[(size_t)(b * NQ + r) * CQ + h * D_ + d] = num / sden[r];
    }
}

// ---------------------------------------------------------------------------
extern "C" void kernel_launch(void* const* d_in, const int* in_sizes, int n_in,
                              void* d_out, int out_size)
{
    const float* query = (const float*)d_in[0];
    const float* kv    = (const float*)d_in[1];
    const float* Wq    = (const float*)d_in[2];
    const float* bq    = (const float*)d_in[3];
    const float* Wk    = (const float*)d_in[4];
    const float* bk    = (const float*)d_in[5];
    const float* Wv    = (const float*)d_in[6];
    const float* bv    = (const float*)d_in[7];
    const float* Wo    = (const float*)d_in[8];
    const float* bo    = (const float*)d_in[9];
    float* out = (float*)d_out;

    float *qp, *kp, *vp, *xp, *accp, *mp, *lp;
    __half *kva, *wkth, *wktl, *wvth, *wvtl;
    cudaGetSymbolAddress((void**)&qp, g_q);
    cudaGetSymbolAddress((void**)&kp, g_k);
    cudaGetSymbolAddress((void**)&vp, g_v);
    cudaGetSymbolAddress((void**)&xp, g_x);
    cudaGetSymbolAddress((void**)&kva, g_kva);
    cudaGetSymbolAddress((void**)&wkth, g_wkth);
    cudaGetSymbolAddress((void**)&wktl, g_wktl);
    cudaGetSymbolAddress((void**)&wvth, g_wvth);
    cudaGetSymbolAddress((void**)&wvtl, g_wvtl);
    cudaGetSymbolAddress((void**)&accp, g_accP);
    cudaGetSymbolAddress((void**)&mp, g_mP);
    cudaGetSymbolAddress((void**)&lp, g_lP);

    cudaFuncSetAttribute(attention_partial,
                         cudaFuncAttributeMaxDynamicSharedMemorySize, ATT_SMEM);
    cudaFuncSetAttribute(hgemm_f16x2,
                         cudaFuncAttributeMaxDynamicSharedMemorySize, HGEMM_SMEM);

    // 1. prep: round kv to fp16; transpose+split weights (fp16 hi/lo)
    round_kernel<<<2048, 256>>>(kv, kva, (size_t)B_ * NKV * CKV / 4);
    transpose_split_kernel<<<dim3(CKV / 256, CQ), 256>>>(Wk, wkth, wktl);
    transpose_split_kernel<<<dim3(CKV / 256, CQ), 256>>>(Wv, wvth, wvtl);

    // 2. q projection (small, fp32, 64x64 tiles)
    sgemm_bias64<<<dim3(CQ / 64, (B_ * NQ) / 64), 256>>>(
        query, Wq, bq, qp, B_ * NQ, CQ, CQ);

    // 3. K / V projections on HMMA tensor cores (fp16 x 2-pass)
    dim3 ggrid(CQ / 128, (B_ * NKV) / 128);   // (6, 512)
    hgemm_f16x2<<<ggrid, 256, HGEMM_SMEM>>>(kva, wkth, wktl, bk, kp);
    hgemm_f16x2<<<ggrid, 256, HGEMM_SMEM>>>(kva, wvth, wvtl, bv, vp);

    // 4. split-KV attention + combine
    attention_partial<<<B_ * H_ * SPLIT, 256, ATT_SMEM>>>(qp, kp, vp, accp, mp, lp);
    attention_combine<<<B_ * H_, 256>>>(accp, mp, lp, xp);

    // 5. output projection
    sgemm_bias64<<<dim3(CQ / 64, (B_ * NQ) / 64), 256>>>(
        xp, Wo, bo, out, B_ * NQ, CQ, CQ);
}

// round 6
// speedup vs baseline: 3.6967x; 1.4793x over previous
#include <cuda_runtime.h>
#include <cuda_bf16.h>
#include <cuda_fp16.h>
#include <math.h>
#include <stdint.h>

#define B_   16
#define NQ   64
#define NKV  4096
#define CQ   768
#define CKV  1024
#define H_   12
#define D_   64
#define SPLIT 8

// ---------------- scratch (device globals; allocation-free) ----------------
__device__ float g_q[(size_t)B_ * NQ * CQ];
__device__ float g_k[(size_t)B_ * NKV * CQ];
__device__ float g_v[(size_t)B_ * NKV * CQ];
__device__ float g_x[(size_t)B_ * NQ * CQ];
__device__ __half g_kva[(size_t)B_ * NKV * CKV];
__device__ __half g_wkt[(size_t)CQ * CKV];
__device__ __half g_wvt[(size_t)CQ * CKV];
__device__ float g_accP[(size_t)B_ * H_ * SPLIT * NQ * D_];
__device__ float g_mP[(size_t)B_ * H_ * SPLIT * NQ];
__device__ float g_lP[(size_t)B_ * H_ * SPLIT * NQ];

// ---------------- helpers ----------------
__device__ __forceinline__ uint32_t smem_u32(const void* p) {
    uint32_t a;
    asm("{ .reg .u64 t; cvta.to.shared.u64 t, %1; cvt.u32.u64 %0, t; }"
        : "=r"(a) : "l"(p));
    return a;
}
__device__ __forceinline__ void cp16(uint32_t s, const void* g) {
    asm volatile("cp.async.cg.shared.global [%0], [%1], 16;\n"
                 :: "r"(s), "l"(__cvta_generic_to_global(g)) : "memory");
}
#define CP_COMMIT() asm volatile("cp.async.commit_group;\n" ::: "memory")
#define CP_WAIT(n)  asm volatile("cp.async.wait_group %0;\n" :: "n"(n) : "memory")

__device__ __forceinline__ void ldsm_x4(uint32_t addr, uint32_t& r0, uint32_t& r1,
                                        uint32_t& r2, uint32_t& r3) {
    asm volatile("ldmatrix.sync.aligned.m8n8.x4.shared.b16 {%0,%1,%2,%3}, [%4];"
                 : "=r"(r0), "=r"(r1), "=r"(r2), "=r"(r3) : "r"(addr));
}
__device__ __forceinline__ void mma_f16(float* d, uint32_t a0, uint32_t a1,
                                        uint32_t a2, uint32_t a3,
                                        uint32_t b0, uint32_t b1) {
    asm volatile(
        "mma.sync.aligned.m16n8k16.row.col.f32.f16.f16.f32 "
        "{%0,%1,%2,%3}, {%4,%5,%6,%7}, {%8,%9}, {%0,%1,%2,%3};"
        : "+f"(d[0]), "+f"(d[1]), "+f"(d[2]), "+f"(d[3])
        : "r"(a0), "r"(a1), "r"(a2), "r"(a3), "r"(b0), "r"(b1));
}

// ---------------------------------------------------------------------------
// fp32 -> fp16 round (for kv)
// ---------------------------------------------------------------------------
__global__ __launch_bounds__(256) void round_kernel(
    const float* __restrict__ src, __half* __restrict__ dst, size_t n4)
{
    size_t i = (size_t)blockIdx.x * blockDim.x + threadIdx.x;
    size_t stride = (size_t)gridDim.x * blockDim.x;
    for (; i < n4; i += stride) {
        float4 x = ((const float4*)src)[i];
        __half2 lo = __floats2half2_rn(x.x, x.y);
        __half2 hi = __floats2half2_rn(x.z, x.w);
        ((__half2*)dst)[i * 2]     = lo;
        ((__half2*)dst)[i * 2 + 1] = hi;
    }
}

// W [K=1024][N=768] -> Wt [N=768][K=1024] fp16
__global__ __launch_bounds__(256) void transpose_f16_kernel(
    const float* __restrict__ W, __half* __restrict__ th)
{
    int n = blockIdx.y;
    int k = blockIdx.x * 256 + threadIdx.x;
    th[(size_t)n * CKV + k] = __float2half_rn(W[(size_t)k * CQ + n]);
}

// ---------------------------------------------------------------------------
// HMMA fp16 GEMM: C[M=65536, N=768] = A16 B16^T + bias
// A fp16 row-major [M,1024]; B fp16 row-major [768,1024].
// CTA 128x128x32, 8 warps (warp tile 64x32), 3-stage cp.async pipeline.
// ---------------------------------------------------------------------------
#define LDS_E 40                      // padded fp16 row stride (80 bytes)
#define TILE_B (128 * LDS_E * 2)      // 10240 bytes per (128x32) tile
#define STAGE_B (2 * TILE_B)          // A, B
#define STAGES 3
#define HGEMM_SMEM (STAGES * STAGE_B) // 61440
#define KT_N (CKV / 32)               // 32 k-tiles

__global__ __launch_bounds__(256, 1) void hgemm_f16(
    const __half* __restrict__ A_g, const __half* __restrict__ B_g,
    const float* __restrict__ bias, float* __restrict__ C)
{
    extern __shared__ char smem[];
    const uint32_t sbase = smem_u32(smem);
    const int tid = threadIdx.x;
    const int wid = tid >> 5, lane = tid & 31;
    const int wm = (wid & 1) * 64;
    const int wn = (wid >> 1) * 32;
    const int m0 = blockIdx.y * 128, n0 = blockIdx.x * 128;

    const int lr = tid >> 1;
    const int lc = (tid & 1) * 16;
    const uint32_t s_off = (uint32_t)(lr * 80 + (tid & 1) * 32);

    const __half* gA = A_g + (size_t)(m0 + lr) * CKV + lc;
    const __half* gB = B_g + (size_t)(n0 + lr) * CKV + lc;

    const int a_row = lane & 15;
    const int a_ko  = ((lane >> 4) & 1) * 8;
    const int b_row = (lane & 7) + ((lane >> 4) & 1) * 8;
    const int b_ko  = ((lane >> 3) & 1) * 8;

    float acc[4][4][4];
    #pragma unroll
    for (int i = 0; i < 4; i++)
        #pragma unroll
        for (int j = 0; j < 4; j++)
            #pragma unroll
            for (int c = 0; c < 4; c++) acc[i][j][c] = 0.f;

    auto load_stage = [&](int kt, int s) {
        const uint32_t sb = sbase + s * STAGE_B;
        const int ke = kt * 32;
        cp16(sb + s_off,               gA + ke);
        cp16(sb + s_off + 16,          gA + ke + 8);
        cp16(sb + TILE_B + s_off,      gB + ke);
        cp16(sb + TILE_B + s_off + 16, gB + ke + 8);
    };

    load_stage(0, 0); CP_COMMIT();
    load_stage(1, 1); CP_COMMIT();

    for (int kt = 0; kt < KT_N; kt++) {
        CP_WAIT(1);
        __syncthreads();

        const int nkt = kt + STAGES - 1;
        if (nkt < KT_N) load_stage(nkt, nkt % STAGES);
        CP_COMMIT();

        const uint32_t sb = sbase + (kt % STAGES) * STAGE_B;
        #pragma unroll
        for (int kb = 0; kb < 32; kb += 16) {
            uint32_t ah[4][4];
            #pragma unroll
            for (int mt = 0; mt < 4; mt++) {
                uint32_t ra = sb + (uint32_t)((wm + mt * 16 + a_row) * 80 + (a_ko + kb) * 2);
                ldsm_x4(ra, ah[mt][0], ah[mt][1], ah[mt][2], ah[mt][3]);
            }
            uint32_t bh[4][2];
            #pragma unroll
            for (int np = 0; np < 2; np++) {
                uint32_t rb = sb + TILE_B +
                              (uint32_t)((wn + np * 16 + b_row) * 80 + (b_ko + kb) * 2);
                ldsm_x4(rb, bh[np * 2][0], bh[np * 2][1], bh[np * 2 + 1][0], bh[np * 2 + 1][1]);
            }
            #pragma unroll
            for (int mt = 0; mt < 4; mt++)
                #pragma unroll
                for (int nt = 0; nt < 4; nt++)
                    mma_f16(acc[mt][nt], ah[mt][0], ah[mt][1], ah[mt][2], ah[mt][3],
                            bh[nt][0], bh[nt][1]);
        }
    }

    const int er = lane >> 2, ec = (lane & 3) * 2;
    #pragma unroll
    for (int mt = 0; mt < 4; mt++) {
        #pragma unroll
        for (int nt = 0; nt < 4; nt++) {
            const int col = n0 + wn + nt * 8 + ec;
            const float b0 = bias[col], b1 = bias[col + 1];
            float* p0 = C + (size_t)(m0 + wm + mt * 16 + er) * CQ + col;
            float* p1 = p0 + 8 * CQ;
            float2 v0 = { acc[mt][nt][0] + b0, acc[mt][nt][1] + b1 };
            float2 v1 = { acc[mt][nt][2] + b0, acc[mt][nt][3] + b1 };
            *(float2*)p0 = v0;
            *(float2*)p1 = v1;
        }
    }
}

// ---------------------------------------------------------------------------
// fp32 SGEMM, 64x64 tile (small Q / O projections)
// ---------------------------------------------------------------------------
__global__ __launch_bounds__(256) void sgemm_bias64(
    const float* __restrict__ A, const float* __restrict__ Bm,
    const float* __restrict__ bias, float* __restrict__ C,
    int M, int N, int K)
{
    __shared__ float As[16][68];
    __shared__ float Bs[16][64];
    const int brow = blockIdx.y * 64;
    const int bcol = blockIdx.x * 64;
    const int tid  = threadIdx.x;
    const int a_row = tid >> 2, a_col = (tid & 3) << 2;
    const int b_row = tid >> 4, b_col = (tid & 15) << 2;
    const int tx = tid & 15, ty = tid >> 4;

    float acc[4][4];
    #pragma unroll
    for (int i = 0; i < 4; i++)
        #pragma unroll
        for (int j = 0; j < 4; j++) acc[i][j] = 0.f;

    for (int k0 = 0; k0 < K; k0 += 16) {
        float4 av = *(const float4*)(A + (size_t)(brow + a_row) * K + k0 + a_col);
        float4 bv = *(const float4*)(Bm + (size_t)(k0 + b_row) * N + bcol + b_col);
        As[a_col + 0][a_row] = av.x; As[a_col + 1][a_row] = av.y;
        As[a_col + 2][a_row] = av.z; As[a_col + 3][a_row] = av.w;
        *(float4*)&Bs[b_row][b_col] = bv;
        __syncthreads();
        #pragma unroll
        for (int k = 0; k < 16; k++) {
            float a[4], b[4];
            *(float4*)&a[0] = *(const float4*)&As[k][ty * 4];
            *(float4*)&b[0] = *(const float4*)&Bs[k][tx * 4];
            #pragma unroll
            for (int i = 0; i < 4; i++)
                #pragma unroll
                for (int j = 0; j < 4; j++)
                    acc[i][j] = fmaf(a[i], b[j], acc[i][j]);
        }
        __syncthreads();
    }
    float bb[4];
    #pragma unroll
    for (int j = 0; j < 4; j++) bb[j] = bias[bcol + tx * 4 + j];
    #pragma unroll
    for (int i = 0; i < 4; i++) {
        float* Cp = C + (size_t)(brow + ty * 4 + i) * N + bcol + tx * 4;
        float4 o;
        o.x = acc[i][0] + bb[0]; o.y = acc[i][1] + bb[1];
        o.z = acc[i][2] + bb[2]; o.w = acc[i][3] + bb[3];
        *(float4*)Cp = o;
    }
}

// ---------------------------------------------------------------------------
// split-KV flash attention partial: one CTA per (b, h, split)
// Q transposed [d][r]; K, V, P natural [r][d]; row stride 68 (16B aligned)
// -> all inner-loop accesses are LDS.128 / STS.128.
// ---------------------------------------------------------------------------
#define APAD 68
#define ATT_SMEM (4 * 64 * APAD * 4)   // 69632
#define KV_PER_SPLIT (NKV / SPLIT)

__global__ __launch_bounds__(256) void attention_partial(
    const float* __restrict__ Qg, const float* __restrict__ Kg,
    const float* __restrict__ Vg,
    float* __restrict__ accP, float* __restrict__ mP, float* __restrict__ lP)
{
    extern __shared__ float sm[];
    float (*Qt)[APAD] = (float(*)[APAD])(sm);
    float (*Ks)[APAD] = (float(*)[APAD])(sm + 64 * APAD);
    float (*Vs)[APAD] = (float(*)[APAD])(sm + 2 * 64 * APAD);
    float (*Ps)[APAD] = (float(*)[APAD])(sm + 3 * 64 * APAD);

    const int bh = blockIdx.x / SPLIT;
    const int sp = blockIdx.x % SPLIT;
    const int b = bh / H_, h = bh % H_;
    const int tid = threadIdx.x;
    const int tx = tid & 15, ty = tid >> 4;

    // Q transposed (one-time; write conflicts tolerable)
    for (int idx = tid; idx < 64 * 64; idx += 256) {
        int rr = idx >> 6, dd = idx & 63;
        Qt[dd][rr] = Qg[(size_t)(b * NQ + rr) * CQ + h * D_ + dd] * 0.125f;
    }

    float acc[4][4], m[4], l[4];
    #pragma unroll
    for (int i = 0; i < 4; i++) {
        m[i] = -1e30f; l[i] = 0.f;
        #pragma unroll
        for (int j = 0; j < 4; j++) acc[i][j] = 0.f;
    }

    const int kv_base = sp * KV_PER_SPLIT;
    for (int kv0 = kv_base; kv0 < kv_base + KV_PER_SPLIT; kv0 += 64) {
        __syncthreads();
        // K, V natural layout, float4 both sides (coalesced + conflict-free)
        for (int idx = tid; idx < 64 * 16; idx += 256) {
            int rr = idx >> 4, d4 = (idx & 15) * 4;
            const float* kb = Kg + (size_t)(b * NKV + kv0 + rr) * CQ + h * D_ + d4;
            const float* vb = Vg + (size_t)(b * NKV + kv0 + rr) * CQ + h * D_ + d4;
            *(float4*)&Ks[rr][d4] = *(const float4*)kb;
            *(float4*)&Vs[rr][d4] = *(const float4*)vb;
        }
        __syncthreads();

        // S = Q K^T (4x4 per thread), d in chunks of 4 via LDS.128
        float s[4][4];
        #pragma unroll
        for (int i = 0; i < 4; i++)
            #pragma unroll
            for (int j = 0; j < 4; j++) s[i][j] = 0.f;

        #pragma unroll 4
        for (int dc = 0; dc < 64; dc += 4) {
            float q[4][4], k[4][4];
            #pragma unroll
            for (int t = 0; t < 4; t++)
                *(float4*)q[t] = *(const float4*)&Qt[dc + t][ty * 4];
            #pragma unroll
            for (int j = 0; j < 4; j++)
                *(float4*)k[j] = *(const float4*)&Ks[tx * 4 + j][dc];
            #pragma unroll
            for (int i = 0; i < 4; i++)
                #pragma unroll
                for (int j = 0; j < 4; j++) {
                    s[i][j] = fmaf(q[0][i], k[j][0], s[i][j]);
                    s[i][j] = fmaf(q[1][i], k[j][1], s[i][j]);
                    s[i][j] = fmaf(q[2][i], k[j][2], s[i][j]);
                    s[i][j] = fmaf(q[3][i], k[j][3], s[i][j]);
                }
        }

        // online softmax per row (16 tx lanes share a row group)
        #pragma unroll
        for (int ii = 0; ii < 4; ii++) {
            float mx = fmaxf(fmaxf(s[ii][0], s[ii][1]), fmaxf(s[ii][2], s[ii][3]));
            #pragma unroll
            for (int o = 1; o < 16; o <<= 1)
                mx = fmaxf(mx, __shfl_xor_sync(0xffffffffu, mx, o));
            float mnew = fmaxf(m[ii], mx);
            float corr = __expf(m[ii] - mnew);
            float ls = 0.f;
            #pragma unroll
            for (int jj = 0; jj < 4; jj++) {
                float p = __expf(s[ii][jj] - mnew);
                s[ii][jj] = p; ls += p;
            }
            #pragma unroll
            for (int o = 1; o < 16; o <<= 1)
                ls += __shfl_xor_sync(0xffffffffu, ls, o);
            l[ii] = l[ii] * corr + ls;
            m[ii] = mnew;
            #pragma unroll
            for (int jj = 0; jj < 4; jj++) acc[ii][jj] *= corr;
            // P natural, STS.128 conflict-free
            float4 pv = { s[ii][0], s[ii][1], s[ii][2], s[ii][3] };
            *(float4*)&Ps[ty * 4 + ii][tx * 4] = pv;
        }
        __syncwarp();   // Ps producer/consumer share ty -> same warp

        // O += P V, j in chunks of 4 via LDS.128
        #pragma unroll 4
        for (int jc = 0; jc < 64; jc += 4) {
            float p[4][4], v[4][4];
            #pragma unroll
            for (int i = 0; i < 4; i++)
                *(float4*)p[i] = *(const float4*)&Ps[ty * 4 + i][jc];
            #pragma unroll
            for (int t = 0; t < 4; t++)
                *(float4*)v[t] = *(const float4*)&Vs[jc + t][tx * 4];
            #pragma unroll
            for (int i = 0; i < 4; i++)
                #pragma unroll
                for (int c = 0; c < 4; c++) {
                    acc[i][c] = fmaf(p[i][0], v[0][c], acc[i][c]);
                    acc[i][c] = fmaf(p[i][1], v[1][c], acc[i][c]);
                    acc[i][c] = fmaf(p[i][2], v[2][c], acc[i][c]);
                    acc[i][c] = fmaf(p[i][3], v[3][c], acc[i][c]);
                }
        }
    }

    float* accp = accP + (size_t)blockIdx.x * 64 * 64;
    #pragma unroll
    for (int ii = 0; ii < 4; ii++) {
        int r = ty * 4 + ii;
        float4 o = { acc[ii][0], acc[ii][1], acc[ii][2], acc[ii][3] };
        *(float4*)&accp[r * 64 + tx * 4] = o;
        if (tx == 0) {
            mP[(size_t)blockIdx.x * 64 + r] = m[ii];
            lP[(size_t)blockIdx.x * 64 + r] = l[ii];
        }
    }
}

__global__ __launch_bounds__(256) void attention_combine(
    const float* __restrict__ accP, const float* __restrict__ mP,
    const float* __restrict__ lP, float* __restrict__ Xg)
{
    __shared__ float sw[SPLIT][64];
    __shared__ float sden[64];
    const int bh = blockIdx.x;
    const int b = bh / H_, h = bh % H_;
    const int tid = threadIdx.x;

    if (tid < 64) {
        int r = tid;
        float M = -1e30f;
        #pragma unroll
        for (int s = 0; s < SPLIT; s++)
            M = fmaxf(M, mP[(size_t)(bh * SPLIT + s) * 64 + r]);
        float den = 0.f;
        #pragma unroll
        for (int s = 0; s < SPLIT; s++) {
            float w = __expf(mP[(size_t)(bh * SPLIT + s) * 64 + r] - M);
            sw[s][r] = w;
            den += w * lP[(size_t)(bh * SPLIT + s) * 64 + r];
        }
        sden[r] = den;
    }
    __syncthreads();

    for (int idx = tid; idx < 64 * 64; idx += 256) {
        int r = idx >> 6, d = idx & 63;
        float num = 0.f;
        #pragma unroll
        for (int s = 0; s < SPLIT; s++)
            num += sw[s][r] * accP[(size_t)(bh * SPLIT + s) * 4096 + idx];
        Xg[(size_t)(b * NQ + r) * CQ + h * D_ + d] = num / sden[r];
    }
}

// ---------------------------------------------------------------------------
extern "C" void kernel_launch(void* const* d_in, const int* in_sizes, int n_in,
                              void* d_out, int out_size)
{
    const float* query = (const float*)d_in[0];
    const float* kv    = (const float*)d_in[1];
    const float* Wq    = (const float*)d_in[2];
    const float* bq    = (const float*)d_in[3];
    const float* Wk    = (const float*)d_in[4];
    const float* bk    = (const float*)d_in[5];
    const float* Wv    = (const float*)d_in[6];
    const float* bv    = (const float*)d_in[7];
    const float* Wo    = (const float*)d_in[8];
    const float* bo    = (const float*)d_in[9];
    float* out = (float*)d_out;

    float *qp, *kp, *vp, *xp, *accp, *mp, *lp;
    __half *kva, *wkt, *wvt;
    cudaGetSymbolAddress((void**)&qp, g_q);
    cudaGetSymbolAddress((void**)&kp, g_k);
    cudaGetSymbolAddress((void**)&vp, g_v);
    cudaGetSymbolAddress((void**)&xp, g_x);
    cudaGetSymbolAddress((void**)&kva, g_kva);
    cudaGetSymbolAddress((void**)&wkt, g_wkt);
    cudaGetSymbolAddress((void**)&wvt, g_wvt);
    cudaGetSymbolAddress((void**)&accp, g_accP);
    cudaGetSymbolAddress((void**)&mp, g_mP);
    cudaGetSymbolAddress((void**)&lp, g_lP);

    cudaFuncSetAttribute(attention_partial,
                         cudaFuncAttributeMaxDynamicSharedMemorySize, ATT_SMEM);
    cudaFuncSetAttribute(hgemm_f16,
                         cudaFuncAttributeMaxDynamicSharedMemorySize, HGEMM_SMEM);

    // 1. prep: round kv to fp16; transpose weights to fp16
    round_kernel<<<2048, 256>>>(kv, kva, (size_t)B_ * NKV * CKV / 4);
    transpose_f16_kernel<<<dim3(CKV / 256, CQ), 256>>>(Wk, wkt);
    transpose_f16_kernel<<<dim3(CKV / 256, CQ), 256>>>(Wv, wvt);

    // 2. q projection (fp32)
    sgemm_bias64<<<dim3(CQ / 64, (B_ * NQ) / 64), 256>>>(
        query, Wq, bq, qp, B_ * NQ, CQ, CQ);

    // 3. K / V projections on HMMA tensor cores (fp16, single pass)
    dim3 ggrid(CQ / 128, (B_ * NKV) / 128);   // (6, 512)
    hgemm_f16<<<ggrid, 256, HGEMM_SMEM>>>(kva, wkt, bk, kp);
    hgemm_f16<<<ggrid, 256, HGEMM_SMEM>>>(kva, wvt, bv, vp);

    // 4. split-KV attention + combine
    attention_partial<<<B_ * H_ * SPLIT, 256, ATT_SMEM>>>(qp, kp, vp, accp, mp, lp);
    attention_combine<<<B_ * H_, 256>>>(accp, mp, lp, xp);

    // 5. output projection
    sgemm_bias64<<<dim3(CQ / 64, (B_ * NQ) / 64), 256>>>(
        xp, Wo, bo, out, B_ * NQ, CQ, CQ);
}

// round 7
// speedup vs baseline: 5.1896x; 1.4038x over previous
#include <cuda_runtime.h>
#include <cuda_bf16.h>
#include <cuda_fp16.h>
#include <math.h>
#include <stdint.h>

#define B_   16
#define NQ   64
#define NKV  4096
#define CQ   768
#define CKV  1024
#define H_   12
#define D_   64
#define SPLIT 8

// ---------------- scratch (device globals; allocation-free) ----------------
__device__ float g_q[(size_t)B_ * NQ * CQ];
__device__ __half g_kh[(size_t)B_ * NKV * CQ];
__device__ __half g_vh[(size_t)B_ * NKV * CQ];
__device__ float g_x[(size_t)B_ * NQ * CQ];
__device__ __half g_kva[(size_t)B_ * NKV * CKV];
__device__ __half g_wkt[(size_t)CQ * CKV];
__device__ __half g_wvt[(size_t)CQ * CKV];
__device__ float g_accP[(size_t)B_ * H_ * SPLIT * NQ * D_];
__device__ float g_mP[(size_t)B_ * H_ * SPLIT * NQ];
__device__ float g_lP[(size_t)B_ * H_ * SPLIT * NQ];

// ---------------- helpers ----------------
__device__ __forceinline__ uint32_t smem_u32(const void* p) {
    uint32_t a;
    asm("{ .reg .u64 t; cvta.to.shared.u64 t, %1; cvt.u32.u64 %0, t; }"
        : "=r"(a) : "l"(p));
    return a;
}
__device__ __forceinline__ void cp16(uint32_t s, const void* g) {
    asm volatile("cp.async.cg.shared.global [%0], [%1], 16;\n"
                 :: "r"(s), "l"(__cvta_generic_to_global(g)) : "memory");
}
#define CP_COMMIT() asm volatile("cp.async.commit_group;\n" ::: "memory")
#define CP_WAIT(n)  asm volatile("cp.async.wait_group %0;\n" :: "n"(n) : "memory")

__device__ __forceinline__ void ldsm_x4(uint32_t addr, uint32_t& r0, uint32_t& r1,
                                        uint32_t& r2, uint32_t& r3) {
    asm volatile("ldmatrix.sync.aligned.m8n8.x4.shared.b16 {%0,%1,%2,%3}, [%4];"
                 : "=r"(r0), "=r"(r1), "=r"(r2), "=r"(r3) : "r"(addr));
}
__device__ __forceinline__ void ldsm_x4_t(uint32_t addr, uint32_t& r0, uint32_t& r1,
                                          uint32_t& r2, uint32_t& r3) {
    asm volatile("ldmatrix.sync.aligned.m8n8.x4.trans.shared.b16 {%0,%1,%2,%3}, [%4];"
                 : "=r"(r0), "=r"(r1), "=r"(r2), "=r"(r3) : "r"(addr));
}
__device__ __forceinline__ void mma_f16(float* d, uint32_t a0, uint32_t a1,
                                        uint32_t a2, uint32_t a3,
                                        uint32_t b0, uint32_t b1) {
    asm volatile(
        "mma.sync.aligned.m16n8k16.row.col.f32.f16.f16.f32 "
        "{%0,%1,%2,%3}, {%4,%5,%6,%7}, {%8,%9}, {%0,%1,%2,%3};"
        : "+f"(d[0]), "+f"(d[1]), "+f"(d[2]), "+f"(d[3])
        : "r"(a0), "r"(a1), "r"(a2), "r"(a3), "r"(b0), "r"(b1));
}
__device__ __forceinline__ uint32_t pack_h2(float a, float b) {
    __half2 h = __floats2half2_rn(a, b);
    return *(uint32_t*)&h;
}

// ---------------------------------------------------------------------------
// prep kernels
// ---------------------------------------------------------------------------
__global__ __launch_bounds__(256) void round_kernel(
    const float* __restrict__ src, __half* __restrict__ dst, size_t n4)
{
    size_t i = (size_t)blockIdx.x * blockDim.x + threadIdx.x;
    size_t stride = (size_t)gridDim.x * blockDim.x;
    for (; i < n4; i += stride) {
        float4 x = ((const float4*)src)[i];
        ((__half2*)dst)[i * 2]     = __floats2half2_rn(x.x, x.y);
        ((__half2*)dst)[i * 2 + 1] = __floats2half2_rn(x.z, x.w);
    }
}

__global__ __launch_bounds__(256) void transpose_f16_kernel(
    const float* __restrict__ W, __half* __restrict__ th)
{
    int n = blockIdx.y;
    int k = blockIdx.x * 256 + threadIdx.x;
    th[(size_t)n * CKV + k] = __float2half_rn(W[(size_t)k * CQ + n]);
}

// ---------------------------------------------------------------------------
// HMMA fp16 GEMM: C16[M=65536, N=768] = A16 B16^T + bias  (fp16 output)
// ---------------------------------------------------------------------------
#define LDS_E 40
#define TILE_B (128 * LDS_E * 2)
#define STAGE_B (2 * TILE_B)
#define STAGES 3
#define HGEMM_SMEM (STAGES * STAGE_B)
#define KT_N (CKV / 32)

__global__ __launch_bounds__(256, 1) void hgemm_f16(
    const __half* __restrict__ A_g, const __half* __restrict__ B_g,
    const float* __restrict__ bias, __half* __restrict__ C)
{
    extern __shared__ char smem[];
    const uint32_t sbase = smem_u32(smem);
    const int tid = threadIdx.x;
    const int wid = tid >> 5, lane = tid & 31;
    const int wm = (wid & 1) * 64;
    const int wn = (wid >> 1) * 32;
    const int m0 = blockIdx.y * 128, n0 = blockIdx.x * 128;

    const int lr = tid >> 1;
    const int lc = (tid & 1) * 16;
    const uint32_t s_off = (uint32_t)(lr * 80 + (tid & 1) * 32);

    const __half* gA = A_g + (size_t)(m0 + lr) * CKV + lc;
    const __half* gB = B_g + (size_t)(n0 + lr) * CKV + lc;

    const int a_row = lane & 15;
    const int a_ko  = ((lane >> 4) & 1) * 8;
    const int b_row = (lane & 7) + ((lane >> 4) & 1) * 8;
    const int b_ko  = ((lane >> 3) & 1) * 8;

    float acc[4][4][4];
    #pragma unroll
    for (int i = 0; i < 4; i++)
        #pragma unroll
        for (int j = 0; j < 4; j++)
            #pragma unroll
            for (int c = 0; c < 4; c++) acc[i][j][c] = 0.f;

    auto load_stage = [&](int kt, int s) {
        const uint32_t sb = sbase + s * STAGE_B;
        const int ke = kt * 32;
        cp16(sb + s_off,               gA + ke);
        cp16(sb + s_off + 16,          gA + ke + 8);
        cp16(sb + TILE_B + s_off,      gB + ke);
        cp16(sb + TILE_B + s_off + 16, gB + ke + 8);
    };

    load_stage(0, 0); CP_COMMIT();
    load_stage(1, 1); CP_COMMIT();

    for (int kt = 0; kt < KT_N; kt++) {
        CP_WAIT(1);
        __syncthreads();

        const int nkt = kt + STAGES - 1;
        if (nkt < KT_N) load_stage(nkt, nkt % STAGES);
        CP_COMMIT();

        const uint32_t sb = sbase + (kt % STAGES) * STAGE_B;
        #pragma unroll
        for (int kb = 0; kb < 32; kb += 16) {
            uint32_t ah[4][4];
            #pragma unroll
            for (int mt = 0; mt < 4; mt++) {
                uint32_t ra = sb + (uint32_t)((wm + mt * 16 + a_row) * 80 + (a_ko + kb) * 2);
                ldsm_x4(ra, ah[mt][0], ah[mt][1], ah[mt][2], ah[mt][3]);
            }
            uint32_t bh[4][2];
            #pragma unroll
            for (int np = 0; np < 2; np++) {
                uint32_t rb = sb + TILE_B +
                              (uint32_t)((wn + np * 16 + b_row) * 80 + (b_ko + kb) * 2);
                ldsm_x4(rb, bh[np * 2][0], bh[np * 2][1], bh[np * 2 + 1][0], bh[np * 2 + 1][1]);
            }
            #pragma unroll
            for (int mt = 0; mt < 4; mt++)
                #pragma unroll
                for (int nt = 0; nt < 4; nt++)
                    mma_f16(acc[mt][nt], ah[mt][0], ah[mt][1], ah[mt][2], ah[mt][3],
                            bh[nt][0], bh[nt][1]);
        }
    }

    const int er = lane >> 2, ec = (lane & 3) * 2;
    #pragma unroll
    for (int mt = 0; mt < 4; mt++) {
        #pragma unroll
        for (int nt = 0; nt < 4; nt++) {
            const int col = n0 + wn + nt * 8 + ec;
            const float b0 = bias[col], b1 = bias[col + 1];
            __half* p0 = C + (size_t)(m0 + wm + mt * 16 + er) * CQ + col;
            __half* p1 = p0 + 8 * CQ;
            *(uint32_t*)p0 = pack_h2(acc[mt][nt][0] + b0, acc[mt][nt][1] + b1);
            *(uint32_t*)p1 = pack_h2(acc[mt][nt][2] + b0, acc[mt][nt][3] + b1);
        }
    }
}

// ---------------------------------------------------------------------------
// fp32 SGEMM, 64x64 tile (Q / O projections)
// ---------------------------------------------------------------------------
__global__ __launch_bounds__(256) void sgemm_bias64(
    const float* __restrict__ A, const float* __restrict__ Bm,
    const float* __restrict__ bias, float* __restrict__ C,
    int M, int N, int K)
{
    __shared__ float As[16][68];
    __shared__ float Bs[16][64];
    const int brow = blockIdx.y * 64;
    const int bcol = blockIdx.x * 64;
    const int tid  = threadIdx.x;
    const int a_row = tid >> 2, a_col = (tid & 3) << 2;
    const int b_row = tid >> 4, b_col = (tid & 15) << 2;
    const int tx = tid & 15, ty = tid >> 4;

    float acc[4][4];
    #pragma unroll
    for (int i = 0; i < 4; i++)
        #pragma unroll
        for (int j = 0; j < 4; j++) acc[i][j] = 0.f;

    for (int k0 = 0; k0 < K; k0 += 16) {
        float4 av = *(const float4*)(A + (size_t)(brow + a_row) * K + k0 + a_col);
        float4 bv = *(const float4*)(Bm + (size_t)(k0 + b_row) * N + bcol + b_col);
        As[a_col + 0][a_row] = av.x; As[a_col + 1][a_row] = av.y;
        As[a_col + 2][a_row] = av.z; As[a_col + 3][a_row] = av.w;
        *(float4*)&Bs[b_row][b_col] = bv;
        __syncthreads();
        #pragma unroll
        for (int k = 0; k < 16; k++) {
            float a[4], b[4];
            *(float4*)&a[0] = *(const float4*)&As[k][ty * 4];
            *(float4*)&b[0] = *(const float4*)&Bs[k][tx * 4];
            #pragma unroll
            for (int i = 0; i < 4; i++)
                #pragma unroll
                for (int j = 0; j < 4; j++)
                    acc[i][j] = fmaf(a[i], b[j], acc[i][j]);
        }
        __syncthreads();
    }
    float bb[4];
    #pragma unroll
    for (int j = 0; j < 4; j++) bb[j] = bias[bcol + tx * 4 + j];
    #pragma unroll
    for (int i = 0; i < 4; i++) {
        float* Cp = C + (size_t)(brow + ty * 4 + i) * N + bcol + tx * 4;
        float4 o;
        o.x = acc[i][0] + bb[0]; o.y = acc[i][1] + bb[1];
        o.z = acc[i][2] + bb[2]; o.w = acc[i][3] + bb[3];
        *(float4*)Cp = o;
    }
}

// ---------------------------------------------------------------------------
// HMMA split-KV flash attention partial: one CTA per (b, h, split),
// 128 threads = 4 warps, warp w owns q rows [16w, 16w+16).
// S = Q K^T on mma.m16n8k16, P·V on mma with V via ldmatrix.trans.
// ---------------------------------------------------------------------------
#define KV_PER_SPLIT (NKV / SPLIT)   // 512

__global__ __launch_bounds__(128) void attention_hmma(
    const float* __restrict__ Qg, const __half* __restrict__ Kg,
    const __half* __restrict__ Vg,
    float* __restrict__ accP, float* __restrict__ mP, float* __restrict__ lP)
{
    __shared__ __half Qs[64][72];
    __shared__ __half Ks[64][72];
    __shared__ __half Vs[64][72];

    const int bh = blockIdx.x / SPLIT;
    const int sp = blockIdx.x % SPLIT;
    const int b = bh / H_, h = bh % H_;
    const int tid = threadIdx.x;
    const int w = tid >> 5, lane = tid & 31;

    // Q fp32 -> fp16 scaled (one-time)
    for (int idx = tid; idx < 64 * 16; idx += 128) {
        int r = idx >> 4, c4 = (idx & 15) * 4;
        float4 q = *(const float4*)(Qg + (size_t)(b * NQ + r) * CQ + h * D_ + c4);
        *(__half2*)&Qs[r][c4]     = __floats2half2_rn(q.x * 0.125f, q.y * 0.125f);
        *(__half2*)&Qs[r][c4 + 2] = __floats2half2_rn(q.z * 0.125f, q.w * 0.125f);
    }

    // ldmatrix lane addressing
    const int qa_row = lane & 15;
    const int qa_ko  = ((lane >> 4) & 1) * 8;
    const int kb_row = (lane & 7) + ((lane >> 4) & 1) * 8;
    const int kb_ko  = ((lane >> 3) & 1) * 8;
    const int vt_row = (lane & 7) + ((lane >> 3) & 1) * 8;
    const int vt_co  = ((lane >> 4) & 1) * 8;

    float m0 = -1e30f, m1 = -1e30f, l0 = 0.f, l1 = 0.f;
    float o[8][4];
    #pragma unroll
    for (int i = 0; i < 8; i++)
        #pragma unroll
        for (int j = 0; j < 4; j++) o[i][j] = 0.f;

    const int kv_lo = sp * KV_PER_SPLIT;
    for (int kv0 = kv_lo; kv0 < kv_lo + KV_PER_SPLIT; kv0 += 64) {
        __syncthreads();   // protect Ks/Vs reuse (and first-iter Q store)
        for (int idx = tid; idx < 512; idx += 128) {
            int r = idx >> 3, sg = idx & 7;
            size_t gofs = (size_t)(b * NKV + kv0 + r) * CQ + h * D_ + sg * 8;
            cp16(smem_u32(&Ks[r][sg * 8]), Kg + gofs);
            cp16(smem_u32(&Vs[r][sg * 8]), Vg + gofs);
        }
        CP_COMMIT(); CP_WAIT(0);
        __syncthreads();

        // ---- S = Q K^T : 8 n-tiles x fp32 acc
        float s[8][4];
        #pragma unroll
        for (int i = 0; i < 8; i++)
            #pragma unroll
            for (int j = 0; j < 4; j++) s[i][j] = 0.f;

        #pragma unroll
        for (int kk = 0; kk < 4; kk++) {
            uint32_t a0, a1, a2, a3;
            ldsm_x4(smem_u32(&Qs[w * 16 + qa_row][kk * 16 + qa_ko]), a0, a1, a2, a3);
            #pragma unroll
            for (int ng = 0; ng < 4; ng++) {
                uint32_t b0, b1, b2, b3;
                ldsm_x4(smem_u32(&Ks[ng * 16 + kb_row][kk * 16 + kb_ko]), b0, b1, b2, b3);
                mma_f16(s[2 * ng],     a0, a1, a2, a3, b0, b1);
                mma_f16(s[2 * ng + 1], a0, a1, a2, a3, b2, b3);
            }
        }

        // ---- online softmax (rows r0 = lane>>2, r1 = r0+8 of warp tile)
        float mx0 = -1e30f, mx1 = -1e30f;
        #pragma unroll
        for (int nt = 0; nt < 8; nt++) {
            mx0 = fmaxf(mx0, fmaxf(s[nt][0], s[nt][1]));
            mx1 = fmaxf(mx1, fmaxf(s[nt][2], s[nt][3]));
        }
        #pragma unroll
        for (int ofs = 1; ofs < 4; ofs <<= 1) {
            mx0 = fmaxf(mx0, __shfl_xor_sync(0xffffffffu, mx0, ofs));
            mx1 = fmaxf(mx1, __shfl_xor_sync(0xffffffffu, mx1, ofs));
        }
        float M0 = fmaxf(m0, mx0), M1 = fmaxf(m1, mx1);
        float c0 = __expf(m0 - M0), c1 = __expf(m1 - M1);
        float ls0 = 0.f, ls1 = 0.f;
        #pragma unroll
        for (int nt = 0; nt < 8; nt++) {
            s[nt][0] = __expf(s[nt][0] - M0); ls0 += s[nt][0];
            s[nt][1] = __expf(s[nt][1] - M0); ls0 += s[nt][1];
            s[nt][2] = __expf(s[nt][2] - M1); ls1 += s[nt][2];
            s[nt][3] = __expf(s[nt][3] - M1); ls1 += s[nt][3];
        }
        #pragma unroll
        for (int ofs = 1; ofs < 4; ofs <<= 1) {
            ls0 += __shfl_xor_sync(0xffffffffu, ls0, ofs);
            ls1 += __shfl_xor_sync(0xffffffffu, ls1, ofs);
        }
        l0 = l0 * c0 + ls0;  l1 = l1 * c1 + ls1;
        m0 = M0;  m1 = M1;
        #pragma unroll
        for (int nt = 0; nt < 8; nt++) {
            o[nt][0] *= c0; o[nt][1] *= c0;
            o[nt][2] *= c1; o[nt][3] *= c1;
        }

        // ---- P -> fp16 A-fragments
        uint32_t pu[8][2];
        #pragma unroll
        for (int nt = 0; nt < 8; nt++) {
            pu[nt][0] = pack_h2(s[nt][0], s[nt][1]);   // row r0
            pu[nt][1] = pack_h2(s[nt][2], s[nt][3]);   // row r1
        }

        // ---- O += P V  (V^T fragments via ldmatrix.trans)
        #pragma unroll
        for (int t = 0; t < 4; t++) {
            uint32_t a0 = pu[2 * t][0],     a1 = pu[2 * t][1];
            uint32_t a2 = pu[2 * t + 1][0], a3 = pu[2 * t + 1][1];
            #pragma unroll
            for (int dg = 0; dg < 4; dg++) {
                uint32_t b0, b1, b2, b3;
                ldsm_x4_t(smem_u32(&Vs[t * 16 + vt_row][dg * 16 + vt_co]), b0, b1, b2, b3);
                mma_f16(o[2 * dg],     a0, a1, a2, a3, b0, b1);
                mma_f16(o[2 * dg + 1], a0, a1, a2, a3, b2, b3);
            }
        }
    }

    // ---- write unnormalized partials
    float* accp = accP + (size_t)blockIdx.x * 64 * 64;
    const int r0 = w * 16 + (lane >> 2), r1 = r0 + 8;
    const int cb = (lane & 3) * 2;
    #pragma unroll
    for (int nt = 0; nt < 8; nt++) {
        float2 v0 = { o[nt][0], o[nt][1] };
        float2 v1 = { o[nt][2], o[nt][3] };
        *(float2*)&accp[r0 * 64 + nt * 8 + cb] = v0;
        *(float2*)&accp[r1 * 64 + nt * 8 + cb] = v1;
    }
    if ((lane & 3) == 0) {
        mP[(size_t)blockIdx.x * 64 + r0] = m0;
        lP[(size_t)blockIdx.x * 64 + r0] = l0;
        mP[(size_t)blockIdx.x * 64 + r1] = m1;
        lP[(size_t)blockIdx.x * 64 + r1] = l1;
    }
}

__global__ __launch_bounds__(256) void attention_combine(
    const float* __restrict__ accP, const float* __restrict__ mP,
    const float* __restrict__ lP, float* __restrict__ Xg)
{
    __shared__ float sw[SPLIT][64];
    __shared__ float sden[64];
    const int bh = blockIdx.x;
    const int b = bh / H_, h = bh % H_;
    const int tid = threadIdx.x;

    if (tid < 64) {
        int r = tid;
        float M = -1e30f;
        #pragma unroll
        for (int s = 0; s < SPLIT; s++)
            M = fmaxf(M, mP[(size_t)(bh * SPLIT + s) * 64 + r]);
        float den = 0.f;
        #pragma unroll
        for (int s = 0; s < SPLIT; s++) {
            float w = __expf(mP[(size_t)(bh * SPLIT + s) * 64 + r] - M);
            sw[s][r] = w;
            den += w * lP[(size_t)(bh * SPLIT + s) * 64 + r];
        }
        sden[r] = den;
    }
    __syncthreads();

    for (int idx = tid; idx < 64 * 64; idx += 256) {
        int r = idx >> 6, d = idx & 63;
        float num = 0.f;
        #pragma unroll
        for (int s = 0; s < SPLIT; s++)
            num += sw[s][r] * accP[(size_t)(bh * SPLIT + s) * 4096 + idx];
        Xg[(size_t)(b * NQ + r) * CQ + h * D_ + d] = num / sden[r];
    }
}

// ---------------------------------------------------------------------------
extern "C" void kernel_launch(void* const* d_in, const int* in_sizes, int n_in,
                              void* d_out, int out_size)
{
    const float* query = (const float*)d_in[0];
    const float* kv    = (const float*)d_in[1];
    const float* Wq    = (const float*)d_in[2];
    const float* bq    = (const float*)d_in[3];
    const float* Wk    = (const float*)d_in[4];
    const float* bk    = (const float*)d_in[5];
    const float* Wv    = (const float*)d_in[6];
    const float* bv    = (const float*)d_in[7];
    const float* Wo    = (const float*)d_in[8];
    const float* bo    = (const float*)d_in[9];
    float* out = (float*)d_out;

    float *qp, *xp, *accp, *mp, *lp;
    __half *kp, *vp, *kva, *wkt, *wvt;
    cudaGetSymbolAddress((void**)&qp, g_q);
    cudaGetSymbolAddress((void**)&kp, g_kh);
    cudaGetSymbolAddress((void**)&vp, g_vh);
    cudaGetSymbolAddress((void**)&xp, g_x);
    cudaGetSymbolAddress((void**)&kva, g_kva);
    cudaGetSymbolAddress((void**)&wkt, g_wkt);
    cudaGetSymbolAddress((void**)&wvt, g_wvt);
    cudaGetSymbolAddress((void**)&accp, g_accP);
    cudaGetSymbolAddress((void**)&mp, g_mP);
    cudaGetSymbolAddress((void**)&lp, g_lP);

    cudaFuncSetAttribute(hgemm_f16,
                         cudaFuncAttributeMaxDynamicSharedMemorySize, HGEMM_SMEM);

    // 1. prep: round kv to fp16; transpose weights to fp16
    round_kernel<<<2048, 256>>>(kv, kva, (size_t)B_ * NKV * CKV / 4);
    transpose_f16_kernel<<<dim3(CKV / 256, CQ), 256>>>(Wk, wkt);
    transpose_f16_kernel<<<dim3(CKV / 256, CQ), 256>>>(Wv, wvt);

    // 2. q projection (fp32)
    sgemm_bias64<<<dim3(CQ / 64, (B_ * NQ) / 64), 256>>>(
        query, Wq, bq, qp, B_ * NQ, CQ, CQ);

    // 3. K / V projections on HMMA tensor cores (fp16, fp16 output)
    dim3 ggrid(CQ / 128, (B_ * NKV) / 128);
    hgemm_f16<<<ggrid, 256, HGEMM_SMEM>>>(kva, wkt, bk, kp);
    hgemm_f16<<<ggrid, 256, HGEMM_SMEM>>>(kva, wvt, bv, vp);

    // 4. HMMA split-KV attention + combine
    attention_hmma<<<B_ * H_ * SPLIT, 128>>>(qp, kp, vp, accp, mp, lp);
    attention_combine<<<B_ * H_, 256>>>(accp, mp, lp, xp);

    // 5. output projection (fp32)
    sgemm_bias64<<<dim3(CQ / 64, (B_ * NQ) / 64), 256>>>(
        xp, Wo, bo, out, B_ * NQ, CQ, CQ);
}

// round 8
// speedup vs baseline: 6.1055x; 1.1765x over previous
#include <cuda_runtime.h>
#include <cuda_bf16.h>
#include <cuda_fp16.h>
#include <math.h>
#include <stdint.h>

#define B_   16
#define NQ   64
#define NKV  4096
#define CQ   768
#define CKV  1024
#define H_   12
#define D_   64
#define SPLIT 8

// ---------------- scratch (device globals; allocation-free) ----------------
__device__ __half g_qa [(size_t)B_ * NQ * CQ];     // query rounded fp16
__device__ __half g_qh [(size_t)B_ * NQ * CQ];     // q projection (fp16)
__device__ __half g_xh [(size_t)B_ * NQ * CQ];     // attention out (fp16)
__device__ __half g_kh [(size_t)B_ * NKV * CQ];
__device__ __half g_vh [(size_t)B_ * NKV * CQ];
__device__ __half g_kva[(size_t)B_ * NKV * CKV];
__device__ __half g_wkt [(size_t)CQ * CKV];
__device__ __half g_wvt [(size_t)CQ * CKV];
__device__ __half g_wqth[(size_t)CQ * CQ];
__device__ __half g_wqtl[(size_t)CQ * CQ];
__device__ __half g_woth[(size_t)CQ * CQ];
__device__ __half g_wotl[(size_t)CQ * CQ];
__device__ float g_accP[(size_t)B_ * H_ * SPLIT * NQ * D_];
__device__ float g_mP[(size_t)B_ * H_ * SPLIT * NQ];
__device__ float g_lP[(size_t)B_ * H_ * SPLIT * NQ];

// ---------------- helpers ----------------
__device__ __forceinline__ uint32_t smem_u32(const void* p) {
    uint32_t a;
    asm("{ .reg .u64 t; cvta.to.shared.u64 t, %1; cvt.u32.u64 %0, t; }"
        : "=r"(a) : "l"(p));
    return a;
}
__device__ __forceinline__ void cp16(uint32_t s, const void* g) {
    asm volatile("cp.async.cg.shared.global [%0], [%1], 16;\n"
                 :: "r"(s), "l"(__cvta_generic_to_global(g)) : "memory");
}
#define CP_COMMIT() asm volatile("cp.async.commit_group;\n" ::: "memory")
#define CP_WAIT(n)  asm volatile("cp.async.wait_group %0;\n" :: "n"(n) : "memory")

__device__ __forceinline__ void ldsm_x4(uint32_t addr, uint32_t& r0, uint32_t& r1,
                                        uint32_t& r2, uint32_t& r3) {
    asm volatile("ldmatrix.sync.aligned.m8n8.x4.shared.b16 {%0,%1,%2,%3}, [%4];"
                 : "=r"(r0), "=r"(r1), "=r"(r2), "=r"(r3) : "r"(addr));
}
__device__ __forceinline__ void ldsm_x4_t(uint32_t addr, uint32_t& r0, uint32_t& r1,
                                          uint32_t& r2, uint32_t& r3) {
    asm volatile("ldmatrix.sync.aligned.m8n8.x4.trans.shared.b16 {%0,%1,%2,%3}, [%4];"
                 : "=r"(r0), "=r"(r1), "=r"(r2), "=r"(r3) : "r"(addr));
}
__device__ __forceinline__ void mma_f16(float* d, uint32_t a0, uint32_t a1,
                                        uint32_t a2, uint32_t a3,
                                        uint32_t b0, uint32_t b1) {
    asm volatile(
        "mma.sync.aligned.m16n8k16.row.col.f32.f16.f16.f32 "
        "{%0,%1,%2,%3}, {%4,%5,%6,%7}, {%8,%9}, {%0,%1,%2,%3};"
        : "+f"(d[0]), "+f"(d[1]), "+f"(d[2]), "+f"(d[3])
        : "r"(a0), "r"(a1), "r"(a2), "r"(a3), "r"(b0), "r"(b1));
}
__device__ __forceinline__ uint32_t pack_h2(float a, float b) {
    __half2 h = __floats2half2_rn(a, b);
    return *(uint32_t*)&h;
}
__device__ __forceinline__ void st2(float* p, float a, float b) {
    float2 v = { a, b }; *(float2*)p = v;
}
__device__ __forceinline__ void st2(__half* p, float a, float b) {
    *(uint32_t*)p = pack_h2(a, b);
}

// ---------------------------------------------------------------------------
// prep kernels
// ---------------------------------------------------------------------------
__global__ __launch_bounds__(256) void round_kernel(
    const float* __restrict__ src, __half* __restrict__ dst, size_t n4)
{
    size_t i = (size_t)blockIdx.x * blockDim.x + threadIdx.x;
    size_t stride = (size_t)gridDim.x * blockDim.x;
    for (; i < n4; i += stride) {
        float4 x = ((const float4*)src)[i];
        ((__half2*)dst)[i * 2]     = __floats2half2_rn(x.x, x.y);
        ((__half2*)dst)[i * 2 + 1] = __floats2half2_rn(x.z, x.w);
    }
}

// W [K=1024][N=768] -> Wt [N=768][K=1024] fp16 (single)
__global__ __launch_bounds__(256) void transpose_f16_kernel(
    const float* __restrict__ W, __half* __restrict__ th)
{
    int n = blockIdx.y;
    int k = blockIdx.x * 256 + threadIdx.x;
    th[(size_t)n * CKV + k] = __float2half_rn(W[(size_t)k * CQ + n]);
}

// W [768][768] -> Wt hi/lo [768][768]
__global__ __launch_bounds__(256) void transpose_split768(
    const float* __restrict__ W, __half* __restrict__ th, __half* __restrict__ tl)
{
    int n = blockIdx.y;
    int k = blockIdx.x * 256 + threadIdx.x;
    float x = W[(size_t)k * CQ + n];
    __half h = __float2half_rn(x);
    th[(size_t)n * CQ + k] = h;
    tl[(size_t)n * CQ + k] = __float2half_rn(x - __half2float(h));
}

// ---------------------------------------------------------------------------
// Big HMMA fp16 GEMM (K/V projections): C16 = A16 B16^T + bias, fp16 out.
// CTA 128x128x32, 8 warps, 3-stage cp.async. __launch_bounds__(256,2):
// occupancy-2 probe of the HMMA issue floor.
// ---------------------------------------------------------------------------
#define LDS_E 40
#define TILE_B (128 * LDS_E * 2)
#define STAGE_B (2 * TILE_B)
#define STAGES 3
#define HGEMM_SMEM (STAGES * STAGE_B)
#define KT_N (CKV / 32)

__global__ __launch_bounds__(256, 2) void hgemm_f16(
    const __half* __restrict__ A_g, const __half* __restrict__ B_g,
    const float* __restrict__ bias, __half* __restrict__ C)
{
    extern __shared__ char smem[];
    const uint32_t sbase = smem_u32(smem);
    const int tid = threadIdx.x;
    const int wid = tid >> 5, lane = tid & 31;
    const int wm = (wid & 1) * 64;
    const int wn = (wid >> 1) * 32;
    const int m0 = blockIdx.y * 128, n0 = blockIdx.x * 128;

    const int lr = tid >> 1;
    const int lc = (tid & 1) * 16;
    const uint32_t s_off = (uint32_t)(lr * 80 + (tid & 1) * 32);

    const __half* gA = A_g + (size_t)(m0 + lr) * CKV + lc;
    const __half* gB = B_g + (size_t)(n0 + lr) * CKV + lc;

    const int a_row = lane & 15;
    const int a_ko  = ((lane >> 4) & 1) * 8;
    const int b_row = (lane & 7) + ((lane >> 4) & 1) * 8;
    const int b_ko  = ((lane >> 3) & 1) * 8;

    float acc[4][4][4];
    #pragma unroll
    for (int i = 0; i < 4; i++)
        #pragma unroll
        for (int j = 0; j < 4; j++)
            #pragma unroll
            for (int c = 0; c < 4; c++) acc[i][j][c] = 0.f;

    auto load_stage = [&](int kt, int s) {
        const uint32_t sb = sbase + s * STAGE_B;
        const int ke = kt * 32;
        cp16(sb + s_off,               gA + ke);
        cp16(sb + s_off + 16,          gA + ke + 8);
        cp16(sb + TILE_B + s_off,      gB + ke);
        cp16(sb + TILE_B + s_off + 16, gB + ke + 8);
    };

    load_stage(0, 0); CP_COMMIT();
    load_stage(1, 1); CP_COMMIT();

    for (int kt = 0; kt < KT_N; kt++) {
        CP_WAIT(1);
        __syncthreads();

        const int nkt = kt + STAGES - 1;
        if (nkt < KT_N) load_stage(nkt, nkt % STAGES);
        CP_COMMIT();

        const uint32_t sb = sbase + (kt % STAGES) * STAGE_B;
        #pragma unroll
        for (int kb = 0; kb < 32; kb += 16) {
            uint32_t ah[4][4];
            #pragma unroll
            for (int mt = 0; mt < 4; mt++) {
                uint32_t ra = sb + (uint32_t)((wm + mt * 16 + a_row) * 80 + (a_ko + kb) * 2);
                ldsm_x4(ra, ah[mt][0], ah[mt][1], ah[mt][2], ah[mt][3]);
            }
            uint32_t bh[4][2];
            #pragma unroll
            for (int np = 0; np < 2; np++) {
                uint32_t rb = sb + TILE_B +
                              (uint32_t)((wn + np * 16 + b_row) * 80 + (b_ko + kb) * 2);
                ldsm_x4(rb, bh[np * 2][0], bh[np * 2][1], bh[np * 2 + 1][0], bh[np * 2 + 1][1]);
            }
            #pragma unroll
            for (int mt = 0; mt < 4; mt++)
                #pragma unroll
                for (int nt = 0; nt < 4; nt++)
                    mma_f16(acc[mt][nt], ah[mt][0], ah[mt][1], ah[mt][2], ah[mt][3],
                            bh[nt][0], bh[nt][1]);
        }
    }

    const int er = lane >> 2, ec = (lane & 3) * 2;
    #pragma unroll
    for (int mt = 0; mt < 4; mt++) {
        #pragma unroll
        for (int nt = 0; nt < 4; nt++) {
            const int col = n0 + wn + nt * 8 + ec;
            const float b0 = bias[col], b1 = bias[col + 1];
            __half* p0 = C + (size_t)(m0 + wm + mt * 16 + er) * CQ + col;
            __half* p1 = p0 + 8 * CQ;
            st2(p0, acc[mt][nt][0] + b0, acc[mt][nt][1] + b1);
            st2(p1, acc[mt][nt][2] + b0, acc[mt][nt][3] + b1);
        }
    }
}

// ---------------------------------------------------------------------------
// Small HMMA fp16x2 GEMM (Q / O projections): C = A16 (Bh+Bl)^T + bias.
// K=768, CTA 64x64x32, 4 warps (warp 32x32), 3-stage. Static smem.
// ---------------------------------------------------------------------------
#define QO_TILE_B 5120                 // 64 rows * 80 B
#define QO_STAGE_B (3 * QO_TILE_B)     // A, Bh, Bl
#define QO_STAGES 3
#define QO_KT (CQ / 32)                // 24

template <typename OutT>
__global__ __launch_bounds__(128) void hgemm_qo(
    const __half* __restrict__ A_g, const __half* __restrict__ Bh_g,
    const __half* __restrict__ Bl_g, const float* __restrict__ bias,
    OutT* __restrict__ C)
{
    __shared__ char smem[QO_STAGES * QO_STAGE_B];
    const uint32_t sbase = smem_u32(smem);
    const int tid = threadIdx.x;
    const int wid = tid >> 5, lane = tid & 31;
    const int wm = (wid & 1) * 32;
    const int wn = (wid >> 1) * 32;
    const int m0 = blockIdx.y * 64, n0 = blockIdx.x * 64;

    const int lr = tid >> 1;
    const int lc = (tid & 1) * 16;
    const uint32_t s_off = (uint32_t)(lr * 80 + (tid & 1) * 32);

    const __half* gA  = A_g  + (size_t)(m0 + lr) * CQ + lc;
    const __half* gBh = Bh_g + (size_t)(n0 + lr) * CQ + lc;
    const __half* gBl = Bl_g + (size_t)(n0 + lr) * CQ + lc;

    const int a_row = lane & 15;
    const int a_ko  = ((lane >> 4) & 1) * 8;
    const int b_row = (lane & 7) + ((lane >> 4) & 1) * 8;
    const int b_ko  = ((lane >> 3) & 1) * 8;

    float acc[2][4][4];
    #pragma unroll
    for (int i = 0; i < 2; i++)
        #pragma unroll
        for (int j = 0; j < 4; j++)
            #pragma unroll
            for (int c = 0; c < 4; c++) acc[i][j][c] = 0.f;

    auto load_stage = [&](int kt, int s) {
        const uint32_t sb = sbase + s * QO_STAGE_B;
        const int ke = kt * 32;
        cp16(sb + s_off,                    gA  + ke);
        cp16(sb + s_off + 16,               gA  + ke + 8);
        cp16(sb + QO_TILE_B + s_off,        gBh + ke);
        cp16(sb + QO_TILE_B + s_off + 16,   gBh + ke + 8);
        cp16(sb + 2*QO_TILE_B + s_off,      gBl + ke);
        cp16(sb + 2*QO_TILE_B + s_off + 16, gBl + ke + 8);
    };

    load_stage(0, 0); CP_COMMIT();
    load_stage(1, 1); CP_COMMIT();

    for (int kt = 0; kt < QO_KT; kt++) {
        CP_WAIT(1);
        __syncthreads();

        const int nkt = kt + QO_STAGES - 1;
        if (nkt < QO_KT) load_stage(nkt, nkt % QO_STAGES);
        CP_COMMIT();

        const uint32_t sb = sbase + (kt % QO_STAGES) * QO_STAGE_B;
        #pragma unroll
        for (int kb = 0; kb < 32; kb += 16) {
            uint32_t a[2][4];
            #pragma unroll
            for (int mt = 0; mt < 2; mt++) {
                uint32_t ra = sb + (uint32_t)((wm + mt * 16 + a_row) * 80 + (a_ko + kb) * 2);
                ldsm_x4(ra, a[mt][0], a[mt][1], a[mt][2], a[mt][3]);
            }
            uint32_t bh[4][2], bl[4][2];
            #pragma unroll
            for (int ng = 0; ng < 2; ng++) {
                uint32_t rbh = sb + QO_TILE_B +
                               (uint32_t)((wn + ng * 16 + b_row) * 80 + (b_ko + kb) * 2);
                ldsm_x4(rbh, bh[2*ng][0], bh[2*ng][1], bh[2*ng+1][0], bh[2*ng+1][1]);
                ldsm_x4(rbh + QO_TILE_B, bl[2*ng][0], bl[2*ng][1], bl[2*ng+1][0], bl[2*ng+1][1]);
            }
            #pragma unroll
            for (int mt = 0; mt < 2; mt++)
                #pragma unroll
                for (int nt = 0; nt < 4; nt++) {
                    mma_f16(acc[mt][nt], a[mt][0], a[mt][1], a[mt][2], a[mt][3],
                            bh[nt][0], bh[nt][1]);
                    mma_f16(acc[mt][nt], a[mt][0], a[mt][1], a[mt][2], a[mt][3],
                            bl[nt][0], bl[nt][1]);
                }
        }
    }

    const int er = lane >> 2, ec = (lane & 3) * 2;
    #pragma unroll
    for (int mt = 0; mt < 2; mt++) {
        #pragma unroll
        for (int nt = 0; nt < 4; nt++) {
            const int col = n0 + wn + nt * 8 + ec;
            const float b0 = bias[col], b1 = bias[col + 1];
            OutT* p0 = C + (size_t)(m0 + wm + mt * 16 + er) * CQ + col;
            OutT* p1 = p0 + 8 * CQ;
            st2(p0, acc[mt][nt][0] + b0, acc[mt][nt][1] + b1);
            st2(p1, acc[mt][nt][2] + b0, acc[mt][nt][3] + b1);
        }
    }
}

// ---------------------------------------------------------------------------
// HMMA split-KV flash attention partial (Q fp16 in)
// ---------------------------------------------------------------------------
#define KV_PER_SPLIT (NKV / SPLIT)

__global__ __launch_bounds__(128) void attention_hmma(
    const __half* __restrict__ Qg, const __half* __restrict__ Kg,
    const __half* __restrict__ Vg,
    float* __restrict__ accP, float* __restrict__ mP, float* __restrict__ lP)
{
    __shared__ __half Qs[64][72];
    __shared__ __half Ks[64][72];
    __shared__ __half Vs[64][72];

    const int bh = blockIdx.x / SPLIT;
    const int sp = blockIdx.x % SPLIT;
    const int b = bh / H_, h = bh % H_;
    const int tid = threadIdx.x;
    const int w = tid >> 5, lane = tid & 31;

    // Q fp16 scaled by 1/8 (exact power of two)
    {
        const __half2 sc = __floats2half2_rn(0.125f, 0.125f);
        for (int idx = tid; idx < 512; idx += 128) {
            int r = idx >> 3, c8 = (idx & 7) * 8;
            uint4 v = *(const uint4*)(Qg + (size_t)(b * NQ + r) * CQ + h * D_ + c8);
            __half2* s = (__half2*)&v;
            __half2* d = (__half2*)&Qs[r][c8];
            d[0] = __hmul2(s[0], sc); d[1] = __hmul2(s[1], sc);
            d[2] = __hmul2(s[2], sc); d[3] = __hmul2(s[3], sc);
        }
    }

    const int qa_row = lane & 15;
    const int qa_ko  = ((lane >> 4) & 1) * 8;
    const int kb_row = (lane & 7) + ((lane >> 4) & 1) * 8;
    const int kb_ko  = ((lane >> 3) & 1) * 8;
    const int vt_row = (lane & 7) + ((lane >> 3) & 1) * 8;
    const int vt_co  = ((lane >> 4) & 1) * 8;

    float m0 = -1e30f, m1 = -1e30f, l0 = 0.f, l1 = 0.f;
    float o[8][4];
    #pragma unroll
    for (int i = 0; i < 8; i++)
        #pragma unroll
        for (int j = 0; j < 4; j++) o[i][j] = 0.f;

    const int kv_lo = sp * KV_PER_SPLIT;
    for (int kv0 = kv_lo; kv0 < kv_lo + KV_PER_SPLIT; kv0 += 64) {
        __syncthreads();
        for (int idx = tid; idx < 512; idx += 128) {
            int r = idx >> 3, sg = idx & 7;
            size_t gofs = (size_t)(b * NKV + kv0 + r) * CQ + h * D_ + sg * 8;
            cp16(smem_u32(&Ks[r][sg * 8]), Kg + gofs);
            cp16(smem_u32(&Vs[r][sg * 8]), Vg + gofs);
        }
        CP_COMMIT(); CP_WAIT(0);
        __syncthreads();

        float s[8][4];
        #pragma unroll
        for (int i = 0; i < 8; i++)
            #pragma unroll
            for (int j = 0; j < 4; j++) s[i][j] = 0.f;

        #pragma unroll
        for (int kk = 0; kk < 4; kk++) {
            uint32_t a0, a1, a2, a3;
            ldsm_x4(smem_u32(&Qs[w * 16 + qa_row][kk * 16 + qa_ko]), a0, a1, a2, a3);
            #pragma unroll
            for (int ng = 0; ng < 4; ng++) {
                uint32_t b0, b1, b2, b3;
                ldsm_x4(smem_u32(&Ks[ng * 16 + kb_row][kk * 16 + kb_ko]), b0, b1, b2, b3);
                mma_f16(s[2 * ng],     a0, a1, a2, a3, b0, b1);
                mma_f16(s[2 * ng + 1], a0, a1, a2, a3, b2, b3);
            }
        }

        float mx0 = -1e30f, mx1 = -1e30f;
        #pragma unroll
        for (int nt = 0; nt < 8; nt++) {
            mx0 = fmaxf(mx0, fmaxf(s[nt][0], s[nt][1]));
            mx1 = fmaxf(mx1, fmaxf(s[nt][2], s[nt][3]));
        }
        #pragma unroll
        for (int ofs = 1; ofs < 4; ofs <<= 1) {
            mx0 = fmaxf(mx0, __shfl_xor_sync(0xffffffffu, mx0, ofs));
            mx1 = fmaxf(mx1, __shfl_xor_sync(0xffffffffu, mx1, ofs));
        }
        float M0 = fmaxf(m0, mx0), M1 = fmaxf(m1, mx1);
        float c0 = __expf(m0 - M0), c1 = __expf(m1 - M1);
        float ls0 = 0.f, ls1 = 0.f;
        #pragma unroll
        for (int nt = 0; nt < 8; nt++) {
            s[nt][0] = __expf(s[nt][0] - M0); ls0 += s[nt][0];
            s[nt][1] = __expf(s[nt][1] - M0); ls0 += s[nt][1];
            s[nt][2] = __expf(s[nt][2] - M1); ls1 += s[nt][2];
            s[nt][3] = __expf(s[nt][3] - M1); ls1 += s[nt][3];
        }
        #pragma unroll
        for (int ofs = 1; ofs < 4; ofs <<= 1) {
            ls0 += __shfl_xor_sync(0xffffffffu, ls0, ofs);
            ls1 += __shfl_xor_sync(0xffffffffu, ls1, ofs);
        }
        l0 = l0 * c0 + ls0;  l1 = l1 * c1 + ls1;
        m0 = M0;  m1 = M1;
        #pragma unroll
        for (int nt = 0; nt < 8; nt++) {
            o[nt][0] *= c0; o[nt][1] *= c0;
            o[nt][2] *= c1; o[nt][3] *= c1;
        }

        uint32_t pu[8][2];
        #pragma unroll
        for (int nt = 0; nt < 8; nt++) {
            pu[nt][0] = pack_h2(s[nt][0], s[nt][1]);
            pu[nt][1] = pack_h2(s[nt][2], s[nt][3]);
        }

        #pragma unroll
        for (int t = 0; t < 4; t++) {
            uint32_t a0 = pu[2 * t][0],     a1 = pu[2 * t][1];
            uint32_t a2 = pu[2 * t + 1][0], a3 = pu[2 * t + 1][1];
            #pragma unroll
            for (int dg = 0; dg < 4; dg++) {
                uint32_t b0, b1, b2, b3;
                ldsm_x4_t(smem_u32(&Vs[t * 16 + vt_row][dg * 16 + vt_co]), b0, b1, b2, b3);
                mma_f16(o[2 * dg],     a0, a1, a2, a3, b0, b1);
                mma_f16(o[2 * dg + 1], a0, a1, a2, a3, b2, b3);
            }
        }
    }

    float* accp = accP + (size_t)blockIdx.x * 64 * 64;
    const int r0 = w * 16 + (lane >> 2), r1 = r0 + 8;
    const int cb = (lane & 3) * 2;
    #pragma unroll
    for (int nt = 0; nt < 8; nt++) {
        st2(&accp[r0 * 64 + nt * 8 + cb], o[nt][0], o[nt][1]);
        st2(&accp[r1 * 64 + nt * 8 + cb], o[nt][2], o[nt][3]);
    }
    if ((lane & 3) == 0) {
        mP[(size_t)blockIdx.x * 64 + r0] = m0;
        lP[(size_t)blockIdx.x * 64 + r0] = l0;
        mP[(size_t)blockIdx.x * 64 + r1] = m1;
        lP[(size_t)blockIdx.x * 64 + r1] = l1;
    }
}

__global__ __launch_bounds__(256) void attention_combine(
    const float* __restrict__ accP, const float* __restrict__ mP,
    const float* __restrict__ lP, __half* __restrict__ Xg)
{
    __shared__ float sw[SPLIT][64];
    __shared__ float sden[64];
    const int bh = blockIdx.x;
    const int b = bh / H_, h = bh % H_;
    const int tid = threadIdx.x;

    if (tid < 64) {
        int r = tid;
        float M = -1e30f;
        #pragma unroll
        for (int s = 0; s < SPLIT; s++)
            M = fmaxf(M, mP[(size_t)(bh * SPLIT + s) * 64 + r]);
        float den = 0.f;
        #pragma unroll
        for (int s = 0; s < SPLIT; s++) {
            float w = __expf(mP[(size_t)(bh * SPLIT + s) * 64 + r] - M);
            sw[s][r] = w;
            den += w * lP[(size_t)(bh * SPLIT + s) * 64 + r];
        }
        sden[r] = den;
    }
    __syncthreads();

    for (int idx = tid; idx < 64 * 64; idx += 256) {
        int r = idx >> 6, d = idx & 63;
        float num = 0.f;
        #pragma unroll
        for (int s = 0; s < SPLIT; s++)
            num += sw[s][r] * accP[(size_t)(bh * SPLIT + s) * 4096 + idx];
        Xg[(size_t)(b * NQ + r) * CQ + h * D_ + d] = __float2half_rn(num / sden[r]);
    }
}

// ---------------------------------------------------------------------------
extern "C" void kernel_launch(void* const* d_in, const int* in_sizes, int n_in,
                              void* d_out, int out_size)
{
    const float* query = (const float*)d_in[0];
    const float* kv    = (const float*)d_in[1];
    const float* Wq    = (const float*)d_in[2];
    const float* bq    = (const float*)d_in[3];
    const float* Wk    = (const float*)d_in[4];
    const float* bk    = (const float*)d_in[5];
    const float* Wv    = (const float*)d_in[6];
    const float* bv    = (const float*)d_in[7];
    const float* Wo    = (const float*)d_in[8];
    const float* bo    = (const float*)d_in[9];
    float* out = (float*)d_out;

    float *accp, *mp, *lp;
    __half *qa, *qh, *xh, *kp, *vp, *kva, *wkt, *wvt, *wqth, *wqtl, *woth, *wotl;
    cudaGetSymbolAddress((void**)&qa, g_qa);
    cudaGetSymbolAddress((void**)&qh, g_qh);
    cudaGetSymbolAddress((void**)&xh, g_xh);
    cudaGetSymbolAddress((void**)&kp, g_kh);
    cudaGetSymbolAddress((void**)&vp, g_vh);
    cudaGetSymbolAddress((void**)&kva, g_kva);
    cudaGetSymbolAddress((void**)&wkt, g_wkt);
    cudaGetSymbolAddress((void**)&wvt, g_wvt);
    cudaGetSymbolAddress((void**)&wqth, g_wqth);
    cudaGetSymbolAddress((void**)&wqtl, g_wqtl);
    cudaGetSymbolAddress((void**)&woth, g_woth);
    cudaGetSymbolAddress((void**)&wotl, g_wotl);
    cudaGetSymbolAddress((void**)&accp, g_accP);
    cudaGetSymbolAddress((void**)&mp, g_mP);
    cudaGetSymbolAddress((void**)&lp, g_lP);

    cudaFuncSetAttribute(hgemm_f16,
                         cudaFuncAttributeMaxDynamicSharedMemorySize, HGEMM_SMEM);

    // 1. prep
    round_kernel<<<2048, 256>>>(kv, kva, (size_t)B_ * NKV * CKV / 4);
    round_kernel<<<768, 256>>>(query, qa, (size_t)B_ * NQ * CQ / 4);
    transpose_f16_kernel<<<dim3(CKV / 256, CQ), 256>>>(Wk, wkt);
    transpose_f16_kernel<<<dim3(CKV / 256, CQ), 256>>>(Wv, wvt);
    transpose_split768<<<dim3(CQ / 256, CQ), 256>>>(Wq, wqth, wqtl);
    transpose_split768<<<dim3(CQ / 256, CQ), 256>>>(Wo, woth, wotl);

    // 2. q projection (HMMA fp16x2, fp16 out)
    hgemm_qo<__half><<<dim3(CQ / 64, (B_ * NQ) / 64), 128>>>(qa, wqth, wqtl, bq, qh);

    // 3. K / V projections (HMMA fp16, fp16 out; occupancy-2 probe)
    dim3 ggrid(CQ / 128, (B_ * NKV) / 128);
    hgemm_f16<<<ggrid, 256, HGEMM_SMEM>>>(kva, wkt, bk, kp);
    hgemm_f16<<<ggrid, 256, HGEMM_SMEM>>>(kva, wvt, bv, vp);

    // 4. HMMA split-KV attention + combine (fp16 x out)
    attention_hmma<<<B_ * H_ * SPLIT, 128>>>(qh, kp, vp, accp, mp, lp);
    attention_combine<<<B_ * H_, 256>>>(accp, mp, lp, xh);

    // 5. output projection (HMMA fp16x2, fp32 out)
    hgemm_qo<float><<<dim3(CQ / 64, (B_ * NQ) / 64), 128>>>(xh, woth, wotl, bo, out);
}

// round 9
// speedup vs baseline: 6.4960x; 1.0640x over previous
#include <cuda_runtime.h>
#include <cuda_bf16.h>
#include <cuda_fp16.h>
#include <math.h>
#include <stdint.h>

#define B_   16
#define NQ   64
#define NKV  4096
#define CQ   768
#define CKV  1024
#define H_   12
#define D_   64
#define SPLIT 8

// ---------------- scratch (device globals; allocation-free) ----------------
__device__ __half g_qa [(size_t)B_ * NQ * CQ];
__device__ __half g_qh [(size_t)B_ * NQ * CQ];
__device__ __half g_xh [(size_t)B_ * NQ * CQ];
__device__ __half g_kh [(size_t)B_ * NKV * CQ];
__device__ __half g_vh [(size_t)B_ * NKV * CQ];
__device__ __half g_kva[(size_t)B_ * NKV * CKV];
__device__ __half g_wkt [(size_t)CQ * CKV];
__device__ __half g_wvt [(size_t)CQ * CKV];
__device__ __half g_wqth[(size_t)CQ * CQ];
__device__ __half g_wqtl[(size_t)CQ * CQ];
__device__ __half g_woth[(size_t)CQ * CQ];
__device__ __half g_wotl[(size_t)CQ * CQ];
__device__ float g_accP[(size_t)B_ * H_ * SPLIT * NQ * D_];
__device__ float g_mP[(size_t)B_ * H_ * SPLIT * NQ];
__device__ float g_lP[(size_t)B_ * H_ * SPLIT * NQ];

// ---------------- helpers ----------------
__device__ __forceinline__ uint32_t smem_u32(const void* p) {
    uint32_t a;
    asm("{ .reg .u64 t; cvta.to.shared.u64 t, %1; cvt.u32.u64 %0, t; }"
        : "=r"(a) : "l"(p));
    return a;
}
__device__ __forceinline__ void cp16(uint32_t s, const void* g) {
    asm volatile("cp.async.cg.shared.global [%0], [%1], 16;\n"
                 :: "r"(s), "l"(__cvta_generic_to_global(g)) : "memory");
}
#define CP_COMMIT() asm volatile("cp.async.commit_group;\n" ::: "memory")
#define CP_WAIT(n)  asm volatile("cp.async.wait_group %0;\n" :: "n"(n) : "memory")

__device__ __forceinline__ void ldsm_x4(uint32_t addr, uint32_t& r0, uint32_t& r1,
                                        uint32_t& r2, uint32_t& r3) {
    asm volatile("ldmatrix.sync.aligned.m8n8.x4.shared.b16 {%0,%1,%2,%3}, [%4];"
                 : "=r"(r0), "=r"(r1), "=r"(r2), "=r"(r3) : "r"(addr));
}
__device__ __forceinline__ void ldsm_x4_t(uint32_t addr, uint32_t& r0, uint32_t& r1,
                                          uint32_t& r2, uint32_t& r3) {
    asm volatile("ldmatrix.sync.aligned.m8n8.x4.trans.shared.b16 {%0,%1,%2,%3}, [%4];"
                 : "=r"(r0), "=r"(r1), "=r"(r2), "=r"(r3) : "r"(addr));
}
__device__ __forceinline__ void mma_f16(float* d, uint32_t a0, uint32_t a1,
                                        uint32_t a2, uint32_t a3,
                                        uint32_t b0, uint32_t b1) {
    asm volatile(
        "mma.sync.aligned.m16n8k16.row.col.f32.f16.f16.f32 "
        "{%0,%1,%2,%3}, {%4,%5,%6,%7}, {%8,%9}, {%0,%1,%2,%3};"
        : "+f"(d[0]), "+f"(d[1]), "+f"(d[2]), "+f"(d[3])
        : "r"(a0), "r"(a1), "r"(a2), "r"(a3), "r"(b0), "r"(b1));
}
__device__ __forceinline__ uint32_t pack_h2(float a, float b) {
    __half2 h = __floats2half2_rn(a, b);
    return *(uint32_t*)&h;
}
__device__ __forceinline__ void st2(float* p, float a, float b) {
    float2 v = { a, b }; *(float2*)p = v;
}
__device__ __forceinline__ void st2(__half* p, float a, float b) {
    *(uint32_t*)p = pack_h2(a, b);
}

// ---------------------------------------------------------------------------
// prep kernels
// ---------------------------------------------------------------------------
__global__ __launch_bounds__(256) void round_kernel(
    const float* __restrict__ src, __half* __restrict__ dst, size_t n4)
{
    size_t i = ((size_t)blockIdx.x * blockDim.x + threadIdx.x) * 2;
    size_t stride = (size_t)gridDim.x * blockDim.x * 2;
    for (; i < n4; i += stride) {
        float4 x = ((const float4*)src)[i];
        float4 y = ((const float4*)src)[i + 1];
        ((__half2*)dst)[i * 2]     = __floats2half2_rn(x.x, x.y);
        ((__half2*)dst)[i * 2 + 1] = __floats2half2_rn(x.z, x.w);
        ((__half2*)dst)[i * 2 + 2] = __floats2half2_rn(y.x, y.y);
        ((__half2*)dst)[i * 2 + 3] = __floats2half2_rn(y.z, y.w);
    }
}

// W [K=1024][N=768] -> Wt [768][1024] fp16, tiled coalesced
__global__ __launch_bounds__(256) void transpose_f16_tiled(
    const float* __restrict__ W, __half* __restrict__ th)
{
    __shared__ float t[32][33];
    const int kb = blockIdx.x * 32, nb = blockIdx.y * 32;
    const int tx = threadIdx.x & 31, ty = threadIdx.x >> 5;   // 32 x 8
    #pragma unroll
    for (int i = ty; i < 32; i += 8)
        t[i][tx] = W[(size_t)(kb + i) * CQ + nb + tx];
    __syncthreads();
    #pragma unroll
    for (int i = ty; i < 32; i += 8)
        th[(size_t)(nb + i) * CKV + kb + tx] = __float2half_rn(t[tx][i]);
}

// W [768][768] -> Wt hi/lo [768][768], tiled coalesced
__global__ __launch_bounds__(256) void transpose_split768_tiled(
    const float* __restrict__ W, __half* __restrict__ th, __half* __restrict__ tl)
{
    __shared__ float t[32][33];
    const int kb = blockIdx.x * 32, nb = blockIdx.y * 32;
    const int tx = threadIdx.x & 31, ty = threadIdx.x >> 5;
    #pragma unroll
    for (int i = ty; i < 32; i += 8)
        t[i][tx] = W[(size_t)(kb + i) * CQ + nb + tx];
    __syncthreads();
    #pragma unroll
    for (int i = ty; i < 32; i += 8) {
        float x = t[tx][i];
        __half h = __float2half_rn(x);
        th[(size_t)(nb + i) * CQ + kb + tx] = h;
        tl[(size_t)(nb + i) * CQ + kb + tx] = __float2half_rn(x - __half2float(h));
    }
}

// ---------------------------------------------------------------------------
// Big HMMA fp16 GEMM (K/V projections): C16 = A16 B16^T + bias, fp16 out.
// CTA 128x128x32, 8 warps, 3-stage cp.async, occupancy 2.
// ---------------------------------------------------------------------------
#define LDS_E 40
#define TILE_B (128 * LDS_E * 2)
#define STAGE_B (2 * TILE_B)
#define STAGES 3
#define HGEMM_SMEM (STAGES * STAGE_B)
#define KT_N (CKV / 32)

__global__ __launch_bounds__(256, 2) void hgemm_f16(
    const __half* __restrict__ A_g, const __half* __restrict__ B_g,
    const float* __restrict__ bias, __half* __restrict__ C)
{
    extern __shared__ char smem[];
    const uint32_t sbase = smem_u32(smem);
    const int tid = threadIdx.x;
    const int wid = tid >> 5, lane = tid & 31;
    const int wm = (wid & 1) * 64;
    const int wn = (wid >> 1) * 32;
    const int m0 = blockIdx.y * 128, n0 = blockIdx.x * 128;

    const int lr = tid >> 1;
    const int lc = (tid & 1) * 16;
    const uint32_t s_off = (uint32_t)(lr * 80 + (tid & 1) * 32);

    const __half* gA = A_g + (size_t)(m0 + lr) * CKV + lc;
    const __half* gB = B_g + (size_t)(n0 + lr) * CKV + lc;

    const int a_row = lane & 15;
    const int a_ko  = ((lane >> 4) & 1) * 8;
    const int b_row = (lane & 7) + ((lane >> 4) & 1) * 8;
    const int b_ko  = ((lane >> 3) & 1) * 8;

    float acc[4][4][4];
    #pragma unroll
    for (int i = 0; i < 4; i++)
        #pragma unroll
        for (int j = 0; j < 4; j++)
            #pragma unroll
            for (int c = 0; c < 4; c++) acc[i][j][c] = 0.f;

    auto load_stage = [&](int kt, int s) {
        const uint32_t sb = sbase + s * STAGE_B;
        const int ke = kt * 32;
        cp16(sb + s_off,               gA + ke);
        cp16(sb + s_off + 16,          gA + ke + 8);
        cp16(sb + TILE_B + s_off,      gB + ke);
        cp16(sb + TILE_B + s_off + 16, gB + ke + 8);
    };

    load_stage(0, 0); CP_COMMIT();
    load_stage(1, 1); CP_COMMIT();

    for (int kt = 0; kt < KT_N; kt++) {
        CP_WAIT(1);
        __syncthreads();

        const int nkt = kt + STAGES - 1;
        if (nkt < KT_N) load_stage(nkt, nkt % STAGES);
        CP_COMMIT();

        const uint32_t sb = sbase + (kt % STAGES) * STAGE_B;
        #pragma unroll
        for (int kb = 0; kb < 32; kb += 16) {
            uint32_t ah[4][4];
            #pragma unroll
            for (int mt = 0; mt < 4; mt++) {
                uint32_t ra = sb + (uint32_t)((wm + mt * 16 + a_row) * 80 + (a_ko + kb) * 2);
                ldsm_x4(ra, ah[mt][0], ah[mt][1], ah[mt][2], ah[mt][3]);
            }
            uint32_t bh[4][2];
            #pragma unroll
            for (int np = 0; np < 2; np++) {
                uint32_t rb = sb + TILE_B +
                              (uint32_t)((wn + np * 16 + b_row) * 80 + (b_ko + kb) * 2);
                ldsm_x4(rb, bh[np * 2][0], bh[np * 2][1], bh[np * 2 + 1][0], bh[np * 2 + 1][1]);
            }
            #pragma unroll
            for (int mt = 0; mt < 4; mt++)
                #pragma unroll
                for (int nt = 0; nt < 4; nt++)
                    mma_f16(acc[mt][nt], ah[mt][0], ah[mt][1], ah[mt][2], ah[mt][3],
                            bh[nt][0], bh[nt][1]);
        }
    }

    const int er = lane >> 2, ec = (lane & 3) * 2;
    #pragma unroll
    for (int mt = 0; mt < 4; mt++) {
        #pragma unroll
        for (int nt = 0; nt < 4; nt++) {
            const int col = n0 + wn + nt * 8 + ec;
            const float b0 = bias[col], b1 = bias[col + 1];
            __half* p0 = C + (size_t)(m0 + wm + mt * 16 + er) * CQ + col;
            __half* p1 = p0 + 8 * CQ;
            st2(p0, acc[mt][nt][0] + b0, acc[mt][nt][1] + b1);
            st2(p1, acc[mt][nt][2] + b0, acc[mt][nt][3] + b1);
        }
    }
}

// ---------------------------------------------------------------------------
// Small HMMA fp16x2 GEMM (Q / O projections)
// ---------------------------------------------------------------------------
#define QO_TILE_B 5120
#define QO_STAGE_B (3 * QO_TILE_B)
#define QO_STAGES 3
#define QO_KT (CQ / 32)

template <typename OutT>
__global__ __launch_bounds__(128) void hgemm_qo(
    const __half* __restrict__ A_g, const __half* __restrict__ Bh_g,
    const __half* __restrict__ Bl_g, const float* __restrict__ bias,
    OutT* __restrict__ C)
{
    __shared__ char smem[QO_STAGES * QO_STAGE_B];
    const uint32_t sbase = smem_u32(smem);
    const int tid = threadIdx.x;
    const int wid = tid >> 5, lane = tid & 31;
    const int wm = (wid & 1) * 32;
    const int wn = (wid >> 1) * 32;
    const int m0 = blockIdx.y * 64, n0 = blockIdx.x * 64;

    const int lr = tid >> 1;
    const int lc = (tid & 1) * 16;
    const uint32_t s_off = (uint32_t)(lr * 80 + (tid & 1) * 32);

    const __half* gA  = A_g  + (size_t)(m0 + lr) * CQ + lc;
    const __half* gBh = Bh_g + (size_t)(n0 + lr) * CQ + lc;
    const __half* gBl = Bl_g + (size_t)(n0 + lr) * CQ + lc;

    const int a_row = lane & 15;
    const int a_ko  = ((lane >> 4) & 1) * 8;
    const int b_row = (lane & 7) + ((lane >> 4) & 1) * 8;
    const int b_ko  = ((lane >> 3) & 1) * 8;

    float acc[2][4][4];
    #pragma unroll
    for (int i = 0; i < 2; i++)
        #pragma unroll
        for (int j = 0; j < 4; j++)
            #pragma unroll
            for (int c = 0; c < 4; c++) acc[i][j][c] = 0.f;

    auto load_stage = [&](int kt, int s) {
        const uint32_t sb = sbase + s * QO_STAGE_B;
        const int ke = kt * 32;
        cp16(sb + s_off,                    gA  + ke);
        cp16(sb + s_off + 16,               gA  + ke + 8);
        cp16(sb + QO_TILE_B + s_off,        gBh + ke);
        cp16(sb + QO_TILE_B + s_off + 16,   gBh + ke + 8);
        cp16(sb + 2*QO_TILE_B + s_off,      gBl + ke);
        cp16(sb + 2*QO_TILE_B + s_off + 16, gBl + ke + 8);
    };

    load_stage(0, 0); CP_COMMIT();
    load_stage(1, 1); CP_COMMIT();

    for (int kt = 0; kt < QO_KT; kt++) {
        CP_WAIT(1);
        __syncthreads();

        const int nkt = kt + QO_STAGES - 1;
        if (nkt < QO_KT) load_stage(nkt, nkt % QO_STAGES);
        CP_COMMIT();

        const uint32_t sb = sbase + (kt % QO_STAGES) * QO_STAGE_B;
        #pragma unroll
        for (int kb = 0; kb < 32; kb += 16) {
            uint32_t a[2][4];
            #pragma unroll
            for (int mt = 0; mt < 2; mt++) {
                uint32_t ra = sb + (uint32_t)((wm + mt * 16 + a_row) * 80 + (a_ko + kb) * 2);
                ldsm_x4(ra, a[mt][0], a[mt][1], a[mt][2], a[mt][3]);
            }
            uint32_t bh[4][2], bl[4][2];
            #pragma unroll
            for (int ng = 0; ng < 2; ng++) {
                uint32_t rbh = sb + QO_TILE_B +
                               (uint32_t)((wn + ng * 16 + b_row) * 80 + (b_ko + kb) * 2);
                ldsm_x4(rbh, bh[2*ng][0], bh[2*ng][1], bh[2*ng+1][0], bh[2*ng+1][1]);
                ldsm_x4(rbh + QO_TILE_B, bl[2*ng][0], bl[2*ng][1], bl[2*ng+1][0], bl[2*ng+1][1]);
            }
            #pragma unroll
            for (int mt = 0; mt < 2; mt++)
                #pragma unroll
                for (int nt = 0; nt < 4; nt++) {
                    mma_f16(acc[mt][nt], a[mt][0], a[mt][1], a[mt][2], a[mt][3],
                            bh[nt][0], bh[nt][1]);
                    mma_f16(acc[mt][nt], a[mt][0], a[mt][1], a[mt][2], a[mt][3],
                            bl[nt][0], bl[nt][1]);
                }
        }
    }

    const int er = lane >> 2, ec = (lane & 3) * 2;
    #pragma unroll
    for (int mt = 0; mt < 2; mt++) {
        #pragma unroll
        for (int nt = 0; nt < 4; nt++) {
            const int col = n0 + wn + nt * 8 + ec;
            const float b0 = bias[col], b1 = bias[col + 1];
            OutT* p0 = C + (size_t)(m0 + wm + mt * 16 + er) * CQ + col;
            OutT* p1 = p0 + 8 * CQ;
            st2(p0, acc[mt][nt][0] + b0, acc[mt][nt][1] + b1);
            st2(p1, acc[mt][nt][2] + b0, acc[mt][nt][3] + b1);
        }
    }
}

// ---------------------------------------------------------------------------
// HMMA split-KV flash attention partial, double-buffered K/V chunks
// ---------------------------------------------------------------------------
#define KV_PER_SPLIT (NKV / SPLIT)
#define N_CHUNKS (KV_PER_SPLIT / 64)   // 8

__global__ __launch_bounds__(128) void attention_hmma(
    const __half* __restrict__ Qg, const __half* __restrict__ Kg,
    const __half* __restrict__ Vg,
    float* __restrict__ accP, float* __restrict__ mP, float* __restrict__ lP)
{
    __shared__ __half Qs[64][72];
    __shared__ __half Ks[2][64][72];
    __shared__ __half Vs[2][64][72];

    const int bh = blockIdx.x / SPLIT;
    const int sp = blockIdx.x % SPLIT;
    const int b = bh / H_, h = bh % H_;
    const int tid = threadIdx.x;
    const int w = tid >> 5, lane = tid & 31;
    const int kv_lo = sp * KV_PER_SPLIT;

    auto load_chunk = [&](int c, int buf) {
        const int kv0 = kv_lo + c * 64;
        #pragma unroll
        for (int idx = tid; idx < 512; idx += 128) {
            int r = idx >> 3, sg = idx & 7;
            size_t gofs = (size_t)(b * NKV + kv0 + r) * CQ + h * D_ + sg * 8;
            cp16(smem_u32(&Ks[buf][r][sg * 8]), Kg + gofs);
            cp16(smem_u32(&Vs[buf][r][sg * 8]), Vg + gofs);
        }
        CP_COMMIT();
    };

    load_chunk(0, 0);   // prefetch first chunk before Q conversion

    // Q fp16 scaled by 1/8 (exact power of two)
    {
        const __half2 sc = __floats2half2_rn(0.125f, 0.125f);
        for (int idx = tid; idx < 512; idx += 128) {
            int r = idx >> 3, c8 = (idx & 7) * 8;
            uint4 v = *(const uint4*)(Qg + (size_t)(b * NQ + r) * CQ + h * D_ + c8);
            __half2* s = (__half2*)&v;
            __half2* d = (__half2*)&Qs[r][c8];
            d[0] = __hmul2(s[0], sc); d[1] = __hmul2(s[1], sc);
            d[2] = __hmul2(s[2], sc); d[3] = __hmul2(s[3], sc);
        }
    }

    const int qa_row = lane & 15;
    const int qa_ko  = ((lane >> 4) & 1) * 8;
    const int kb_row = (lane & 7) + ((lane >> 4) & 1) * 8;
    const int kb_ko  = ((lane >> 3) & 1) * 8;
    const int vt_row = (lane & 7) + ((lane >> 3) & 1) * 8;
    const int vt_co  = ((lane >> 4) & 1) * 8;

    float m0 = -1e30f, m1 = -1e30f, l0 = 0.f, l1 = 0.f;
    float o[8][4];
    #pragma unroll
    for (int i = 0; i < 8; i++)
        #pragma unroll
        for (int j = 0; j < 4; j++) o[i][j] = 0.f;

    for (int c = 0; c < N_CHUNKS; c++) {
        const int cur = c & 1;
        if (c + 1 < N_CHUNKS) { load_chunk(c + 1, cur ^ 1); CP_WAIT(1); }
        else                  { CP_WAIT(0); }
        __syncthreads();   // chunk c resident (also publishes Qs on c==0)

        float s[8][4];
        #pragma unroll
        for (int i = 0; i < 8; i++)
            #pragma unroll
            for (int j = 0; j < 4; j++) s[i][j] = 0.f;

        #pragma unroll
        for (int kk = 0; kk < 4; kk++) {
            uint32_t a0, a1, a2, a3;
            ldsm_x4(smem_u32(&Qs[w * 16 + qa_row][kk * 16 + qa_ko]), a0, a1, a2, a3);
            #pragma unroll
            for (int ng = 0; ng < 4; ng++) {
                uint32_t b0, b1, b2, b3;
                ldsm_x4(smem_u32(&Ks[cur][ng * 16 + kb_row][kk * 16 + kb_ko]),
                        b0, b1, b2, b3);
                mma_f16(s[2 * ng],     a0, a1, a2, a3, b0, b1);
                mma_f16(s[2 * ng + 1], a0, a1, a2, a3, b2, b3);
            }
        }

        float mx0 = -1e30f, mx1 = -1e30f;
        #pragma unroll
        for (int nt = 0; nt < 8; nt++) {
            mx0 = fmaxf(mx0, fmaxf(s[nt][0], s[nt][1]));
            mx1 = fmaxf(mx1, fmaxf(s[nt][2], s[nt][3]));
        }
        #pragma unroll
        for (int ofs = 1; ofs < 4; ofs <<= 1) {
            mx0 = fmaxf(mx0, __shfl_xor_sync(0xffffffffu, mx0, ofs));
            mx1 = fmaxf(mx1, __shfl_xor_sync(0xffffffffu, mx1, ofs));
        }
        float M0 = fmaxf(m0, mx0), M1 = fmaxf(m1, mx1);
        float c0 = __expf(m0 - M0), c1 = __expf(m1 - M1);
        float ls0 = 0.f, ls1 = 0.f;
        #pragma unroll
        for (int nt = 0; nt < 8; nt++) {
            s[nt][0] = __expf(s[nt][0] - M0); ls0 += s[nt][0];
            s[nt][1] = __expf(s[nt][1] - M0); ls0 += s[nt][1];
            s[nt][2] = __expf(s[nt][2] - M1); ls1 += s[nt][2];
            s[nt][3] = __expf(s[nt][3] - M1); ls1 += s[nt][3];
        }
        #pragma unroll
        for (int ofs = 1; ofs < 4; ofs <<= 1) {
            ls0 += __shfl_xor_sync(0xffffffffu, ls0, ofs);
            ls1 += __shfl_xor_sync(0xffffffffu, ls1, ofs);
        }
        l0 = l0 * c0 + ls0;  l1 = l1 * c1 + ls1;
        m0 = M0;  m1 = M1;
        #pragma unroll
        for (int nt = 0; nt < 8; nt++) {
            o[nt][0] *= c0; o[nt][1] *= c0;
            o[nt][2] *= c1; o[nt][3] *= c1;
        }

        uint32_t pu[8][2];
        #pragma unroll
        for (int nt = 0; nt < 8; nt++) {
            pu[nt][0] = pack_h2(s[nt][0], s[nt][1]);
            pu[nt][1] = pack_h2(s[nt][2], s[nt][3]);
        }

        #pragma unroll
        for (int t = 0; t < 4; t++) {
            uint32_t a0 = pu[2 * t][0],     a1 = pu[2 * t][1];
            uint32_t a2 = pu[2 * t + 1][0], a3 = pu[2 * t + 1][1];
            #pragma unroll
            for (int dg = 0; dg < 4; dg++) {
                uint32_t b0, b1, b2, b3;
                ldsm_x4_t(smem_u32(&Vs[cur][t * 16 + vt_row][dg * 16 + vt_co]),
                          b0, b1, b2, b3);
                mma_f16(o[2 * dg],     a0, a1, a2, a3, b0, b1);
                mma_f16(o[2 * dg + 1], a0, a1, a2, a3, b2, b3);
            }
        }
        __syncthreads();   // all warps done with buf cur before next prefetch reuses it
    }

    float* accp = accP + (size_t)blockIdx.x * 64 * 64;
    const int r0 = w * 16 + (lane >> 2), r1 = r0 + 8;
    const int cb = (lane & 3) * 2;
    #pragma unroll
    for (int nt = 0; nt < 8; nt++) {
        st2(&accp[r0 * 64 + nt * 8 + cb], o[nt][0], o[nt][1]);
        st2(&accp[r1 * 64 + nt * 8 + cb], o[nt][2], o[nt][3]);
    }
    if ((lane & 3) == 0) {
        mP[(size_t)blockIdx.x * 64 + r0] = m0;
        lP[(size_t)blockIdx.x * 64 + r0] = l0;
        mP[(size_t)blockIdx.x * 64 + r1] = m1;
        lP[(size_t)blockIdx.x * 64 + r1] = l1;
    }
}

__global__ __launch_bounds__(256) void attention_combine(
    const float* __restrict__ accP, const float* __restrict__ mP,
    const float* __restrict__ lP, __half* __restrict__ Xg)
{
    __shared__ float sw[SPLIT][64];
    __shared__ float sden[64];
    const int bh = blockIdx.x;
    const int b = bh / H_, h = bh % H_;
    const int tid = threadIdx.x;

    if (tid < 64) {
        int r = tid;
        float M = -1e30f;
        #pragma unroll
        for (int s = 0; s < SPLIT; s++)
            M = fmaxf(M, mP[(size_t)(bh * SPLIT + s) * 64 + r]);
        float den = 0.f;
        #pragma unroll
        for (int s = 0; s < SPLIT; s++) {
            float w = __expf(mP[(size_t)(bh * SPLIT + s) * 64 + r] - M);
            sw[s][r] = w;
            den += w * lP[(size_t)(bh * SPLIT + s) * 64 + r];
        }
        sden[r] = den;
    }
    __syncthreads();

    for (int idx = tid; idx < 64 * 64; idx += 256) {
        int r = idx >> 6, d = idx & 63;
        float num = 0.f;
        #pragma unroll
        for (int s = 0; s < SPLIT; s++)
            num += sw[s][r] * accP[(size_t)(bh * SPLIT + s) * 4096 + idx];
        Xg[(size_t)(b * NQ + r) * CQ + h * D_ + d] = __float2half_rn(num / sden[r]);
    }
}

// ---------------------------------------------------------------------------
extern "C" void kernel_launch(void* const* d_in, const int* in_sizes, int n_in,
                              void* d_out, int out_size)
{
    const float* query = (const float*)d_in[0];
    const float* kv    = (const float*)d_in[1];
    const float* Wq    = (const float*)d_in[2];
    const float* bq    = (const float*)d_in[3];
    const float* Wk    = (const float*)d_in[4];
    const float* bk    = (const float*)d_in[5];
    const float* Wv    = (const float*)d_in[6];
    const float* bv    = (const float*)d_in[7];
    const float* Wo    = (const float*)d_in[8];
    const float* bo    = (const float*)d_in[9];
    float* out = (float*)d_out;

    float *accp, *mp, *lp;
    __half *qa, *qh, *xh, *kp, *vp, *kva, *wkt, *wvt, *wqth, *wqtl, *woth, *wotl;
    cudaGetSymbolAddress((void**)&qa, g_qa);
    cudaGetSymbolAddress((void**)&qh, g_qh);
    cudaGetSymbolAddress((void**)&xh, g_xh);
    cudaGetSymbolAddress((void**)&kp, g_kh);
    cudaGetSymbolAddress((void**)&vp, g_vh);
    cudaGetSymbolAddress((void**)&kva, g_kva);
    cudaGetSymbolAddress((void**)&wkt, g_wkt);
    cudaGetSymbolAddress((void**)&wvt, g_wvt);
    cudaGetSymbolAddress((void**)&wqth, g_wqth);
    cudaGetSymbolAddress((void**)&wqtl, g_wqtl);
    cudaGetSymbolAddress((void**)&woth, g_woth);
    cudaGetSymbolAddress((void**)&wotl, g_wotl);
    cudaGetSymbolAddress((void**)&accp, g_accP);
    cudaGetSymbolAddress((void**)&mp, g_mP);
    cudaGetSymbolAddress((void**)&lp, g_lP);

    cudaFuncSetAttribute(hgemm_f16,
                         cudaFuncAttributeMaxDynamicSharedMemorySize, HGEMM_SMEM);

    // 1. prep
    round_kernel<<<4096, 256>>>(kv, kva, (size_t)B_ * NKV * CKV / 4);
    round_kernel<<<384, 256>>>(query, qa, (size_t)B_ * NQ * CQ / 4);
    transpose_f16_tiled<<<dim3(CKV / 32, CQ / 32), 256>>>(Wk, wkt);
    transpose_f16_tiled<<<dim3(CKV / 32, CQ / 32), 256>>>(Wv, wvt);
    transpose_split768_tiled<<<dim3(CQ / 32, CQ / 32), 256>>>(Wq, wqth, wqtl);
    transpose_split768_tiled<<<dim3(CQ / 32, CQ / 32), 256>>>(Wo, woth, wotl);

    // 2. q projection (HMMA fp16x2, fp16 out)
    hgemm_qo<__half><<<dim3(CQ / 64, (B_ * NQ) / 64), 128>>>(qa, wqth, wqtl, bq, qh);

    // 3. K / V projections (HMMA fp16, fp16 out)
    dim3 ggrid(CQ / 128, (B_ * NKV) / 128);
    hgemm_f16<<<ggrid, 256, HGEMM_SMEM>>>(kva, wkt, bk, kp);
    hgemm_f16<<<ggrid, 256, HGEMM_SMEM>>>(kva, wvt, bv, vp);

    // 4. HMMA split-KV attention (double-buffered) + combine
    attention_hmma<<<B_ * H_ * SPLIT, 128>>>(qh, kp, vp, accp, mp, lp);
    attention_combine<<<B_ * H_, 256>>>(accp, mp, lp, xh);

    // 5. output projection (HMMA fp16x2, fp32 out)
    hgemm_qo<float><<<dim3(CQ / 64, (B_ * NQ) / 64), 128>>>(xh, woth, wotl, bo, out);
}

// round 10
// speedup vs baseline: 6.6811x; 1.0285x over previous
#include <cuda_runtime.h>
#include <cuda_bf16.h>
#include <cuda_fp16.h>
#include <math.h>
#include <stdint.h>

#define B_   16
#define NQ   64
#define NKV  4096
#define CQ   768
#define CKV  1024
#define H_   12
#define D_   64
#define SPLIT 8

// ---------------- scratch (device globals; allocation-free) ----------------
__device__ __half g_qa  [(size_t)B_ * NQ * CQ];
__device__ __half g_qh  [(size_t)B_ * NQ * CQ];
__device__ __half g_xh  [(size_t)B_ * NQ * CQ];
__device__ __half g_kh  [(size_t)B_ * NKV * CQ];
__device__ __half g_vh  [(size_t)B_ * NKV * CQ];
__device__ __half g_kva [(size_t)B_ * NKV * CKV];
__device__ __half g_wkvt[(size_t)2 * CQ * CKV];     // [Wk^T ; Wv^T] rows 0..1535
__device__ __half g_wqth[(size_t)CQ * CQ];
__device__ __half g_wqtl[(size_t)CQ * CQ];
__device__ __half g_woth[(size_t)CQ * CQ];
__device__ __half g_wotl[(size_t)CQ * CQ];
__device__ float g_accP[(size_t)B_ * H_ * SPLIT * NQ * D_];
__device__ float g_mP[(size_t)B_ * H_ * SPLIT * NQ];
__device__ float g_lP[(size_t)B_ * H_ * SPLIT * NQ];

// ---------------- helpers ----------------
__device__ __forceinline__ uint32_t smem_u32(const void* p) {
    uint32_t a;
    asm("{ .reg .u64 t; cvta.to.shared.u64 t, %1; cvt.u32.u64 %0, t; }"
        : "=r"(a) : "l"(p));
    return a;
}
__device__ __forceinline__ void cp16(uint32_t s, const void* g) {
    asm volatile("cp.async.cg.shared.global [%0], [%1], 16;\n"
                 :: "r"(s), "l"(__cvta_generic_to_global(g)) : "memory");
}
#define CP_COMMIT() asm volatile("cp.async.commit_group;\n" ::: "memory")
#define CP_WAIT(n)  asm volatile("cp.async.wait_group %0;\n" :: "n"(n) : "memory")

__device__ __forceinline__ void ldsm_x4(uint32_t addr, uint32_t& r0, uint32_t& r1,
                                        uint32_t& r2, uint32_t& r3) {
    asm volatile("ldmatrix.sync.aligned.m8n8.x4.shared.b16 {%0,%1,%2,%3}, [%4];"
                 : "=r"(r0), "=r"(r1), "=r"(r2), "=r"(r3) : "r"(addr));
}
__device__ __forceinline__ void ldsm_x4_t(uint32_t addr, uint32_t& r0, uint32_t& r1,
                                          uint32_t& r2, uint32_t& r3) {
    asm volatile("ldmatrix.sync.aligned.m8n8.x4.trans.shared.b16 {%0,%1,%2,%3}, [%4];"
                 : "=r"(r0), "=r"(r1), "=r"(r2), "=r"(r3) : "r"(addr));
}
__device__ __forceinline__ void mma_f16(float* d, uint32_t a0, uint32_t a1,
                                        uint32_t a2, uint32_t a3,
                                        uint32_t b0, uint32_t b1) {
    asm volatile(
        "mma.sync.aligned.m16n8k16.row.col.f32.f16.f16.f32 "
        "{%0,%1,%2,%3}, {%4,%5,%6,%7}, {%8,%9}, {%0,%1,%2,%3};"
        : "+f"(d[0]), "+f"(d[1]), "+f"(d[2]), "+f"(d[3])
        : "r"(a0), "r"(a1), "r"(a2), "r"(a3), "r"(b0), "r"(b1));
}
__device__ __forceinline__ uint32_t pack_h2(float a, float b) {
    __half2 h = __floats2half2_rn(a, b);
    return *(uint32_t*)&h;
}
__device__ __forceinline__ void st2(float* p, float a, float b) {
    float2 v = { a, b }; *(float2*)p = v;
}
__device__ __forceinline__ void st2(__half* p, float a, float b) {
    *(uint32_t*)p = pack_h2(a, b);
}

// ---------------------------------------------------------------------------
// prep kernels
// ---------------------------------------------------------------------------
__global__ __launch_bounds__(256) void round_kernel(
    const float* __restrict__ src, __half* __restrict__ dst, size_t n4)
{
    size_t i = ((size_t)blockIdx.x * blockDim.x + threadIdx.x) * 2;
    size_t stride = (size_t)gridDim.x * blockDim.x * 2;
    for (; i < n4; i += stride) {
        float4 x = ((const float4*)src)[i];
        float4 y = ((const float4*)src)[i + 1];
        ((__half2*)dst)[i * 2]     = __floats2half2_rn(x.x, x.y);
        ((__half2*)dst)[i * 2 + 1] = __floats2half2_rn(x.z, x.w);
        ((__half2*)dst)[i * 2 + 2] = __floats2half2_rn(y.x, y.y);
        ((__half2*)dst)[i * 2 + 3] = __floats2half2_rn(y.z, y.w);
    }
}

// W [K=1024][N=768] -> th [768][1024] fp16, tiled coalesced
__global__ __launch_bounds__(256) void transpose_f16_tiled(
    const float* __restrict__ W, __half* __restrict__ th)
{
    __shared__ float t[32][33];
    const int kb = blockIdx.x * 32, nb = blockIdx.y * 32;
    const int tx = threadIdx.x & 31, ty = threadIdx.x >> 5;
    #pragma unroll
    for (int i = ty; i < 32; i += 8)
        t[i][tx] = W[(size_t)(kb + i) * CQ + nb + tx];
    __syncthreads();
    #pragma unroll
    for (int i = ty; i < 32; i += 8)
        th[(size_t)(nb + i) * CKV + kb + tx] = __float2half_rn(t[tx][i]);
}

// W [768][768] -> Wt hi/lo [768][768], tiled coalesced
__global__ __launch_bounds__(256) void transpose_split768_tiled(
    const float* __restrict__ W, __half* __restrict__ th, __half* __restrict__ tl)
{
    __shared__ float t[32][33];
    const int kb = blockIdx.x * 32, nb = blockIdx.y * 32;
    const int tx = threadIdx.x & 31, ty = threadIdx.x >> 5;
    #pragma unroll
    for (int i = ty; i < 32; i += 8)
        t[i][tx] = W[(size_t)(kb + i) * CQ + nb + tx];
    __syncthreads();
    #pragma unroll
    for (int i = ty; i < 32; i += 8) {
        float x = t[tx][i];
        __half h = __float2half_rn(x);
        th[(size_t)(nb + i) * CQ + kb + tx] = h;
        tl[(size_t)(nb + i) * CQ + kb + tx] = __float2half_rn(x - __half2float(h));
    }
}

// ---------------------------------------------------------------------------
// Fused K+V HMMA fp16 GEMM: [K|V] = A16 [Wk^T;Wv^T]_rows + bias, fp16 out.
// B has 1536 rows; n-blocks 0..5 -> K output, 6..11 -> V output.
// CTA 128x128x32, 8 warps, 3-stage cp.async, occupancy 2.
// ---------------------------------------------------------------------------
#define LDS_E 40
#define TILE_B (128 * LDS_E * 2)
#define STAGE_B (2 * TILE_B)
#define STAGES 3
#define HGEMM_SMEM (STAGES * STAGE_B)
#define KT_N (CKV / 32)

__global__ __launch_bounds__(256, 2) void hgemm_kv(
    const __half* __restrict__ A_g, const __half* __restrict__ Bkv,
    const float* __restrict__ bk, const float* __restrict__ bv,
    __half* __restrict__ Kout, __half* __restrict__ Vout)
{
    extern __shared__ char smem[];
    const uint32_t sbase = smem_u32(smem);
    const int tid = threadIdx.x;
    const int wid = tid >> 5, lane = tid & 31;
    const int wm = (wid & 1) * 64;
    const int wn = (wid >> 1) * 32;
    const int m0 = blockIdx.y * 128, n0 = blockIdx.x * 128;

    const int lr = tid >> 1;
    const int lc = (tid & 1) * 16;
    const uint32_t s_off = (uint32_t)(lr * 80 + (tid & 1) * 32);

    const __half* gA = A_g + (size_t)(m0 + lr) * CKV + lc;
    const __half* gB = Bkv + (size_t)(n0 + lr) * CKV + lc;

    const int a_row = lane & 15;
    const int a_ko  = ((lane >> 4) & 1) * 8;
    const int b_row = (lane & 7) + ((lane >> 4) & 1) * 8;
    const int b_ko  = ((lane >> 3) & 1) * 8;

    float acc[4][4][4];
    #pragma unroll
    for (int i = 0; i < 4; i++)
        #pragma unroll
        for (int j = 0; j < 4; j++)
            #pragma unroll
            for (int c = 0; c < 4; c++) acc[i][j][c] = 0.f;

    auto load_stage = [&](int kt, int s) {
        const uint32_t sb = sbase + s * STAGE_B;
        const int ke = kt * 32;
        cp16(sb + s_off,               gA + ke);
        cp16(sb + s_off + 16,          gA + ke + 8);
        cp16(sb + TILE_B + s_off,      gB + ke);
        cp16(sb + TILE_B + s_off + 16, gB + ke + 8);
    };

    load_stage(0, 0); CP_COMMIT();
    load_stage(1, 1); CP_COMMIT();

    for (int kt = 0; kt < KT_N; kt++) {
        CP_WAIT(1);
        __syncthreads();

        const int nkt = kt + STAGES - 1;
        if (nkt < KT_N) load_stage(nkt, nkt % STAGES);
        CP_COMMIT();

        const uint32_t sb = sbase + (kt % STAGES) * STAGE_B;
        #pragma unroll
        for (int kb = 0; kb < 32; kb += 16) {
            uint32_t ah[4][4];
            #pragma unroll
            for (int mt = 0; mt < 4; mt++) {
                uint32_t ra = sb + (uint32_t)((wm + mt * 16 + a_row) * 80 + (a_ko + kb) * 2);
                ldsm_x4(ra, ah[mt][0], ah[mt][1], ah[mt][2], ah[mt][3]);
            }
            uint32_t bh[4][2];
            #pragma unroll
            for (int np = 0; np < 2; np++) {
                uint32_t rb = sb + TILE_B +
                              (uint32_t)((wn + np * 16 + b_row) * 80 + (b_ko + kb) * 2);
                ldsm_x4(rb, bh[np * 2][0], bh[np * 2][1], bh[np * 2 + 1][0], bh[np * 2 + 1][1]);
            }
            #pragma unroll
            for (int mt = 0; mt < 4; mt++)
                #pragma unroll
                for (int nt = 0; nt < 4; nt++)
                    mma_f16(acc[mt][nt], ah[mt][0], ah[mt][1], ah[mt][2], ah[mt][3],
                            bh[nt][0], bh[nt][1]);
        }
    }

    // route to K or V output
    const bool isV = (n0 >= CQ);
    const float* bias = isV ? bv : bk;
    __half* C = isV ? Vout : Kout;
    const int nc0 = isV ? (n0 - CQ) : n0;

    const int er = lane >> 2, ec = (lane & 3) * 2;
    #pragma unroll
    for (int mt = 0; mt < 4; mt++) {
        #pragma unroll
        for (int nt = 0; nt < 4; nt++) {
            const int col = nc0 + wn + nt * 8 + ec;
            const float b0 = bias[col], b1 = bias[col + 1];
            __half* p0 = C + (size_t)(m0 + wm + mt * 16 + er) * CQ + col;
            __half* p1 = p0 + 8 * CQ;
            st2(p0, acc[mt][nt][0] + b0, acc[mt][nt][1] + b1);
            st2(p1, acc[mt][nt][2] + b0, acc[mt][nt][3] + b1);
        }
    }
}

// ---------------------------------------------------------------------------
// Small HMMA fp16x2 GEMM (Q / O projections)
// ---------------------------------------------------------------------------
#define QO_TILE_B 5120
#define QO_STAGE_B (3 * QO_TILE_B)
#define QO_STAGES 3
#define QO_KT (CQ / 32)

template <typename OutT>
__global__ __launch_bounds__(128) void hgemm_qo(
    const __half* __restrict__ A_g, const __half* __restrict__ Bh_g,
    const __half* __restrict__ Bl_g, const float* __restrict__ bias,
    OutT* __restrict__ C)
{
    __shared__ char smem[QO_STAGES * QO_STAGE_B];
    const uint32_t sbase = smem_u32(smem);
    const int tid = threadIdx.x;
    const int wid = tid >> 5, lane = tid & 31;
    const int wm = (wid & 1) * 32;
    const int wn = (wid >> 1) * 32;
    const int m0 = blockIdx.y * 64, n0 = blockIdx.x * 64;

    const int lr = tid >> 1;
    const int lc = (tid & 1) * 16;
    const uint32_t s_off = (uint32_t)(lr * 80 + (tid & 1) * 32);

    const __half* gA  = A_g  + (size_t)(m0 + lr) * CQ + lc;
    const __half* gBh = Bh_g + (size_t)(n0 + lr) * CQ + lc;
    const __half* gBl = Bl_g + (size_t)(n0 + lr) * CQ + lc;

    const int a_row = lane & 15;
    const int a_ko  = ((lane >> 4) & 1) * 8;
    const int b_row = (lane & 7) + ((lane >> 4) & 1) * 8;
    const int b_ko  = ((lane >> 3) & 1) * 8;

    float acc[2][4][4];
    #pragma unroll
    for (int i = 0; i < 2; i++)
        #pragma unroll
        for (int j = 0; j < 4; j++)
            #pragma unroll
            for (int c = 0; c < 4; c++) acc[i][j][c] = 0.f;

    auto load_stage = [&](int kt, int s) {
        const uint32_t sb = sbase + s * QO_STAGE_B;
        const int ke = kt * 32;
        cp16(sb + s_off,                    gA  + ke);
        cp16(sb + s_off + 16,               gA  + ke + 8);
        cp16(sb + QO_TILE_B + s_off,        gBh + ke);
        cp16(sb + QO_TILE_B + s_off + 16,   gBh + ke + 8);
        cp16(sb + 2*QO_TILE_B + s_off,      gBl + ke);
        cp16(sb + 2*QO_TILE_B + s_off + 16, gBl + ke + 8);
    };

    load_stage(0, 0); CP_COMMIT();
    load_stage(1, 1); CP_COMMIT();

    for (int kt = 0; kt < QO_KT; kt++) {
        CP_WAIT(1);
        __syncthreads();

        const int nkt = kt + QO_STAGES - 1;
        if (nkt < QO_KT) load_stage(nkt, nkt % QO_STAGES);
        CP_COMMIT();

        const uint32_t sb = sbase + (kt % QO_STAGES) * QO_STAGE_B;
        #pragma unroll
        for (int kb = 0; kb < 32; kb += 16) {
            uint32_t a[2][4];
            #pragma unroll
            for (int mt = 0; mt < 2; mt++) {
                uint32_t ra = sb + (uint32_t)((wm + mt * 16 + a_row) * 80 + (a_ko + kb) * 2);
                ldsm_x4(ra, a[mt][0], a[mt][1], a[mt][2], a[mt][3]);
            }
            uint32_t bh[4][2], bl[4][2];
            #pragma unroll
            for (int ng = 0; ng < 2; ng++) {
                uint32_t rbh = sb + QO_TILE_B +
                               (uint32_t)((wn + ng * 16 + b_row) * 80 + (b_ko + kb) * 2);
                ldsm_x4(rbh, bh[2*ng][0], bh[2*ng][1], bh[2*ng+1][0], bh[2*ng+1][1]);
                ldsm_x4(rbh + QO_TILE_B, bl[2*ng][0], bl[2*ng][1], bl[2*ng+1][0], bl[2*ng+1][1]);
            }
            #pragma unroll
            for (int mt = 0; mt < 2; mt++)
                #pragma unroll
                for (int nt = 0; nt < 4; nt++) {
                    mma_f16(acc[mt][nt], a[mt][0], a[mt][1], a[mt][2], a[mt][3],
                            bh[nt][0], bh[nt][1]);
                    mma_f16(acc[mt][nt], a[mt][0], a[mt][1], a[mt][2], a[mt][3],
                            bl[nt][0], bl[nt][1]);
                }
        }
    }

    const int er = lane >> 2, ec = (lane & 3) * 2;
    #pragma unroll
    for (int mt = 0; mt < 2; mt++) {
        #pragma unroll
        for (int nt = 0; nt < 4; nt++) {
            const int col = n0 + wn + nt * 8 + ec;
            const float b0 = bias[col], b1 = bias[col + 1];
            OutT* p0 = C + (size_t)(m0 + wm + mt * 16 + er) * CQ + col;
            OutT* p1 = p0 + 8 * CQ;
            st2(p0, acc[mt][nt][0] + b0, acc[mt][nt][1] + b1);
            st2(p1, acc[mt][nt][2] + b0, acc[mt][nt][3] + b1);
        }
    }
}

// ---------------------------------------------------------------------------
// HMMA split-KV flash attention partial, double-buffered K/V chunks
// ---------------------------------------------------------------------------
#define KV_PER_SPLIT (NKV / SPLIT)
#define N_CHUNKS (KV_PER_SPLIT / 64)

__global__ __launch_bounds__(128) void attention_hmma(
    const __half* __restrict__ Qg, const __half* __restrict__ Kg,
    const __half* __restrict__ Vg,
    float* __restrict__ accP, float* __restrict__ mP, float* __restrict__ lP)
{
    __shared__ __half Qs[64][72];
    __shared__ __half Ks[2][64][72];
    __shared__ __half Vs[2][64][72];

    const int bh = blockIdx.x / SPLIT;
    const int sp = blockIdx.x % SPLIT;
    const int b = bh / H_, h = bh % H_;
    const int tid = threadIdx.x;
    const int w = tid >> 5, lane = tid & 31;
    const int kv_lo = sp * KV_PER_SPLIT;

    auto load_chunk = [&](int c, int buf) {
        const int kv0 = kv_lo + c * 64;
        #pragma unroll
        for (int idx = tid; idx < 512; idx += 128) {
            int r = idx >> 3, sg = idx & 7;
            size_t gofs = (size_t)(b * NKV + kv0 + r) * CQ + h * D_ + sg * 8;
            cp16(smem_u32(&Ks[buf][r][sg * 8]), Kg + gofs);
            cp16(smem_u32(&Vs[buf][r][sg * 8]), Vg + gofs);
        }
        CP_COMMIT();
    };

    load_chunk(0, 0);

    {
        const __half2 sc = __floats2half2_rn(0.125f, 0.125f);
        for (int idx = tid; idx < 512; idx += 128) {
            int r = idx >> 3, c8 = (idx & 7) * 8;
            uint4 v = *(const uint4*)(Qg + (size_t)(b * NQ + r) * CQ + h * D_ + c8);
            __half2* s = (__half2*)&v;
            __half2* d = (__half2*)&Qs[r][c8];
            d[0] = __hmul2(s[0], sc); d[1] = __hmul2(s[1], sc);
            d[2] = __hmul2(s[2], sc); d[3] = __hmul2(s[3], sc);
        }
    }

    const int qa_row = lane & 15;
    const int qa_ko  = ((lane >> 4) & 1) * 8;
    const int kb_row = (lane & 7) + ((lane >> 4) & 1) * 8;
    const int kb_ko  = ((lane >> 3) & 1) * 8;
    const int vt_row = (lane & 7) + ((lane >> 3) & 1) * 8;
    const int vt_co  = ((lane >> 4) & 1) * 8;

    float m0 = -1e30f, m1 = -1e30f, l0 = 0.f, l1 = 0.f;
    float o[8][4];
    #pragma unroll
    for (int i = 0; i < 8; i++)
        #pragma unroll
        for (int j = 0; j < 4; j++) o[i][j] = 0.f;

    for (int c = 0; c < N_CHUNKS; c++) {
        const int cur = c & 1;
        if (c + 1 < N_CHUNKS) { load_chunk(c + 1, cur ^ 1); CP_WAIT(1); }
        else                  { CP_WAIT(0); }
        __syncthreads();

        float s[8][4];
        #pragma unroll
        for (int i = 0; i < 8; i++)
            #pragma unroll
            for (int j = 0; j < 4; j++) s[i][j] = 0.f;

        #pragma unroll
        for (int kk = 0; kk < 4; kk++) {
            uint32_t a0, a1, a2, a3;
            ldsm_x4(smem_u32(&Qs[w * 16 + qa_row][kk * 16 + qa_ko]), a0, a1, a2, a3);
            #pragma unroll
            for (int ng = 0; ng < 4; ng++) {
                uint32_t b0, b1, b2, b3;
                ldsm_x4(smem_u32(&Ks[cur][ng * 16 + kb_row][kk * 16 + kb_ko]),
                        b0, b1, b2, b3);
                mma_f16(s[2 * ng],     a0, a1, a2, a3, b0, b1);
                mma_f16(s[2 * ng + 1], a0, a1, a2, a3, b2, b3);
            }
        }

        float mx0 = -1e30f, mx1 = -1e30f;
        #pragma unroll
        for (int nt = 0; nt < 8; nt++) {
            mx0 = fmaxf(mx0, fmaxf(s[nt][0], s[nt][1]));
            mx1 = fmaxf(mx1, fmaxf(s[nt][2], s[nt][3]));
        }
        #pragma unroll
        for (int ofs = 1; ofs < 4; ofs <<= 1) {
            mx0 = fmaxf(mx0, __shfl_xor_sync(0xffffffffu, mx0, ofs));
            mx1 = fmaxf(mx1, __shfl_xor_sync(0xffffffffu, mx1, ofs));
        }
        float M0 = fmaxf(m0, mx0), M1 = fmaxf(m1, mx1);
        float c0 = __expf(m0 - M0), c1 = __expf(m1 - M1);
        float ls0 = 0.f, ls1 = 0.f;
        #pragma unroll
        for (int nt = 0; nt < 8; nt++) {
            s[nt][0] = __expf(s[nt][0] - M0); ls0 += s[nt][0];
            s[nt][1] = __expf(s[nt][1] - M0); ls0 += s[nt][1];
            s[nt][2] = __expf(s[nt][2] - M1); ls1 += s[nt][2];
            s[nt][3] = __expf(s[nt][3] - M1); ls1 += s[nt][3];
        }
        #pragma unroll
        for (int ofs = 1; ofs < 4; ofs <<= 1) {
            ls0 += __shfl_xor_sync(0xffffffffu, ls0, ofs);
            ls1 += __shfl_xor_sync(0xffffffffu, ls1, ofs);
        }
        l0 = l0 * c0 + ls0;  l1 = l1 * c1 + ls1;
        m0 = M0;  m1 = M1;
        #pragma unroll
        for (int nt = 0; nt < 8; nt++) {
            o[nt][0] *= c0; o[nt][1] *= c0;
            o[nt][2] *= c1; o[nt][3] *= c1;
        }

        uint32_t pu[8][2];
        #pragma unroll
        for (int nt = 0; nt < 8; nt++) {
            pu[nt][0] = pack_h2(s[nt][0], s[nt][1]);
            pu[nt][1] = pack_h2(s[nt][2], s[nt][3]);
        }

        #pragma unroll
        for (int t = 0; t < 4; t++) {
            uint32_t a0 = pu[2 * t][0],     a1 = pu[2 * t][1];
            uint32_t a2 = pu[2 * t + 1][0], a3 = pu[2 * t + 1][1];
            #pragma unroll
            for (int dg = 0; dg < 4; dg++) {
                uint32_t b0, b1, b2, b3;
                ldsm_x4_t(smem_u32(&Vs[cur][t * 16 + vt_row][dg * 16 + vt_co]),
                          b0, b1, b2, b3);
                mma_f16(o[2 * dg],     a0, a1, a2, a3, b0, b1);
                mma_f16(o[2 * dg + 1], a0, a1, a2, a3, b2, b3);
            }
        }
        __syncthreads();
    }

    float* accp = accP + (size_t)blockIdx.x * 64 * 64;
    const int r0 = w * 16 + (lane >> 2), r1 = r0 + 8;
    const int cb = (lane & 3) * 2;
    #pragma unroll
    for (int nt = 0; nt < 8; nt++) {
        st2(&accp[r0 * 64 + nt * 8 + cb], o[nt][0], o[nt][1]);
        st2(&accp[r1 * 64 + nt * 8 + cb], o[nt][2], o[nt][3]);
    }
    if ((lane & 3) == 0) {
        mP[(size_t)blockIdx.x * 64 + r0] = m0;
        lP[(size_t)blockIdx.x * 64 + r0] = l0;
        mP[(size_t)blockIdx.x * 64 + r1] = m1;
        lP[(size_t)blockIdx.x * 64 + r1] = l1;
    }
}

__global__ __launch_bounds__(256) void attention_combine(
    const float* __restrict__ accP, const float* __restrict__ mP,
    const float* __restrict__ lP, __half* __restrict__ Xg)
{
    __shared__ float sw[SPLIT][64];
    __shared__ float sden[64];
    const int bh = blockIdx.x;
    const int b = bh / H_, h = bh % H_;
    const int tid = threadIdx.x;

    if (tid < 64) {
        int r = tid;
        float M = -1e30f;
        #pragma unroll
        for (int s = 0; s < SPLIT; s++)
            M = fmaxf(M, mP[(size_t)(bh * SPLIT + s) * 64 + r]);
        float den = 0.f;
        #pragma unroll
        for (int s = 0; s < SPLIT; s++) {
            float w = __expf(mP[(size_t)(bh * SPLIT + s) * 64 + r] - M);
            sw[s][r] = w;
            den += w * lP[(size_t)(bh * SPLIT + s) * 64 + r];
        }
        sden[r] = den;
    }
    __syncthreads();

    for (int idx = tid; idx < 64 * 64; idx += 256) {
        int r = idx >> 6, d = idx & 63;
        float num = 0.f;
        #pragma unroll
        for (int s = 0; s < SPLIT; s++)
            num += sw[s][r] * accP[(size_t)(bh * SPLIT + s) * 4096 + idx];
        Xg[(size_t)(b * NQ + r) * CQ + h * D_ + d] = __float2half_rn(num / sden[r]);
    }
}

// ---------------------------------------------------------------------------
extern "C" void kernel_launch(void* const* d_in, const int* in_sizes, int n_in,
                              void* d_out, int out_size)
{
    const float* query = (const float*)d_in[0];
    const float* kv    = (const float*)d_in[1];
    const float* Wq    = (const float*)d_in[2];
    const float* bq    = (const float*)d_in[3];
    const float* Wk    = (const float*)d_in[4];
    const float* bk    = (const float*)d_in[5];
    const float* Wv    = (const float*)d_in[6];
    const float* bv    = (const float*)d_in[7];
    const float* Wo    = (const float*)d_in[8];
    const float* bo    = (const float*)d_in[9];
    float* out = (float*)d_out;

    float *accp, *mp, *lp;
    __half *qa, *qh, *xh, *kp, *vp, *kva, *wkvt, *wqth, *wqtl, *woth, *wotl;
    cudaGetSymbolAddress((void**)&qa, g_qa);
    cudaGetSymbolAddress((void**)&qh, g_qh);
    cudaGetSymbolAddress((void**)&xh, g_xh);
    cudaGetSymbolAddress((void**)&kp, g_kh);
    cudaGetSymbolAddress((void**)&vp, g_vh);
    cudaGetSymbolAddress((void**)&kva, g_kva);
    cudaGetSymbolAddress((void**)&wkvt, g_wkvt);
    cudaGetSymbolAddress((void**)&wqth, g_wqth);
    cudaGetSymbolAddress((void**)&wqtl, g_wqtl);
    cudaGetSymbolAddress((void**)&woth, g_woth);
    cudaGetSymbolAddress((void**)&wotl, g_wotl);
    cudaGetSymbolAddress((void**)&accp, g_accP);
    cudaGetSymbolAddress((void**)&mp, g_mP);
    cudaGetSymbolAddress((void**)&lp, g_lP);

    cudaFuncSetAttribute(hgemm_kv,
                         cudaFuncAttributeMaxDynamicSharedMemorySize, HGEMM_SMEM);

    // fork a side stream into the capture (event-linked; created fresh each
    // capture call — host-side objects only, no device allocation)
    cudaStream_t s2;
    cudaStreamCreateWithFlags(&s2, cudaStreamNonBlocking);
    cudaEvent_t eFork, eW, eJoin;
    cudaEventCreateWithFlags(&eFork, cudaEventDisableTiming);
    cudaEventCreateWithFlags(&eW, cudaEventDisableTiming);
    cudaEventCreateWithFlags(&eJoin, cudaEventDisableTiming);

    cudaEventRecord(eFork, 0);
    cudaStreamWaitEvent(s2, eFork, 0);

    // main stream: kv rounding (producer of the big GEMM)
    round_kernel<<<4096, 256>>>(kv, kva, (size_t)B_ * NKV * CKV / 4);

    // side stream: weight transposes + q path (independent of kv)
    transpose_f16_tiled<<<dim3(CKV / 32, CQ / 32), 256, 0, s2>>>(Wk, wkvt);
    transpose_f16_tiled<<<dim3(CKV / 32, CQ / 32), 256, 0, s2>>>(Wv, wkvt + (size_t)CQ * CKV);
    cudaEventRecord(eW, s2);   // GEMM dependency satisfied here
    round_kernel<<<384, 256, 0, s2>>>(query, qa, (size_t)B_ * NQ * CQ / 4);
    transpose_split768_tiled<<<dim3(CQ / 32, CQ / 32), 256, 0, s2>>>(Wq, wqth, wqtl);
    transpose_split768_tiled<<<dim3(CQ / 32, CQ / 32), 256, 0, s2>>>(Wo, woth, wotl);
    hgemm_qo<__half><<<dim3(CQ / 64, (B_ * NQ) / 64), 128, 0, s2>>>(qa, wqth, wqtl, bq, qh);
    cudaEventRecord(eJoin, s2);

    // main stream: fused K+V projection (waits for weight transposes)
    cudaStreamWaitEvent(0, eW, 0);
    hgemm_kv<<<dim3(2 * CQ / 128, (B_ * NKV) / 128), 256, HGEMM_SMEM>>>(
        kva, wkvt, bk, bv, kp, vp);

    // join q path, then attention + combine + output projection
    cudaStreamWaitEvent(0, eJoin, 0);
    attention_hmma<<<B_ * H_ * SPLIT, 128>>>(qh, kp, vp, accp, mp, lp);
    attention_combine<<<B_ * H_, 256>>>(accp, mp, lp, xh);
    hgemm_qo<float><<<dim3(CQ / 64, (B_ * NQ) / 64), 128>>>(xh, woth, wotl, bo, out);

    cudaEventDestroy(eFork);
    cudaEventDestroy(eW);
    cudaEventDestroy(eJoin);
    cudaStreamDestroy(s2);
}

// round 12
// speedup vs baseline: 7.3645x; 1.1023x over previous
#include <cuda_runtime.h>
#include <cuda_bf16.h>
#include <cuda_fp16.h>
#include <math.h>
#include <stdint.h>

#define B_   16
#define NQ   64
#define NKV  4096
#define CQ   768
#define CKV  1024
#define H_   12
#define D_   64
#define SPLIT 8

// ---------------- scratch (device globals; allocation-free) ----------------
__device__ __half g_qa  [(size_t)B_ * NQ * CQ];
__device__ __half g_qh  [(size_t)B_ * NQ * CQ];
__device__ __half g_xh  [(size_t)B_ * NQ * CQ];
__device__ __half g_kh  [(size_t)B_ * NKV * CQ];
__device__ __half g_vh  [(size_t)B_ * NKV * CQ];
__device__ __half g_kva [(size_t)B_ * NKV * CKV];
__device__ __half g_wkvt[(size_t)2 * CQ * CKV];
__device__ __half g_wqth[(size_t)CQ * CQ];
__device__ __half g_wqtl[(size_t)CQ * CQ];
__device__ __half g_woth[(size_t)CQ * CQ];
__device__ __half g_wotl[(size_t)CQ * CQ];
__device__ float g_accP[(size_t)B_ * H_ * SPLIT * NQ * D_];
__device__ float g_mP[(size_t)B_ * H_ * SPLIT * NQ];
__device__ float g_lP[(size_t)B_ * H_ * SPLIT * NQ];

// ---------------- helpers ----------------
__device__ __forceinline__ uint32_t smem_u32(const void* p) {
    uint32_t a;
    asm("{ .reg .u64 t; cvta.to.shared.u64 t, %1; cvt.u32.u64 %0, t; }"
        : "=r"(a) : "l"(p));
    return a;
}
__device__ __forceinline__ void cp16(uint32_t s, const void* g) {
    asm volatile("cp.async.cg.shared.global [%0], [%1], 16;\n"
                 :: "r"(s), "l"(__cvta_generic_to_global(g)) : "memory");
}
#define CP_COMMIT() asm volatile("cp.async.commit_group;\n" ::: "memory")
#define CP_WAIT(n)  asm volatile("cp.async.wait_group %0;\n" :: "n"(n) : "memory")

__device__ __forceinline__ void ldsm_x4(uint32_t addr, uint32_t& r0, uint32_t& r1,
                                        uint32_t& r2, uint32_t& r3) {
    asm volatile("ldmatrix.sync.aligned.m8n8.x4.shared.b16 {%0,%1,%2,%3}, [%4];"
                 : "=r"(r0), "=r"(r1), "=r"(r2), "=r"(r3) : "r"(addr));
}
__device__ __forceinline__ void ldsm_x4_t(uint32_t addr, uint32_t& r0, uint32_t& r1,
                                          uint32_t& r2, uint32_t& r3) {
    asm volatile("ldmatrix.sync.aligned.m8n8.x4.trans.shared.b16 {%0,%1,%2,%3}, [%4];"
                 : "=r"(r0), "=r"(r1), "=r"(r2), "=r"(r3) : "r"(addr));
}
__device__ __forceinline__ void mma_f16(float* d, uint32_t a0, uint32_t a1,
                                        uint32_t a2, uint32_t a3,
                                        uint32_t b0, uint32_t b1) {
    asm volatile(
        "mma.sync.aligned.m16n8k16.row.col.f32.f16.f16.f32 "
        "{%0,%1,%2,%3}, {%4,%5,%6,%7}, {%8,%9}, {%0,%1,%2,%3};"
        : "+f"(d[0]), "+f"(d[1]), "+f"(d[2]), "+f"(d[3])
        : "r"(a0), "r"(a1), "r"(a2), "r"(a3), "r"(b0), "r"(b1));
}
__device__ __forceinline__ uint32_t pack_h2(float a, float b) {
    __half2 h = __floats2half2_rn(a, b);
    return *(uint32_t*)&h;
}
__device__ __forceinline__ void st2(float* p, float a, float b) {
    float2 v = { a, b }; *(float2*)p = v;
}
__device__ __forceinline__ void st2(__half* p, float a, float b) {
    *(uint32_t*)p = pack_h2(a, b);
}

// ---------------------------------------------------------------------------
// prep kernels
// ---------------------------------------------------------------------------
__global__ __launch_bounds__(256) void round_kernel(
    const float* __restrict__ src, __half* __restrict__ dst, size_t n4)
{
    size_t i = ((size_t)blockIdx.x * blockDim.x + threadIdx.x) * 2;
    size_t stride = (size_t)gridDim.x * blockDim.x * 2;
    for (; i < n4; i += stride) {
        float4 x = ((const float4*)src)[i];
        float4 y = ((const float4*)src)[i + 1];
        ((__half2*)dst)[i * 2]     = __floats2half2_rn(x.x, x.y);
        ((__half2*)dst)[i * 2 + 1] = __floats2half2_rn(x.z, x.w);
        ((__half2*)dst)[i * 2 + 2] = __floats2half2_rn(y.x, y.y);
        ((__half2*)dst)[i * 2 + 3] = __floats2half2_rn(y.z, y.w);
    }
}

__global__ __launch_bounds__(256) void transpose_f16_tiled(
    const float* __restrict__ W, __half* __restrict__ th)
{
    __shared__ float t[32][33];
    const int kb = blockIdx.x * 32, nb = blockIdx.y * 32;
    const int tx = threadIdx.x & 31, ty = threadIdx.x >> 5;
    #pragma unroll
    for (int i = ty; i < 32; i += 8)
        t[i][tx] = W[(size_t)(kb + i) * CQ + nb + tx];
    __syncthreads();
    #pragma unroll
    for (int i = ty; i < 32; i += 8)
        th[(size_t)(nb + i) * CKV + kb + tx] = __float2half_rn(t[tx][i]);
}

__global__ __launch_bounds__(256) void transpose_split768_tiled(
    const float* __restrict__ W, __half* __restrict__ th, __half* __restrict__ tl)
{
    __shared__ float t[32][33];
    const int kb = blockIdx.x * 32, nb = blockIdx.y * 32;
    const int tx = threadIdx.x & 31, ty = threadIdx.x >> 5;
    #pragma unroll
    for (int i = ty; i < 32; i += 8)
        t[i][tx] = W[(size_t)(kb + i) * CQ + nb + tx];
    __syncthreads();
    #pragma unroll
    for (int i = ty; i < 32; i += 8) {
        float x = t[tx][i];
        __half h = __float2half_rn(x);
        th[(size_t)(nb + i) * CQ + kb + tx] = h;
        tl[(size_t)(nb + i) * CQ + kb + tx] = __float2half_rn(x - __half2float(h));
    }
}

// ---------------------------------------------------------------------------
// Fused K+V HMMA fp16 GEMM, k-chunk 64: [K|V] = A16 [Wk^T;Wv^T] + bias.
// CTA 128x128x64, 8 warps, 3-stage cp.async, occupancy 2.
// Row stride 144 B (16B pad): ldmatrix conflict-free (144 mod 128 = 16).
// ---------------------------------------------------------------------------
#define GR_STRIDE 144
#define TILE_B (128 * GR_STRIDE)      // 18432
#define STAGE_B (2 * TILE_B)          // 36864
#define STAGES 3
#define HGEMM_SMEM (STAGES * STAGE_B) // 110592
#define KT_N (CKV / 64)               // 16

__global__ __launch_bounds__(256, 2) void hgemm_kv(
    const __half* __restrict__ A_g, const __half* __restrict__ Bkv,
    const float* __restrict__ bk, const float* __restrict__ bv,
    __half* __restrict__ Kout, __half* __restrict__ Vout)
{
    extern __shared__ char smem[];
    const uint32_t sbase = smem_u32(smem);
    const int tid = threadIdx.x;
    const int wid = tid >> 5, lane = tid & 31;
    const int wm = (wid & 1) * 64;
    const int wn = (wid >> 1) * 32;
    const int m0 = blockIdx.y * 128, n0 = blockIdx.x * 128;

    // loader mapping: 8 x 16B segments per 128B row chunk; 4 row-steps per thread
    const int l_row = tid >> 3;          // rows 0..31 (x4 j-steps -> 0..127)
    const int l_c16 = tid & 7;
    const uint32_t l_soff = (uint32_t)(l_row * GR_STRIDE + l_c16 * 16);

    const int a_row = lane & 15;
    const int a_ko  = ((lane >> 4) & 1) * 8;
    const int b_row = (lane & 7) + ((lane >> 4) & 1) * 8;
    const int b_ko  = ((lane >> 3) & 1) * 8;

    float acc[4][4][4];
    #pragma unroll
    for (int i = 0; i < 4; i++)
        #pragma unroll
        for (int j = 0; j < 4; j++)
            #pragma unroll
            for (int c = 0; c < 4; c++) acc[i][j][c] = 0.f;

    auto load_stage = [&](int kt, int s) {
        const uint32_t sb = sbase + s * STAGE_B;
        const int ke = kt * 64;
        #pragma unroll
        for (int j = 0; j < 4; j++) {
            const int row = l_row + j * 32;
            const uint32_t so = l_soff + (uint32_t)(j * 32 * GR_STRIDE);
            cp16(sb + so,          A_g + (size_t)(m0 + row) * CKV + ke + l_c16 * 8);
            cp16(sb + TILE_B + so, Bkv + (size_t)(n0 + row) * CKV + ke + l_c16 * 8);
        }
        CP_COMMIT();
    };

    load_stage(0, 0);
    load_stage(1, 1);

    for (int kt = 0; kt < KT_N; kt++) {
        CP_WAIT(1);
        __syncthreads();

        const int nkt = kt + STAGES - 1;
        if (nkt < KT_N) load_stage(nkt, nkt % STAGES);
        else CP_COMMIT();

        const uint32_t sb = sbase + (kt % STAGES) * STAGE_B;
        #pragma unroll
        for (int kb = 0; kb < 64; kb += 16) {
            uint32_t ah[4][4];
            #pragma unroll
            for (int mt = 0; mt < 4; mt++) {
                uint32_t ra = sb + (uint32_t)((wm + mt * 16 + a_row) * GR_STRIDE
                                              + (a_ko + kb) * 2);
                ldsm_x4(ra, ah[mt][0], ah[mt][1], ah[mt][2], ah[mt][3]);
            }
            uint32_t bh[4][2];
            #pragma unroll
            for (int np = 0; np < 2; np++) {
                uint32_t rb = sb + TILE_B +
                              (uint32_t)((wn + np * 16 + b_row) * GR_STRIDE
                                         + (b_ko + kb) * 2);
                ldsm_x4(rb, bh[np * 2][0], bh[np * 2][1], bh[np * 2 + 1][0], bh[np * 2 + 1][1]);
            }
            #pragma unroll
            for (int mt = 0; mt < 4; mt++)
                #pragma unroll
                for (int nt = 0; nt < 4; nt++)
                    mma_f16(acc[mt][nt], ah[mt][0], ah[mt][1], ah[mt][2], ah[mt][3],
                            bh[nt][0], bh[nt][1]);
        }
    }

    const bool isV = (n0 >= CQ);
    const float* bias = isV ? bv : bk;
    __half* C = isV ? Vout : Kout;
    const int nc0 = isV ? (n0 - CQ) : n0;

    const int er = lane >> 2, ec = (lane & 3) * 2;
    #pragma unroll
    for (int mt = 0; mt < 4; mt++) {
        #pragma unroll
        for (int nt = 0; nt < 4; nt++) {
            const int col = nc0 + wn + nt * 8 + ec;
            const float b0 = bias[col], b1 = bias[col + 1];
            __half* p0 = C + (size_t)(m0 + wm + mt * 16 + er) * CQ + col;
            __half* p1 = p0 + 8 * CQ;
            st2(p0, acc[mt][nt][0] + b0, acc[mt][nt][1] + b1);
            st2(p1, acc[mt][nt][2] + b0, acc[mt][nt][3] + b1);
        }
    }
}

// ---------------------------------------------------------------------------
// Small HMMA fp16x2 GEMM (Q / O projections)
// ---------------------------------------------------------------------------
#define QO_TILE_B 5120
#define QO_STAGE_B (3 * QO_TILE_B)
#define QO_STAGES 3
#define QO_KT (CQ / 32)

template <typename OutT>
__global__ __launch_bounds__(128) void hgemm_qo(
    const __half* __restrict__ A_g, const __half* __restrict__ Bh_g,
    const __half* __restrict__ Bl_g, const float* __restrict__ bias,
    OutT* __restrict__ C)
{
    __shared__ char smem[QO_STAGES * QO_STAGE_B];
    const uint32_t sbase = smem_u32(smem);
    const int tid = threadIdx.x;
    const int wid = tid >> 5, lane = tid & 31;
    const int wm = (wid & 1) * 32;
    const int wn = (wid >> 1) * 32;
    const int m0 = blockIdx.y * 64, n0 = blockIdx.x * 64;

    const int lr = tid >> 1;
    const int lc = (tid & 1) * 16;
    const uint32_t s_off = (uint32_t)(lr * 80 + (tid & 1) * 32);

    const __half* gA  = A_g  + (size_t)(m0 + lr) * CQ + lc;
    const __half* gBh = Bh_g + (size_t)(n0 + lr) * CQ + lc;
    const __half* gBl = Bl_g + (size_t)(n0 + lr) * CQ + lc;

    const int a_row = lane & 15;
    const int a_ko  = ((lane >> 4) & 1) * 8;
    const int b_row = (lane & 7) + ((lane >> 4) & 1) * 8;
    const int b_ko  = ((lane >> 3) & 1) * 8;

    float acc[2][4][4];
    #pragma unroll
    for (int i = 0; i < 2; i++)
        #pragma unroll
        for (int j = 0; j < 4; j++)
            #pragma unroll
            for (int c = 0; c < 4; c++) acc[i][j][c] = 0.f;

    auto load_stage = [&](int kt, int s) {
        const uint32_t sb = sbase + s * QO_STAGE_B;
        const int ke = kt * 32;
        cp16(sb + s_off,                    gA  + ke);
        cp16(sb + s_off + 16,               gA  + ke + 8);
        cp16(sb + QO_TILE_B + s_off,        gBh + ke);
        cp16(sb + QO_TILE_B + s_off + 16,   gBh + ke + 8);
        cp16(sb + 2*QO_TILE_B + s_off,      gBl + ke);
        cp16(sb + 2*QO_TILE_B + s_off + 16, gBl + ke + 8);
    };

    load_stage(0, 0); CP_COMMIT();
    load_stage(1, 1); CP_COMMIT();

    for (int kt = 0; kt < QO_KT; kt++) {
        CP_WAIT(1);
        __syncthreads();

        const int nkt = kt + QO_STAGES - 1;
        if (nkt < QO_KT) load_stage(nkt, nkt % QO_STAGES);
        CP_COMMIT();

        const uint32_t sb = sbase + (kt % QO_STAGES) * QO_STAGE_B;
        #pragma unroll
        for (int kb = 0; kb < 32; kb += 16) {
            uint32_t a[2][4];
            #pragma unroll
            for (int mt = 0; mt < 2; mt++) {
                uint32_t ra = sb + (uint32_t)((wm + mt * 16 + a_row) * 80 + (a_ko + kb) * 2);
                ldsm_x4(ra, a[mt][0], a[mt][1], a[mt][2], a[mt][3]);
            }
            uint32_t bh[4][2], bl[4][2];
            #pragma unroll
            for (int ng = 0; ng < 2; ng++) {
                uint32_t rbh = sb + QO_TILE_B +
                               (uint32_t)((wn + ng * 16 + b_row) * 80 + (b_ko + kb) * 2);
                ldsm_x4(rbh, bh[2*ng][0], bh[2*ng][1], bh[2*ng+1][0], bh[2*ng+1][1]);
                ldsm_x4(rbh + QO_TILE_B, bl[2*ng][0], bl[2*ng][1], bl[2*ng+1][0], bl[2*ng+1][1]);
            }
            #pragma unroll
            for (int mt = 0; mt < 2; mt++)
                #pragma unroll
                for (int nt = 0; nt < 4; nt++) {
                    mma_f16(acc[mt][nt], a[mt][0], a[mt][1], a[mt][2], a[mt][3],
                            bh[nt][0], bh[nt][1]);
                    mma_f16(acc[mt][nt], a[mt][0], a[mt][1], a[mt][2], a[mt][3],
                            bl[nt][0], bl[nt][1]);
                }
        }
    }

    const int er = lane >> 2, ec = (lane & 3) * 2;
    #pragma unroll
    for (int mt = 0; mt < 2; mt++) {
        #pragma unroll
        for (int nt = 0; nt < 4; nt++) {
            const int col = n0 + wn + nt * 8 + ec;
            const float b0 = bias[col], b1 = bias[col + 1];
            OutT* p0 = C + (size_t)(m0 + wm + mt * 16 + er) * CQ + col;
            OutT* p1 = p0 + 8 * CQ;
            st2(p0, acc[mt][nt][0] + b0, acc[mt][nt][1] + b1);
            st2(p1, acc[mt][nt][2] + b0, acc[mt][nt][3] + b1);
        }
    }
}

// ---------------------------------------------------------------------------
// HMMA split-KV flash attention partial, double-buffered K/V chunks
// ---------------------------------------------------------------------------
#define KV_PER_SPLIT (NKV / SPLIT)
#define N_CHUNKS (KV_PER_SPLIT / 64)

__global__ __launch_bounds__(128) void attention_hmma(
    const __half* __restrict__ Qg, const __half* __restrict__ Kg,
    const __half* __restrict__ Vg,
    float* __restrict__ accP, float* __restrict__ mP, float* __restrict__ lP)
{
    __shared__ __half Qs[64][72];
    __shared__ __half Ks[2][64][72];
    __shared__ __half Vs[2][64][72];

    const int bh = blockIdx.x / SPLIT;
    const int sp = blockIdx.x % SPLIT;
    const int b = bh / H_, h = bh % H_;
    const int tid = threadIdx.x;
    const int w = tid >> 5, lane = tid & 31;
    const int kv_lo = sp * KV_PER_SPLIT;

    auto load_chunk = [&](int c, int buf) {
        const int kv0 = kv_lo + c * 64;
        #pragma unroll
        for (int idx = tid; idx < 512; idx += 128) {
            int r = idx >> 3, sg = idx & 7;
            size_t gofs = (size_t)(b * NKV + kv0 + r) * CQ + h * D_ + sg * 8;
            cp16(smem_u32(&Ks[buf][r][sg * 8]), Kg + gofs);
            cp16(smem_u32(&Vs[buf][r][sg * 8]), Vg + gofs);
        }
        CP_COMMIT();
    };

    load_chunk(0, 0);

    {
        const __half2 sc = __floats2half2_rn(0.125f, 0.125f);
        for (int idx = tid; idx < 512; idx += 128) {
            int r = idx >> 3, c8 = (idx & 7) * 8;
            uint4 v = *(const uint4*)(Qg + (size_t)(b * NQ + r) * CQ + h * D_ + c8);
            __half2* s = (__half2*)&v;
            __half2* d = (__half2*)&Qs[r][c8];
            d[0] = __hmul2(s[0], sc); d[1] = __hmul2(s[1], sc);
            d[2] = __hmul2(s[2], sc); d[3] = __hmul2(s[3], sc);
        }
    }

    const int qa_row = lane & 15;
    const int qa_ko  = ((lane >> 4) & 1) * 8;
    const int kb_row = (lane & 7) + ((lane >> 4) & 1) * 8;
    const int kb_ko  = ((lane >> 3) & 1) * 8;
    const int vt_row = (lane & 7) + ((lane >> 3) & 1) * 8;
    const int vt_co  = ((lane >> 4) & 1) * 8;

    float m0 = -1e30f, m1 = -1e30f, l0 = 0.f, l1 = 0.f;
    float o[8][4];
    #pragma unroll
    for (int i = 0; i < 8; i++)
        #pragma unroll
        for (int j = 0; j < 4; j++) o[i][j] = 0.f;

    for (int c = 0; c < N_CHUNKS; c++) {
        const int cur = c & 1;
        if (c + 1 < N_CHUNKS) { load_chunk(c + 1, cur ^ 1); CP_WAIT(1); }
        else                  { CP_WAIT(0); }
        __syncthreads();

        float s[8][4];
        #pragma unroll
        for (int i = 0; i < 8; i++)
            #pragma unroll
            for (int j = 0; j < 4; j++) s[i][j] = 0.f;

        #pragma unroll
        for (int kk = 0; kk < 4; kk++) {
            uint32_t a0, a1, a2, a3;
            ldsm_x4(smem_u32(&Qs[w * 16 + qa_row][kk * 16 + qa_ko]), a0, a1, a2, a3);
            #pragma unroll
            for (int ng = 0; ng < 4; ng++) {
                uint32_t b0, b1, b2, b3;
                ldsm_x4(smem_u32(&Ks[cur][ng * 16 + kb_row][kk * 16 + kb_ko]),
                        b0, b1, b2, b3);
                mma_f16(s[2 * ng],     a0, a1, a2, a3, b0, b1);
                mma_f16(s[2 * ng + 1], a0, a1, a2, a3, b2, b3);
            }
        }

        float mx0 = -1e30f, mx1 = -1e30f;
        #pragma unroll
        for (int nt = 0; nt < 8; nt++) {
            mx0 = fmaxf(mx0, fmaxf(s[nt][0], s[nt][1]));
            mx1 = fmaxf(mx1, fmaxf(s[nt][2], s[nt][3]));
        }
        #pragma unroll
        for (int ofs = 1; ofs < 4; ofs <<= 1) {
            mx0 = fmaxf(mx0, __shfl_xor_sync(0xffffffffu, mx0, ofs));
            mx1 = fmaxf(mx1, __shfl_xor_sync(0xffffffffu, mx1, ofs));
        }
        float M0 = fmaxf(m0, mx0), M1 = fmaxf(m1, mx1);
        float c0 = __expf(m0 - M0), c1 = __expf(m1 - M1);
        float ls0 = 0.f, ls1 = 0.f;
        #pragma unroll
        for (int nt = 0; nt < 8; nt++) {
            s[nt][0] = __expf(s[nt][0] - M0); ls0 += s[nt][0];
            s[nt][1] = __expf(s[nt][1] - M0); ls0 += s[nt][1];
            s[nt][2] = __expf(s[nt][2] - M1); ls1 += s[nt][2];
            s[nt][3] = __expf(s[nt][3] - M1); ls1 += s[nt][3];
        }
        #pragma unroll
        for (int ofs = 1; ofs < 4; ofs <<= 1) {
            ls0 += __shfl_xor_sync(0xffffffffu, ls0, ofs);
            ls1 += __shfl_xor_sync(0xffffffffu, ls1, ofs);
        }
        l0 = l0 * c0 + ls0;  l1 = l1 * c1 + ls1;
        m0 = M0;  m1 = M1;
        #pragma unroll
        for (int nt = 0; nt < 8; nt++) {
            o[nt][0] *= c0; o[nt][1] *= c0;
            o[nt][2] *= c1; o[nt][3] *= c1;
        }

        uint32_t pu[8][2];
        #pragma unroll
        for (int nt = 0; nt < 8; nt++) {
            pu[nt][0] = pack_h2(s[nt][0], s[nt][1]);
            pu[nt][1] = pack_h2(s[nt][2], s[nt][3]);
        }

        #pragma unroll
        for (int t = 0; t < 4; t++) {
            uint32_t a0 = pu[2 * t][0],     a1 = pu[2 * t][1];
            uint32_t a2 = pu[2 * t + 1][0], a3 = pu[2 * t + 1][1];
            #pragma unroll
            for (int dg = 0; dg < 4; dg++) {
                uint32_t b0, b1, b2, b3;
                ldsm_x4_t(smem_u32(&Vs[cur][t * 16 + vt_row][dg * 16 + vt_co]),
                          b0, b1, b2, b3);
                mma_f16(o[2 * dg],     a0, a1, a2, a3, b0, b1);
                mma_f16(o[2 * dg + 1], a0, a1, a2, a3, b2, b3);
            }
        }
        __syncthreads();
    }

    float* accp = accP + (size_t)blockIdx.x * 64 * 64;
    const int r0 = w * 16 + (lane >> 2), r1 = r0 + 8;
    const int cb = (lane & 3) * 2;
    #pragma unroll
    for (int nt = 0; nt < 8; nt++) {
        st2(&accp[r0 * 64 + nt * 8 + cb], o[nt][0], o[nt][1]);
        st2(&accp[r1 * 64 + nt * 8 + cb], o[nt][2], o[nt][3]);
    }
    if ((lane & 3) == 0) {
        mP[(size_t)blockIdx.x * 64 + r0] = m0;
        lP[(size_t)blockIdx.x * 64 + r0] = l0;
        mP[(size_t)blockIdx.x * 64 + r1] = m1;
        lP[(size_t)blockIdx.x * 64 + r1] = l1;
    }
}

__global__ __launch_bounds__(256) void attention_combine(
    const float* __restrict__ accP, const float* __restrict__ mP,
    const float* __restrict__ lP, __half* __restrict__ Xg)
{
    __shared__ float sw[SPLIT][64];
    __shared__ float sden[64];
    const int bh = blockIdx.x;
    const int b = bh / H_, h = bh % H_;
    const int tid = threadIdx.x;

    if (tid < 64) {
        int r = tid;
        float M = -1e30f;
        #pragma unroll
        for (int s = 0; s < SPLIT; s++)
            M = fmaxf(M, mP[(size_t)(bh * SPLIT + s) * 64 + r]);
        float den = 0.f;
        #pragma unroll
        for (int s = 0; s < SPLIT; s++) {
            float w = __expf(mP[(size_t)(bh * SPLIT + s) * 64 + r] - M);
            sw[s][r] = w;
            den += w * lP[(size_t)(bh * SPLIT + s) * 64 + r];
        }
        sden[r] = den;
    }
    __syncthreads();

    for (int idx = tid; idx < 64 * 64; idx += 256) {
        int r = idx >> 6, d = idx & 63;
        float num = 0.f;
        #pragma unroll
        for (int s = 0; s < SPLIT; s++)
            num += sw[s][r] * accP[(size_t)(bh * SPLIT + s) * 4096 + idx];
        Xg[(size_t)(b * NQ + r) * CQ + h * D_ + d] = __float2half_rn(num / sden[r]);
    }
}

// ---------------------------------------------------------------------------
extern "C" void kernel_launch(void* const* d_in, const int* in_sizes, int n_in,
                              void* d_out, int out_size)
{
    const float* query = (const float*)d_in[0];
    const float* kv    = (const float*)d_in[1];
    const float* Wq    = (const float*)d_in[2];
    const float* bq    = (const float*)d_in[3];
    const float* Wk    = (const float*)d_in[4];
    const float* bk    = (const float*)d_in[5];
    const float* Wv    = (const float*)d_in[6];
    const float* bv    = (const float*)d_in[7];
    const float* Wo    = (const float*)d_in[8];
    const float* bo    = (const float*)d_in[9];
    float* out = (float*)d_out;

    float *accp, *mp, *lp;
    __half *qa, *qh, *xh, *kp, *vp, *kva, *wkvt, *wqth, *wqtl, *woth, *wotl;
    cudaGetSymbolAddress((void**)&qa, g_qa);
    cudaGetSymbolAddress((void**)&qh, g_qh);
    cudaGetSymbolAddress((void**)&xh, g_xh);
    cudaGetSymbolAddress((void**)&kp, g_kh);
    cudaGetSymbolAddress((void**)&vp, g_vh);
    cudaGetSymbolAddress((void**)&kva, g_kva);
    cudaGetSymbolAddress((void**)&wkvt, g_wkvt);
    cudaGetSymbolAddress((void**)&wqth, g_wqth);
    cudaGetSymbolAddress((void**)&wqtl, g_wqtl);
    cudaGetSymbolAddress((void**)&woth, g_woth);
    cudaGetSymbolAddress((void**)&wotl, g_wotl);
    cudaGetSymbolAddress((void**)&accp, g_accP);
    cudaGetSymbolAddress((void**)&mp, g_mP);
    cudaGetSymbolAddress((void**)&lp, g_lP);

    cudaFuncSetAttribute(hgemm_kv,
                         cudaFuncAttributeMaxDynamicSharedMemorySize, HGEMM_SMEM);

    // half-split element counts (ELEMENT units made explicit)
    const size_t M_HALF       = (size_t)B_ * NKV / 2;    // 32768 rows
    const size_t ELEMS_HALF   = M_HALF * CKV;            // elements in half of kv/kva
    const size_t C_HALF       = M_HALF * CQ;             // elements in half of K/V out
    const size_t N4_HALF      = ELEMS_HALF / 4;          // float4 count per half

    // side stream (high priority so round1 CTAs slot into GEMM0 wave gaps)
    int prLo, prHi;
    cudaDeviceGetStreamPriorityRange(&prLo, &prHi);
    cudaStream_t s2;
    cudaStreamCreateWithPriority(&s2, cudaStreamNonBlocking, prHi);
    cudaEvent_t eFork, eW, eR1, eJoin;
    cudaEventCreateWithFlags(&eFork, cudaEventDisableTiming);
    cudaEventCreateWithFlags(&eW, cudaEventDisableTiming);
    cudaEventCreateWithFlags(&eR1, cudaEventDisableTiming);
    cudaEventCreateWithFlags(&eJoin, cudaEventDisableTiming);

    cudaEventRecord(eFork, 0);
    cudaStreamWaitEvent(s2, eFork, 0);

    // main: round first half of kv
    round_kernel<<<2048, 256>>>(kv, kva, N4_HALF);

    // side: weight transposes (GEMM dep) -> round second half -> q path
    transpose_f16_tiled<<<dim3(CKV / 32, CQ / 32), 256, 0, s2>>>(Wk, wkvt);
    transpose_f16_tiled<<<dim3(CKV / 32, CQ / 32), 256, 0, s2>>>(Wv, wkvt + (size_t)CQ * CKV);
    cudaEventRecord(eW, s2);
    round_kernel<<<2048, 256, 0, s2>>>(kv + ELEMS_HALF, kva + ELEMS_HALF, N4_HALF);
    cudaEventRecord(eR1, s2);
    round_kernel<<<384, 256, 0, s2>>>(query, qa, (size_t)B_ * NQ * CQ / 4);
    transpose_split768_tiled<<<dim3(CQ / 32, CQ / 32), 256, 0, s2>>>(Wq, wqth, wqtl);
    transpose_split768_tiled<<<dim3(CQ / 32, CQ / 32), 256, 0, s2>>>(Wo, woth, wotl);
    hgemm_qo<__half><<<dim3(CQ / 64, (B_ * NQ) / 64), 128, 0, s2>>>(qa, wqth, wqtl, bq, qh);
    cudaEventRecord(eJoin, s2);

    // main: fused K+V projection in two m-halves (256 m-blocks each)
    cudaStreamWaitEvent(0, eW, 0);
    hgemm_kv<<<dim3(2 * CQ / 128, (unsigned)(M_HALF / 128)), 256, HGEMM_SMEM>>>(
        kva, wkvt, bk, bv, kp, vp);
    cudaStreamWaitEvent(0, eR1, 0);
    hgemm_kv<<<dim3(2 * CQ / 128, (unsigned)(M_HALF / 128)), 256, HGEMM_SMEM>>>(
        kva + ELEMS_HALF, wkvt, bk, bv, kp + C_HALF, vp + C_HALF);

    // join q path, then attention + combine + output projection
    cudaStreamWaitEvent(0, eJoin, 0);
    attention_hmma<<<B_ * H_ * SPLIT, 128>>>(qh, kp, vp, accp, mp, lp);
    attention_combine<<<B_ * H_, 256>>>(accp, mp, lp, xh);
    hgemm_qo<float><<<dim3(CQ / 64, (B_ * NQ) / 64), 128>>>(xh, woth, wotl, bo, out);

    cudaEventDestroy(eFork);
    cudaEventDestroy(eW);
    cudaEventDestroy(eR1);
    cudaEventDestroy(eJoin);
    cudaStreamDestroy(s2);
}